// round 3
// baseline (speedup 1.0000x reference)
#include <cuda_runtime.h>
#include <cuda_bf16.h>
#include <math.h>

#define Vv 32000
#define Ee 512
#define Hh 1024
#define Bb 16
#define Ss 128
#define Kk 15

// ------------------------- device scratch (no allocs allowed) -------------------------
__device__ float g_G[Ss * Bb * Hh];          // [s][b][h] : x@W_ih^T + b_ih + b_hh
__device__ float g_HS[Bb * Ss * Hh];         // [b][s][h] : RNN outputs (decoder A matrix)
__device__ float g_H[2][Bb * Hh];            // ping-pong hidden state [b][h]
__device__ float g_topic[Vv];                // theta @ beta
__device__ unsigned g_bar_count;             // returns to 0 after every barrier (replay-safe)
__device__ unsigned g_bar_gen;               // monotone generation counter (replay-safe)

// ------------------------- small helpers -------------------------
__device__ __forceinline__ void fma2(unsigned long long &d, unsigned long long a,
                                     unsigned long long b) {
    asm("fma.rn.f32x2 %0, %1, %2, %0;" : "+l"(d) : "l"(a), "l"(b));
}

__device__ __forceinline__ void grid_barrier(unsigned nblocks) {
    __syncthreads();
    if (threadIdx.x == 0) {
        unsigned my = *((volatile unsigned*)&g_bar_gen);
        __threadfence();
        if (atomicAdd(&g_bar_count, 1u) == nblocks - 1u) {
            g_bar_count = 0;
            __threadfence();
            atomicAdd(&g_bar_gen, 1u);
        } else {
            while (*((volatile unsigned*)&g_bar_gen) == my) { }
        }
        __threadfence();
    }
    __syncthreads();
}

// ------------------------- tiny kernels -------------------------
__global__ void topic_kernel(const float* __restrict__ beta, const float* __restrict__ theta) {
    int v = blockIdx.x * 256 + threadIdx.x;
    if (v < Vv) {
        float s = 0.f;
#pragma unroll
        for (int k = 0; k < Kk; k++) s += theta[k] * beta[k * Vv + v];
        g_topic[v] = s;
    }
}

__global__ void init_h_kernel(const float* __restrict__ hidden) {
    int i = blockIdx.x * 256 + threadIdx.x;
    if (i < Bb * Hh) g_H[0][i] = hidden[i];
}

__global__ void copy_ht_kernel(float* __restrict__ out) {
    int i = blockIdx.x * 256 + threadIdx.x;
    if (i < Bb * Hh) out[(size_t)Bb * Ss * Vv + i] = g_H[0][i];
}

// ------------------------- embedding gather + input projection -------------------------
// G[m][n] = W_emb[ids(m)] . W_ih[n] + b_ih[n] + b_hh[n];  m = s*16+b (M=2048), N=1024, K=512
__global__ __launch_bounds__(256) void embed_gemm(const int* __restrict__ ids,
                                                  const float* __restrict__ W_emb,
                                                  const float* __restrict__ W_ih,
                                                  const float* __restrict__ b_ih,
                                                  const float* __restrict__ b_hh) {
    __shared__ __align__(16) float As[8][132];
    __shared__ __align__(16) float Bs[8][132];
    __shared__ int rowid[128];
    const int tid = threadIdx.x;
    const int bm = blockIdx.x * 128;
    const int bn = blockIdx.y * 128;
    if (tid < 128) {
        int m = bm + tid;
        rowid[tid] = ids[(m & 15) * Ss + (m >> 4)];   // input_ids[b][s]
    }
    __syncthreads();
    const int lrow = tid >> 1;
    const int lk = (tid & 1) * 4;
    const float* Ap = W_emb + (size_t)rowid[lrow] * Ee + lk;
    const float* Bp = W_ih + (size_t)(bn + lrow) * Ee + lk;
    const int tx = tid & 15, ty = tid >> 4;
    float acc[8][8] = {};
    float4 av = *(const float4*)(Ap);
    float4 bv = *(const float4*)(Bp);
    for (int kt = 0; kt < Ee; kt += 8) {
        As[lk + 0][lrow] = av.x; As[lk + 1][lrow] = av.y;
        As[lk + 2][lrow] = av.z; As[lk + 3][lrow] = av.w;
        Bs[lk + 0][lrow] = bv.x; Bs[lk + 1][lrow] = bv.y;
        Bs[lk + 2][lrow] = bv.z; Bs[lk + 3][lrow] = bv.w;
        __syncthreads();
        if (kt + 8 < Ee) {
            av = *(const float4*)(Ap + kt + 8);
            bv = *(const float4*)(Bp + kt + 8);
        }
#pragma unroll
        for (int kk = 0; kk < 8; kk++) {
            float a[8], b[8];
            *(float4*)&a[0] = *(const float4*)&As[kk][ty * 8];
            *(float4*)&a[4] = *(const float4*)&As[kk][ty * 8 + 4];
            *(float4*)&b[0] = *(const float4*)&Bs[kk][tx * 8];
            *(float4*)&b[4] = *(const float4*)&Bs[kk][tx * 8 + 4];
#pragma unroll
            for (int i = 0; i < 8; i++)
#pragma unroll
                for (int j = 0; j < 8; j++) acc[i][j] = fmaf(a[i], b[j], acc[i][j]);
        }
        __syncthreads();
    }
#pragma unroll
    for (int i = 0; i < 8; i++) {
        int m = bm + ty * 8 + i;
#pragma unroll
        for (int j = 0; j < 8; j++) {
            int n = bn + tx * 8 + j;
            g_G[(size_t)m * Hh + n] = acc[i][j] + b_ih[n] + b_hh[n];
        }
    }
}

// ------------------------- persistent RNN recurrence -------------------------
// 64 blocks x 256 threads; block handles 16 output columns (n0..n0+15), all 16 batches.
// W_hh slice stays in SMEM for the whole kernel; h re-staged each step via __ldcg.
#define RNN_NB 64
#define RSTRIDE 1028   // 1024 + pad 4 (conflict mitigation)

__global__ __launch_bounds__(256, 1) void rnn_kernel(const float* __restrict__ W_hh) {
    extern __shared__ __align__(16) float smem[];
    float* Ws = smem;                       // [16][RSTRIDE]
    float* hs = smem + 16 * RSTRIDE;        // [16][RSTRIDE]
    const int tid = threadIdx.x;
    const int n0 = blockIdx.x * 16;
    const int b = tid & 15;                 // 16 batches x 16 n-rows
    const int nl = tid >> 4;
    const int n = n0 + nl;

    // load W_hh slice once (rows n0..n0+15)
    for (int i = tid; i < 16 * (Hh / 4); i += 256) {
        int row = i >> 8;                   // Hh/4 = 256 float4 per row
        int q = i & 255;
        float4 v = *(const float4*)(W_hh + (size_t)(n0 + row) * Hh + q * 4);
        *(float4*)(Ws + row * RSTRIDE + q * 4) = v;
    }

    for (int s = 0; s < Ss; s++) {
        const int cur = s & 1;
        // stage h[cur] into shared (L2-coherent loads)
        const float* hsrc = g_H[cur];
        for (int i = tid; i < 16 * (Hh / 4); i += 256) {
            int row = i >> 8;
            int q = i & 255;
            float4 v = __ldcg((const float4*)(hsrc + row * Hh + q * 4));
            *(float4*)(hs + row * RSTRIDE + q * 4) = v;
        }
        __syncthreads();

        const float* wrow = Ws + nl * RSTRIDE;
        const float* hrow = hs + b * RSTRIDE;
        float acc = g_G[(size_t)s * (Bb * Hh) + b * Hh + n];
#pragma unroll 4
        for (int k4 = 0; k4 < Hh / 4; k4++) {
            float4 w = *(const float4*)(wrow + k4 * 4);
            float4 h = *(const float4*)(hrow + k4 * 4);
            acc = fmaf(w.x, h.x, acc);
            acc = fmaf(w.y, h.y, acc);
            acc = fmaf(w.z, h.z, acc);
            acc = fmaf(w.w, h.w, acc);
        }
        float hv = tanhf(acc);
        __stcg(&g_H[cur ^ 1][b * Hh + n], hv);
        g_HS[(size_t)b * (Ss * Hh) + (size_t)s * Hh + n] = hv;
        grid_barrier(RNN_NB);
    }
}

// ------------------------- decoder GEMM (f32x2 packed FFMA) -------------------------
// out[m][v] = HS[m] . W_dec[v] + b_dec[v] + topic[v]*mask[m];  M=2048, N=32000, K=1024
__global__ __launch_bounds__(256) void dec_gemm(const float* __restrict__ W_dec,
                                                const float* __restrict__ b_dec,
                                                const int* __restrict__ stop,
                                                float* __restrict__ out) {
    __shared__ __align__(16) float As2[8][264];  // A duplicated: As2[k][2m]==As2[k][2m+1]==A[m][k]
    __shared__ __align__(16) float Bs[8][132];
    const int tid = threadIdx.x;
    const int bm = blockIdx.x * 128;
    const int bn = blockIdx.y * 128;
    const int lrow = tid >> 1;
    const int lk = (tid & 1) * 4;
    const int tx = tid & 15, ty = tid >> 4;

    const float* Ap = g_HS + (size_t)(bm + lrow) * Hh + lk;
    const float* Bp = W_dec + (size_t)(bn + lrow) * Hh + lk;

    unsigned long long acc2[8][4] = {};
    float4 av = *(const float4*)(Ap);
    float4 bv = *(const float4*)(Bp);
    for (int kt = 0; kt < Hh; kt += 8) {
        As2[lk + 0][lrow * 2] = av.x; As2[lk + 0][lrow * 2 + 1] = av.x;
        As2[lk + 1][lrow * 2] = av.y; As2[lk + 1][lrow * 2 + 1] = av.y;
        As2[lk + 2][lrow * 2] = av.z; As2[lk + 2][lrow * 2 + 1] = av.z;
        As2[lk + 3][lrow * 2] = av.w; As2[lk + 3][lrow * 2 + 1] = av.w;
        Bs[lk + 0][lrow] = bv.x; Bs[lk + 1][lrow] = bv.y;
        Bs[lk + 2][lrow] = bv.z; Bs[lk + 3][lrow] = bv.w;
        __syncthreads();
        if (kt + 8 < Hh) {
            av = *(const float4*)(Ap + kt + 8);
            bv = *(const float4*)(Bp + kt + 8);
        }
#pragma unroll
        for (int kk = 0; kk < 8; kk++) {
            const ulonglong2* ap = (const ulonglong2*)&As2[kk][ty * 16];
            const ulonglong2* bp = (const ulonglong2*)&Bs[kk][tx * 8];
            ulonglong2 a01 = ap[0], a23 = ap[1], a45 = ap[2], a67 = ap[3];
            ulonglong2 b01 = bp[0], b23 = bp[1];
            unsigned long long a2[8] = {a01.x, a01.y, a23.x, a23.y,
                                        a45.x, a45.y, a67.x, a67.y};
#pragma unroll
            for (int i = 0; i < 8; i++) {
                fma2(acc2[i][0], a2[i], b01.x);
                fma2(acc2[i][1], a2[i], b01.y);
                fma2(acc2[i][2], a2[i], b23.x);
                fma2(acc2[i][3], a2[i], b23.y);
            }
        }
        __syncthreads();
    }

    // epilogue: bias + topic * (stop==0)
    const int nbase = bn + tx * 8;
    float4 bd0 = *(const float4*)(b_dec + nbase);
    float4 bd1 = *(const float4*)(b_dec + nbase + 4);
    float4 t0 = *(const float4*)(g_topic + nbase);
    float4 t1 = *(const float4*)(g_topic + nbase + 4);
#pragma unroll
    for (int i = 0; i < 8; i++) {
        int m = bm + ty * 8 + i;
        float msk = (stop[m] == 0) ? 1.0f : 0.0f;
        float2 p0 = *(float2*)&acc2[i][0];
        float2 p1 = *(float2*)&acc2[i][1];
        float2 p2 = *(float2*)&acc2[i][2];
        float2 p3 = *(float2*)&acc2[i][3];
        float4 o0 = make_float4(p0.x + bd0.x + t0.x * msk,
                                p0.y + bd0.y + t0.y * msk,
                                p1.x + bd0.z + t0.z * msk,
                                p1.y + bd0.w + t0.w * msk);
        float4 o1 = make_float4(p2.x + bd1.x + t1.x * msk,
                                p2.y + bd1.y + t1.y * msk,
                                p3.x + bd1.z + t1.z * msk,
                                p3.y + bd1.w + t1.w * msk);
        float* op = out + (size_t)m * Vv + nbase;
        *(float4*)(op) = o0;
        *(float4*)(op + 4) = o1;
    }
}

// ------------------------- launch -------------------------
extern "C" void kernel_launch(void* const* d_in, const int* in_sizes, int n_in,
                              void* d_out, int out_size) {
    const int*   input_ids = (const int*)d_in[0];
    const float* hidden    = (const float*)d_in[1];
    const int*   stop      = (const int*)d_in[2];
    const float* W_emb     = (const float*)d_in[3];
    const float* W_ih      = (const float*)d_in[4];
    const float* b_ih      = (const float*)d_in[5];
    const float* W_hh      = (const float*)d_in[6];
    const float* b_hh      = (const float*)d_in[7];
    const float* W_dec     = (const float*)d_in[8];
    const float* b_dec     = (const float*)d_in[9];
    const float* beta      = (const float*)d_in[10];
    const float* theta     = (const float*)d_in[11];
    float* out = (float*)d_out;

    const int rnn_smem = 2 * 16 * RSTRIDE * (int)sizeof(float);   // ~131.5 KB
    cudaFuncSetAttribute(rnn_kernel, cudaFuncAttributeMaxDynamicSharedMemorySize,
                         rnn_smem);

    topic_kernel<<<(Vv + 255) / 256, 256>>>(beta, theta);
    init_h_kernel<<<(Bb * Hh + 255) / 256, 256>>>(hidden);
    embed_gemm<<<dim3(16, 8), 256>>>(input_ids, W_emb, W_ih, b_ih, b_hh);
    rnn_kernel<<<RNN_NB, 256, rnn_smem>>>(W_hh);
    dec_gemm<<<dim3(16, 250), 256>>>(W_dec, b_dec, stop, out);
    copy_ht_kernel<<<(Bb * Hh + 255) / 256, 256>>>(out);
}

// round 5
// speedup vs baseline: 1.9989x; 1.9989x over previous
#include <cuda_runtime.h>
#include <cuda_bf16.h>
#include <math.h>
#include <stdint.h>

#define Vv 32000
#define Ee 512
#define Hh 1024
#define Bb 16
#define Ss 128
#define Kk 15

// ------------------------- device scratch (no allocs allowed) -------------------------
__device__ float g_G[Ss * Bb * Hh];          // [s][b][h] : x@W_ih^T + b_ih + b_hh
__device__ float g_HS[Bb * Ss * Hh];         // [b][s][h] : RNN outputs (decoder A matrix)
__device__ float g_H[2][Bb * Hh];            // ping-pong hidden state [b][h]
__device__ float g_topic[Vv];                // theta @ beta
__device__ unsigned g_bar_count;
__device__ unsigned g_bar_gen;
// bf16 split operands: A2 = [Ah | Al] (K=2048), B2 = [Bh | Bl] (K=2048)
__device__ __nv_bfloat16 g_A2[2048 * 2048];
__device__ __nv_bfloat16 g_B2[(size_t)Vv * 2048];

// ------------------------- PTX helpers -------------------------
__device__ __forceinline__ uint32_t smem_u32(const void* p) {
    uint32_t a;
    asm("{ .reg .u64 t; cvta.to.shared.u64 t, %1; cvt.u32.u64 %0, t; }" : "=r"(a) : "l"(p));
    return a;
}
__device__ __forceinline__ void cp_async16(uint32_t dst, const void* src) {
    asm volatile("cp.async.cg.shared.global [%0], [%1], 16;" :: "r"(dst), "l"(src) : "memory");
}
__device__ __forceinline__ void cp_commit() { asm volatile("cp.async.commit_group;" ::: "memory"); }

__device__ __forceinline__ void ldsm4(uint32_t* r, uint32_t addr) {
    asm volatile("ldmatrix.sync.aligned.m8n8.x4.shared.b16 {%0,%1,%2,%3}, [%4];"
                 : "=r"(r[0]), "=r"(r[1]), "=r"(r[2]), "=r"(r[3]) : "r"(addr));
}
__device__ __forceinline__ void mma16816(float* c, const uint32_t* a, uint32_t b0, uint32_t b1) {
    asm volatile("mma.sync.aligned.m16n8k16.row.col.f32.bf16.bf16.f32 "
                 "{%0,%1,%2,%3}, {%4,%5,%6,%7}, {%8,%9}, {%0,%1,%2,%3};"
                 : "+f"(c[0]), "+f"(c[1]), "+f"(c[2]), "+f"(c[3])
                 : "r"(a[0]), "r"(a[1]), "r"(a[2]), "r"(a[3]), "r"(b0), "r"(b1));
}

__device__ __forceinline__ void grid_barrier(unsigned nblocks) {
    __syncthreads();
    if (threadIdx.x == 0) {
        unsigned my = *((volatile unsigned*)&g_bar_gen);
        __threadfence();
        if (atomicAdd(&g_bar_count, 1u) == nblocks - 1u) {
            g_bar_count = 0;
            __threadfence();
            atomicAdd(&g_bar_gen, 1u);
        } else {
            while (*((volatile unsigned*)&g_bar_gen) == my) { }
        }
        __threadfence();
    }
    __syncthreads();
}

// ------------------------- tiny kernels -------------------------
__global__ void topic_kernel(const float* __restrict__ beta, const float* __restrict__ theta) {
    int v = blockIdx.x * 256 + threadIdx.x;
    if (v < Vv) {
        float s = 0.f;
#pragma unroll
        for (int k = 0; k < Kk; k++) s += theta[k] * beta[k * Vv + v];
        g_topic[v] = s;
    }
}
__global__ void init_h_kernel(const float* __restrict__ hidden) {
    int i = blockIdx.x * 256 + threadIdx.x;
    if (i < Bb * Hh) g_H[0][i] = hidden[i];
}
__global__ void copy_ht_kernel(float* __restrict__ out) {
    int i = blockIdx.x * 256 + threadIdx.x;
    if (i < Bb * Hh) out[(size_t)Bb * Ss * Vv + i] = g_H[0][i];
}
// fp32 -> (hi, lo) bf16 split conversions
__global__ void convA_kernel() {
    int i = blockIdx.x * 256 + threadIdx.x;   // 2048*1024
    int m = i >> 10, k = i & 1023;
    float x = g_HS[i];
    __nv_bfloat16 hi = __float2bfloat16(x);
    __nv_bfloat16 lo = __float2bfloat16(x - __bfloat162float(hi));
    size_t base = (size_t)m * 2048;
    g_A2[base + k] = hi;
    g_A2[base + 1024 + k] = lo;
}
__global__ void convB_kernel(const float* __restrict__ W_dec) {
    size_t i = (size_t)blockIdx.x * 256 + threadIdx.x;  // 32000*1024
    size_t v = i >> 10, k = i & 1023;
    float x = W_dec[i];
    __nv_bfloat16 hi = __float2bfloat16(x);
    __nv_bfloat16 lo = __float2bfloat16(x - __bfloat162float(hi));
    size_t base = v * 2048;
    g_B2[base + k] = hi;
    g_B2[base + 1024 + k] = lo;
}

// ------------------------- embedding gather + input projection -------------------------
__global__ __launch_bounds__(256) void embed_gemm(const int* __restrict__ ids,
                                                  const float* __restrict__ W_emb,
                                                  const float* __restrict__ W_ih,
                                                  const float* __restrict__ b_ih,
                                                  const float* __restrict__ b_hh) {
    __shared__ __align__(16) float As[8][132];
    __shared__ __align__(16) float Bs[8][132];
    __shared__ int rowid[128];
    const int tid = threadIdx.x;
    const int bm = blockIdx.x * 128;
    const int bn = blockIdx.y * 128;
    if (tid < 128) {
        int m = bm + tid;
        rowid[tid] = ids[(m & 15) * Ss + (m >> 4)];
    }
    __syncthreads();
    const int lrow = tid >> 1;
    const int lk = (tid & 1) * 4;
    const float* Ap = W_emb + (size_t)rowid[lrow] * Ee + lk;
    const float* Bp = W_ih + (size_t)(bn + lrow) * Ee + lk;
    const int tx = tid & 15, ty = tid >> 4;
    float acc[8][8] = {};
    float4 av = *(const float4*)(Ap);
    float4 bv = *(const float4*)(Bp);
    for (int kt = 0; kt < Ee; kt += 8) {
        As[lk + 0][lrow] = av.x; As[lk + 1][lrow] = av.y;
        As[lk + 2][lrow] = av.z; As[lk + 3][lrow] = av.w;
        Bs[lk + 0][lrow] = bv.x; Bs[lk + 1][lrow] = bv.y;
        Bs[lk + 2][lrow] = bv.z; Bs[lk + 3][lrow] = bv.w;
        __syncthreads();
        if (kt + 8 < Ee) {
            av = *(const float4*)(Ap + kt + 8);
            bv = *(const float4*)(Bp + kt + 8);
        }
#pragma unroll
        for (int kk = 0; kk < 8; kk++) {
            float a[8], b[8];
            *(float4*)&a[0] = *(const float4*)&As[kk][ty * 8];
            *(float4*)&a[4] = *(const float4*)&As[kk][ty * 8 + 4];
            *(float4*)&b[0] = *(const float4*)&Bs[kk][tx * 8];
            *(float4*)&b[4] = *(const float4*)&Bs[kk][tx * 8 + 4];
#pragma unroll
            for (int i = 0; i < 8; i++)
#pragma unroll
                for (int j = 0; j < 8; j++) acc[i][j] = fmaf(a[i], b[j], acc[i][j]);
        }
        __syncthreads();
    }
#pragma unroll
    for (int i = 0; i < 8; i++) {
        int m = bm + ty * 8 + i;
#pragma unroll
        for (int j = 0; j < 8; j++) {
            int n = bn + tx * 8 + j;
            g_G[(size_t)m * Hh + n] = acc[i][j] + b_ih[n] + b_hh[n];
        }
    }
}

// ------------------------- persistent RNN recurrence -------------------------
#define RNN_NB 64
#define RSTRIDE 1028

__global__ __launch_bounds__(256, 1) void rnn_kernel(const float* __restrict__ W_hh) {
    extern __shared__ __align__(16) float smem[];
    float* Ws = smem;
    float* hs = smem + 16 * RSTRIDE;
    const int tid = threadIdx.x;
    const int n0 = blockIdx.x * 16;
    const int b = tid & 15;
    const int nl = tid >> 4;
    const int n = n0 + nl;

    for (int i = tid; i < 16 * (Hh / 4); i += 256) {
        int row = i >> 8;
        int q = i & 255;
        float4 v = *(const float4*)(W_hh + (size_t)(n0 + row) * Hh + q * 4);
        *(float4*)(Ws + row * RSTRIDE + q * 4) = v;
    }

    for (int s = 0; s < Ss; s++) {
        const int cur = s & 1;
        const float* hsrc = g_H[cur];
        for (int i = tid; i < 16 * (Hh / 4); i += 256) {
            int row = i >> 8;
            int q = i & 255;
            float4 v = __ldcg((const float4*)(hsrc + row * Hh + q * 4));
            *(float4*)(hs + row * RSTRIDE + q * 4) = v;
        }
        __syncthreads();

        const float* wrow = Ws + nl * RSTRIDE;
        const float* hrow = hs + b * RSTRIDE;
        float acc = g_G[(size_t)s * (Bb * Hh) + b * Hh + n];
#pragma unroll 4
        for (int k4 = 0; k4 < Hh / 4; k4++) {
            float4 w = *(const float4*)(wrow + k4 * 4);
            float4 h = *(const float4*)(hrow + k4 * 4);
            acc = fmaf(w.x, h.x, acc);
            acc = fmaf(w.y, h.y, acc);
            acc = fmaf(w.z, h.z, acc);
            acc = fmaf(w.w, h.w, acc);
        }
        float hv = tanhf(acc);
        __stcg(&g_H[cur ^ 1][b * Hh + n], hv);
        g_HS[(size_t)b * (Ss * Hh) + (size_t)s * Hh + n] = hv;
        grid_barrier(RNN_NB);
    }
}

// ------------------------- tensor-core decoder GEMM (mma.sync bf16) -------------------------
// out[m][v] = sum over virtual K' = 3072:  [Ah|Ah|Al] . [Bh|Bl|Bh]
// CTA tile 128m x 256n, k-chunk 64; 8 warps (2 m x 4 n), warp tile 64x64.
#define DEC_KI 48
#define DEC_ASZ 16384              // 128 rows * 128 B
#define DEC_BSZ 32768              // 256 rows * 128 B
#define DEC_STG (DEC_ASZ + DEC_BSZ)
#define DEC_SMEM (3 * DEC_STG + 1024)

__device__ __forceinline__ void dec_load_stage(uint32_t sb, int stg, int ki,
                                               int bm, int bn, int tid) {
    const int kA = (ki < 16) ? ki : ki - 16;       // [Ah|Ah|Al] -> A2 chunk
    const int kB = (ki < 32) ? ki : ki - 32;       // [Bh|Bl|Bh] -> B2 chunk
    uint32_t base = sb + stg * DEC_STG;
    const __nv_bfloat16* gA = g_A2 + (size_t)bm * 2048 + kA * 64;
    const __nv_bfloat16* gB = g_B2 + (size_t)bn * 2048 + kB * 64;
#pragma unroll
    for (int i = 0; i < 4; i++) {                  // A: 1024 x 16B
        int c = tid + i * 256;
        int r = c >> 3, cc = c & 7;
        cp_async16(base + r * 128 + (((cc ^ (r & 7)) & 7) << 4),
                   gA + (size_t)r * 2048 + cc * 8);
    }
#pragma unroll
    for (int i = 0; i < 8; i++) {                  // B: 2048 x 16B
        int c = tid + i * 256;
        int r = c >> 3, cc = c & 7;
        cp_async16(base + DEC_ASZ + r * 128 + (((cc ^ (r & 7)) & 7) << 4),
                   gB + (size_t)r * 2048 + cc * 8);
    }
}

__global__ __launch_bounds__(256, 1) void dec_mma(const float* __restrict__ b_dec,
                                                  const int* __restrict__ stop,
                                                  float* __restrict__ out) {
    extern __shared__ char dsm_raw[];
    const int tid = threadIdx.x;
    const int wid = tid >> 5;
    const int lane = tid & 31;
    const int wm = wid & 1;        // 2 m-warps
    const int wn = wid >> 1;       // 4 n-warps
    const int bm = blockIdx.x * 128;    // 16
    const int bn = blockIdx.y * 256;    // 125
    uint32_t sb = (smem_u32(dsm_raw) + 1023) & ~1023u;

    float acc[4][8][4];
#pragma unroll
    for (int i = 0; i < 4; i++)
#pragma unroll
        for (int j = 0; j < 8; j++)
#pragma unroll
            for (int q = 0; q < 4; q++) acc[i][j][q] = 0.f;

    // ldmatrix address components
    const int arow = wm * 64 + (lane & 15);
    const int ach = lane >> 4;                     // col half for A
    const int as = arow & 7;
    const int brow = wn * 64 + ((lane >> 4) << 3) + (lane & 7);
    const int bch = (lane >> 3) & 1;
    const int bs = brow & 7;

    dec_load_stage(sb, 0, 0, bm, bn, tid); cp_commit();
    dec_load_stage(sb, 1, 1, bm, bn, tid); cp_commit();

    for (int ki = 0; ki < DEC_KI; ki++) {
        const int cur = ki % 3;
        if (ki + 2 < DEC_KI) {
            dec_load_stage(sb, (ki + 2) % 3, ki + 2, bm, bn, tid); cp_commit();
            asm volatile("cp.async.wait_group 2;" ::: "memory");
        } else if (ki + 1 < DEC_KI) {
            asm volatile("cp.async.wait_group 1;" ::: "memory");
        } else {
            asm volatile("cp.async.wait_group 0;" ::: "memory");
        }
        __syncthreads();

        const uint32_t aB = sb + cur * DEC_STG + arow * 128;
        const uint32_t bB = sb + cur * DEC_STG + DEC_ASZ + brow * 128;
#pragma unroll
        for (int k16 = 0; k16 < 4; k16++) {
            uint32_t af[4][4], bf[4][4];
            const uint32_t acs = ((uint32_t)((k16 * 2 + ach) ^ as)) << 4;
            const uint32_t bcs = ((uint32_t)((k16 * 2 + bch) ^ bs)) << 4;
#pragma unroll
            for (int mi = 0; mi < 4; mi++) ldsm4(af[mi], aB + mi * 2048 + acs);
#pragma unroll
            for (int ni2 = 0; ni2 < 4; ni2++) ldsm4(bf[ni2], bB + ni2 * 2048 + bcs);
#pragma unroll
            for (int mi = 0; mi < 4; mi++)
#pragma unroll
                for (int ni = 0; ni < 8; ni++)
                    mma16816(acc[mi][ni], af[mi], bf[ni >> 1][(ni & 1) * 2],
                             bf[ni >> 1][(ni & 1) * 2 + 1]);
        }
        __syncthreads();
    }

    // ------------- epilogue: bias + topic*mask, fp32 out -------------
    float msk0[4], msk1[4];
#pragma unroll
    for (int mi = 0; mi < 4; mi++) {
        int m0 = bm + wm * 64 + mi * 16 + (lane >> 2);
        msk0[mi] = (stop[m0] == 0) ? 1.0f : 0.0f;
        msk1[mi] = (stop[m0 + 8] == 0) ? 1.0f : 0.0f;
    }
#pragma unroll
    for (int ni = 0; ni < 8; ni++) {
        int n0 = bn + wn * 64 + ni * 8 + (lane & 3) * 2;
        float2 bd = *(const float2*)(b_dec + n0);
        float2 tp = *(const float2*)(g_topic + n0);
#pragma unroll
        for (int mi = 0; mi < 4; mi++) {
            int m0 = bm + wm * 64 + mi * 16 + (lane >> 2);
            float2 o0, o1;
            o0.x = acc[mi][ni][0] + bd.x + tp.x * msk0[mi];
            o0.y = acc[mi][ni][1] + bd.y + tp.y * msk0[mi];
            o1.x = acc[mi][ni][2] + bd.x + tp.x * msk1[mi];
            o1.y = acc[mi][ni][3] + bd.y + tp.y * msk1[mi];
            *(float2*)(out + (size_t)m0 * Vv + n0) = o0;
            *(float2*)(out + (size_t)(m0 + 8) * Vv + n0) = o1;
        }
    }
}

// ------------------------- launch -------------------------
extern "C" void kernel_launch(void* const* d_in, const int* in_sizes, int n_in,
                              void* d_out, int out_size) {
    const int*   input_ids = (const int*)d_in[0];
    const float* hidden    = (const float*)d_in[1];
    const int*   stop      = (const int*)d_in[2];
    const float* W_emb     = (const float*)d_in[3];
    const float* W_ih      = (const float*)d_in[4];
    const float* b_ih      = (const float*)d_in[5];
    const float* W_hh      = (const float*)d_in[6];
    const float* b_hh      = (const float*)d_in[7];
    const float* W_dec     = (const float*)d_in[8];
    const float* b_dec     = (const float*)d_in[9];
    const float* beta      = (const float*)d_in[10];
    const float* theta     = (const float*)d_in[11];
    float* out = (float*)d_out;

    const int rnn_smem = 2 * 16 * RSTRIDE * (int)sizeof(float);
    cudaFuncSetAttribute(rnn_kernel, cudaFuncAttributeMaxDynamicSharedMemorySize, rnn_smem);
    cudaFuncSetAttribute(dec_mma, cudaFuncAttributeMaxDynamicSharedMemorySize, DEC_SMEM);

    topic_kernel<<<(Vv + 255) / 256, 256>>>(beta, theta);
    init_h_kernel<<<(Bb * Hh + 255) / 256, 256>>>(hidden);
    convB_kernel<<<(int)(((size_t)Vv * 1024) / 256), 256>>>(W_dec);
    embed_gemm<<<dim3(16, 8), 256>>>(input_ids, W_emb, W_ih, b_ih, b_hh);
    rnn_kernel<<<RNN_NB, 256, rnn_smem>>>(W_hh);
    convA_kernel<<<(2048 * 1024) / 256, 256>>>();
    dec_mma<<<dim3(16, 125), 256, DEC_SMEM>>>(b_dec, stop, out);
    copy_ht_kernel<<<(Bb * Hh + 255) / 256, 256>>>(out);
}

// round 6
// speedup vs baseline: 2.6645x; 1.3330x over previous
#include <cuda_runtime.h>
#include <cuda_bf16.h>
#include <math.h>
#include <stdint.h>

#define Vv 32000
#define Ee 512
#define Hh 1024
#define Bb 16
#define Ss 128
#define Kk 15

// ------------------------- device scratch (no allocs allowed) -------------------------
__device__ float g_G[Ss * Bb * Hh];          // [s][b][h] : x@W_ih^T + b_ih + b_hh
__device__ float g_H[2][Bb * Hh];            // ping-pong hidden state [b][h]
__device__ float g_topic[Vv];                // theta @ beta
__device__ unsigned g_bar_count;
__device__ unsigned g_bar_gen;
// bf16 operands for the decoder GEMM (single-pass bf16)
__device__ __nv_bfloat16 g_A2[2048 * 1024];       // [m = b*128+s][k]
__device__ __nv_bfloat16 g_B2[(size_t)Vv * 1024]; // [v][k]

// ------------------------- PTX helpers -------------------------
__device__ __forceinline__ uint32_t smem_u32(const void* p) {
    uint32_t a;
    asm("{ .reg .u64 t; cvta.to.shared.u64 t, %1; cvt.u32.u64 %0, t; }" : "=r"(a) : "l"(p));
    return a;
}
__device__ __forceinline__ void cp_async16(uint32_t dst, const void* src) {
    asm volatile("cp.async.cg.shared.global [%0], [%1], 16;" :: "r"(dst), "l"(src) : "memory");
}
__device__ __forceinline__ void cp_commit() { asm volatile("cp.async.commit_group;" ::: "memory"); }

__device__ __forceinline__ void ldsm4(uint32_t* r, uint32_t addr) {
    asm volatile("ldmatrix.sync.aligned.m8n8.x4.shared.b16 {%0,%1,%2,%3}, [%4];"
                 : "=r"(r[0]), "=r"(r[1]), "=r"(r[2]), "=r"(r[3]) : "r"(addr));
}
__device__ __forceinline__ void mma16816(float* c, const uint32_t* a, uint32_t b0, uint32_t b1) {
    asm volatile("mma.sync.aligned.m16n8k16.row.col.f32.bf16.bf16.f32 "
                 "{%0,%1,%2,%3}, {%4,%5,%6,%7}, {%8,%9}, {%0,%1,%2,%3};"
                 : "+f"(c[0]), "+f"(c[1]), "+f"(c[2]), "+f"(c[3])
                 : "r"(a[0]), "r"(a[1]), "r"(a[2]), "r"(a[3]), "r"(b0), "r"(b1));
}

__device__ __forceinline__ void grid_barrier(unsigned nblocks) {
    __syncthreads();
    if (threadIdx.x == 0) {
        unsigned my = *((volatile unsigned*)&g_bar_gen);
        __threadfence();
        if (atomicAdd(&g_bar_count, 1u) == nblocks - 1u) {
            g_bar_count = 0;
            __threadfence();
            atomicAdd(&g_bar_gen, 1u);
        } else {
            while (*((volatile unsigned*)&g_bar_gen) == my) { }
        }
        __threadfence();
    }
    __syncthreads();
}

// ------------------------- tiny kernels -------------------------
__global__ void topic_kernel(const float* __restrict__ beta, const float* __restrict__ theta) {
    int v = blockIdx.x * 256 + threadIdx.x;
    if (v < Vv) {
        float s = 0.f;
#pragma unroll
        for (int k = 0; k < Kk; k++) s += theta[k] * beta[k * Vv + v];
        g_topic[v] = s;
    }
}
__global__ void init_h_kernel(const float* __restrict__ hidden) {
    int i = blockIdx.x * 256 + threadIdx.x;
    if (i < Bb * Hh) g_H[0][i] = hidden[i];
}
__global__ void copy_ht_kernel(float* __restrict__ out) {
    int i = blockIdx.x * 256 + threadIdx.x;
    if (i < Bb * Hh) out[(size_t)Bb * Ss * Vv + i] = g_H[0][i];
}
// fp32 W_dec -> bf16 (single precision pass is sufficient: GEMM term is ~1e-3 of output)
__global__ void convB_kernel(const float* __restrict__ W_dec) {
    size_t i = (size_t)blockIdx.x * 256 + threadIdx.x;  // 32000*1024
    g_B2[i] = __float2bfloat16(W_dec[i]);
}

// ------------------------- embedding gather + input projection -------------------------
__global__ __launch_bounds__(256) void embed_gemm(const int* __restrict__ ids,
                                                  const float* __restrict__ W_emb,
                                                  const float* __restrict__ W_ih,
                                                  const float* __restrict__ b_ih,
                                                  const float* __restrict__ b_hh) {
    __shared__ __align__(16) float As[8][132];
    __shared__ __align__(16) float Bs[8][132];
    __shared__ int rowid[128];
    const int tid = threadIdx.x;
    const int bm = blockIdx.x * 128;
    const int bn = blockIdx.y * 128;
    if (tid < 128) {
        int m = bm + tid;
        rowid[tid] = ids[(m & 15) * Ss + (m >> 4)];
    }
    __syncthreads();
    const int lrow = tid >> 1;
    const int lk = (tid & 1) * 4;
    const float* Ap = W_emb + (size_t)rowid[lrow] * Ee + lk;
    const float* Bp = W_ih + (size_t)(bn + lrow) * Ee + lk;
    const int tx = tid & 15, ty = tid >> 4;
    float acc[8][8] = {};
    float4 av = *(const float4*)(Ap);
    float4 bv = *(const float4*)(Bp);
    for (int kt = 0; kt < Ee; kt += 8) {
        As[lk + 0][lrow] = av.x; As[lk + 1][lrow] = av.y;
        As[lk + 2][lrow] = av.z; As[lk + 3][lrow] = av.w;
        Bs[lk + 0][lrow] = bv.x; Bs[lk + 1][lrow] = bv.y;
        Bs[lk + 2][lrow] = bv.z; Bs[lk + 3][lrow] = bv.w;
        __syncthreads();
        if (kt + 8 < Ee) {
            av = *(const float4*)(Ap + kt + 8);
            bv = *(const float4*)(Bp + kt + 8);
        }
#pragma unroll
        for (int kk = 0; kk < 8; kk++) {
            float a[8], b[8];
            *(float4*)&a[0] = *(const float4*)&As[kk][ty * 8];
            *(float4*)&a[4] = *(const float4*)&As[kk][ty * 8 + 4];
            *(float4*)&b[0] = *(const float4*)&Bs[kk][tx * 8];
            *(float4*)&b[4] = *(const float4*)&Bs[kk][tx * 8 + 4];
#pragma unroll
            for (int i = 0; i < 8; i++)
#pragma unroll
                for (int j = 0; j < 8; j++) acc[i][j] = fmaf(a[i], b[j], acc[i][j]);
        }
        __syncthreads();
    }
#pragma unroll
    for (int i = 0; i < 8; i++) {
        int m = bm + ty * 8 + i;
#pragma unroll
        for (int j = 0; j < 8; j++) {
            int n = bn + tx * 8 + j;
            g_G[(size_t)m * Hh + n] = acc[i][j] + b_ih[n] + b_hh[n];
        }
    }
}

// ------------------------- persistent RNN recurrence -------------------------
// Writes decoder A operand (bf16) directly — no separate conversion pass.
#define RNN_NB 64
#define RSTRIDE 1028

__global__ __launch_bounds__(256, 1) void rnn_kernel(const float* __restrict__ W_hh) {
    extern __shared__ __align__(16) float smem[];
    float* Ws = smem;
    float* hs = smem + 16 * RSTRIDE;
    const int tid = threadIdx.x;
    const int n0 = blockIdx.x * 16;
    const int b = tid & 15;
    const int nl = tid >> 4;
    const int n = n0 + nl;

    for (int i = tid; i < 16 * (Hh / 4); i += 256) {
        int row = i >> 8;
        int q = i & 255;
        float4 v = *(const float4*)(W_hh + (size_t)(n0 + row) * Hh + q * 4);
        *(float4*)(Ws + row * RSTRIDE + q * 4) = v;
    }

    for (int s = 0; s < Ss; s++) {
        const int cur = s & 1;
        const float* hsrc = g_H[cur];
        for (int i = tid; i < 16 * (Hh / 4); i += 256) {
            int row = i >> 8;
            int q = i & 255;
            float4 v = __ldcg((const float4*)(hsrc + row * Hh + q * 4));
            *(float4*)(hs + row * RSTRIDE + q * 4) = v;
        }
        __syncthreads();

        const float* wrow = Ws + nl * RSTRIDE;
        const float* hrow = hs + b * RSTRIDE;
        float acc = g_G[(size_t)s * (Bb * Hh) + b * Hh + n];
#pragma unroll 4
        for (int k4 = 0; k4 < Hh / 4; k4++) {
            float4 w = *(const float4*)(wrow + k4 * 4);
            float4 h = *(const float4*)(hrow + k4 * 4);
            acc = fmaf(w.x, h.x, acc);
            acc = fmaf(w.y, h.y, acc);
            acc = fmaf(w.z, h.z, acc);
            acc = fmaf(w.w, h.w, acc);
        }
        float hv = tanhf(acc);
        __stcg(&g_H[cur ^ 1][b * Hh + n], hv);
        g_A2[((size_t)b * Ss + s) * Hh + n] = __float2bfloat16(hv);  // decoder A row m=b*128+s
        grid_barrier(RNN_NB);
    }
}

// ------------------------- tensor-core decoder GEMM (mma.sync bf16, single pass) -----
// out[m][v] = A2[m] . B2[v]  (K = 1024)
// CTA tile 128m x 256n, k-chunk 64; 8 warps (2 m x 4 n), warp tile 64x64.
#define DEC_KI 16
#define DEC_ASZ 16384              // 128 rows * 128 B
#define DEC_BSZ 32768              // 256 rows * 128 B
#define DEC_STG (DEC_ASZ + DEC_BSZ)
#define DEC_SMEM (3 * DEC_STG + 1024)

__device__ __forceinline__ void dec_load_stage(uint32_t sb, int stg, int ki,
                                               int bm, int bn, int tid) {
    uint32_t base = sb + stg * DEC_STG;
    const __nv_bfloat16* gA = g_A2 + (size_t)bm * 1024 + ki * 64;
    const __nv_bfloat16* gB = g_B2 + (size_t)bn * 1024 + ki * 64;
#pragma unroll
    for (int i = 0; i < 4; i++) {                  // A: 1024 x 16B
        int c = tid + i * 256;
        int r = c >> 3, cc = c & 7;
        cp_async16(base + r * 128 + (((cc ^ (r & 7)) & 7) << 4),
                   gA + (size_t)r * 1024 + cc * 8);
    }
#pragma unroll
    for (int i = 0; i < 8; i++) {                  // B: 2048 x 16B
        int c = tid + i * 256;
        int r = c >> 3, cc = c & 7;
        cp_async16(base + DEC_ASZ + r * 128 + (((cc ^ (r & 7)) & 7) << 4),
                   gB + (size_t)r * 1024 + cc * 8);
    }
}

__global__ __launch_bounds__(256, 1) void dec_mma(const float* __restrict__ b_dec,
                                                  const int* __restrict__ stop,
                                                  float* __restrict__ out) {
    extern __shared__ char dsm_raw[];
    const int tid = threadIdx.x;
    const int wid = tid >> 5;
    const int lane = tid & 31;
    const int wm = wid & 1;        // 2 m-warps
    const int wn = wid >> 1;       // 4 n-warps
    const int bm = blockIdx.x * 128;    // 16
    const int bn = blockIdx.y * 256;    // 125
    uint32_t sb = (smem_u32(dsm_raw) + 1023) & ~1023u;

    float acc[4][8][4];
#pragma unroll
    for (int i = 0; i < 4; i++)
#pragma unroll
        for (int j = 0; j < 8; j++)
#pragma unroll
            for (int q = 0; q < 4; q++) acc[i][j][q] = 0.f;

    const int arow = wm * 64 + (lane & 15);
    const int ach = lane >> 4;
    const int as = arow & 7;
    const int brow = wn * 64 + ((lane >> 4) << 3) + (lane & 7);
    const int bch = (lane >> 3) & 1;
    const int bs = brow & 7;

    dec_load_stage(sb, 0, 0, bm, bn, tid); cp_commit();
    dec_load_stage(sb, 1, 1, bm, bn, tid); cp_commit();

    for (int ki = 0; ki < DEC_KI; ki++) {
        const int cur = ki % 3;
        if (ki + 2 < DEC_KI) {
            dec_load_stage(sb, (ki + 2) % 3, ki + 2, bm, bn, tid); cp_commit();
            asm volatile("cp.async.wait_group 2;" ::: "memory");
        } else if (ki + 1 < DEC_KI) {
            asm volatile("cp.async.wait_group 1;" ::: "memory");
        } else {
            asm volatile("cp.async.wait_group 0;" ::: "memory");
        }
        __syncthreads();

        const uint32_t aB = sb + cur * DEC_STG + arow * 128;
        const uint32_t bB = sb + cur * DEC_STG + DEC_ASZ + brow * 128;
#pragma unroll
        for (int k16 = 0; k16 < 4; k16++) {
            uint32_t af[4][4], bf[4][4];
            const uint32_t acs = ((uint32_t)((k16 * 2 + ach) ^ as)) << 4;
            const uint32_t bcs = ((uint32_t)((k16 * 2 + bch) ^ bs)) << 4;
#pragma unroll
            for (int mi = 0; mi < 4; mi++) ldsm4(af[mi], aB + mi * 2048 + acs);
#pragma unroll
            for (int ni2 = 0; ni2 < 4; ni2++) ldsm4(bf[ni2], bB + ni2 * 2048 + bcs);
#pragma unroll
            for (int mi = 0; mi < 4; mi++)
#pragma unroll
                for (int ni = 0; ni < 8; ni++)
                    mma16816(acc[mi][ni], af[mi], bf[ni >> 1][(ni & 1) * 2],
                             bf[ni >> 1][(ni & 1) * 2 + 1]);
        }
        __syncthreads();
    }

    // ------------- epilogue: bias + topic*mask, fp32 out -------------
    float msk0[4], msk1[4];
#pragma unroll
    for (int mi = 0; mi < 4; mi++) {
        int m0 = bm + wm * 64 + mi * 16 + (lane >> 2);
        msk0[mi] = (stop[m0] == 0) ? 1.0f : 0.0f;
        msk1[mi] = (stop[m0 + 8] == 0) ? 1.0f : 0.0f;
    }
#pragma unroll
    for (int ni = 0; ni < 8; ni++) {
        int n0 = bn + wn * 64 + ni * 8 + (lane & 3) * 2;
        float2 bd = *(const float2*)(b_dec + n0);
        float2 tp = *(const float2*)(g_topic + n0);
#pragma unroll
        for (int mi = 0; mi < 4; mi++) {
            int m0 = bm + wm * 64 + mi * 16 + (lane >> 2);
            float2 o0, o1;
            o0.x = acc[mi][ni][0] + bd.x + tp.x * msk0[mi];
            o0.y = acc[mi][ni][1] + bd.y + tp.y * msk0[mi];
            o1.x = acc[mi][ni][2] + bd.x + tp.x * msk1[mi];
            o1.y = acc[mi][ni][3] + bd.y + tp.y * msk1[mi];
            *(float2*)(out + (size_t)m0 * Vv + n0) = o0;
            *(float2*)(out + (size_t)(m0 + 8) * Vv + n0) = o1;
        }
    }
}

// ------------------------- launch -------------------------
extern "C" void kernel_launch(void* const* d_in, const int* in_sizes, int n_in,
                              void* d_out, int out_size) {
    const int*   input_ids = (const int*)d_in[0];
    const float* hidden    = (const float*)d_in[1];
    const int*   stop      = (const int*)d_in[2];
    const float* W_emb     = (const float*)d_in[3];
    const float* W_ih      = (const float*)d_in[4];
    const float* b_ih      = (const float*)d_in[5];
    const float* W_hh      = (const float*)d_in[6];
    const float* b_hh      = (const float*)d_in[7];
    const float* W_dec     = (const float*)d_in[8];
    const float* b_dec     = (const float*)d_in[9];
    const float* beta      = (const float*)d_in[10];
    const float* theta     = (const float*)d_in[11];
    float* out = (float*)d_out;

    const int rnn_smem = 2 * 16 * RSTRIDE * (int)sizeof(float);
    cudaFuncSetAttribute(rnn_kernel, cudaFuncAttributeMaxDynamicSharedMemorySize, rnn_smem);
    cudaFuncSetAttribute(dec_mma, cudaFuncAttributeMaxDynamicSharedMemorySize, DEC_SMEM);

    topic_kernel<<<(Vv + 255) / 256, 256>>>(beta, theta);
    init_h_kernel<<<(Bb * Hh + 255) / 256, 256>>>(hidden);
    convB_kernel<<<(int)(((size_t)Vv * 1024) / 256), 256>>>(W_dec);
    embed_gemm<<<dim3(16, 8), 256>>>(input_ids, W_emb, W_ih, b_ih, b_hh);
    rnn_kernel<<<RNN_NB, 256, rnn_smem>>>(W_hh);
    dec_mma<<<dim3(16, 125), 256, DEC_SMEM>>>(b_dec, stop, out);
    copy_ht_kernel<<<(Bb * Hh + 255) / 256, 256>>>(out);
}

// round 8
// speedup vs baseline: 4.5160x; 1.6948x over previous
#include <cuda_runtime.h>
#include <cuda_bf16.h>
#include <math.h>
#include <stdint.h>

#define Vv 32000
#define Ee 512
#define Hh 1024
#define Bb 16
#define Ss 128
#define Kk 15

// ------------------------- device scratch (no allocs allowed) -------------------------
__device__ float g_G[Ss * Bb * Hh];          // [s][b][h] : x@W_ih^T + b_ih + b_hh
__device__ float g_H[2][Bb * Hh];            // ping-pong hidden state fp32 [b][h]
__device__ float g_Hf[Bb * Hh];              // final hidden hT (fp32)
__device__ float g_topic[Vv];                // theta @ beta
__device__ unsigned g_bar_count;
__device__ unsigned g_bar_gen;
// bf16 operands for the decoder GEMM
__device__ __nv_bfloat16 g_A2[2048 * 1024];       // [m = b*128+s][k]
__device__ __nv_bfloat16 g_B2[(size_t)Vv * 1024]; // [v][k]

// ------------------------- PTX helpers -------------------------
__device__ __forceinline__ uint32_t smem_u32(const void* p) {
    uint32_t a;
    asm("{ .reg .u64 t; cvta.to.shared.u64 t, %1; cvt.u32.u64 %0, t; }" : "=r"(a) : "l"(p));
    return a;
}
__device__ __forceinline__ void cp_async16(uint32_t dst, const void* src) {
    asm volatile("cp.async.cg.shared.global [%0], [%1], 16;" :: "r"(dst), "l"(src) : "memory");
}
__device__ __forceinline__ void cp_commit() { asm volatile("cp.async.commit_group;" ::: "memory"); }

__device__ __forceinline__ void ldsm4(uint32_t* r, uint32_t addr) {
    asm volatile("ldmatrix.sync.aligned.m8n8.x4.shared.b16 {%0,%1,%2,%3}, [%4];"
                 : "=r"(r[0]), "=r"(r[1]), "=r"(r[2]), "=r"(r[3]) : "r"(addr));
}
__device__ __forceinline__ void mma16816(float* c, const uint32_t* a, uint32_t b0, uint32_t b1) {
    asm volatile("mma.sync.aligned.m16n8k16.row.col.f32.bf16.bf16.f32 "
                 "{%0,%1,%2,%3}, {%4,%5,%6,%7}, {%8,%9}, {%0,%1,%2,%3};"
                 : "+f"(c[0]), "+f"(c[1]), "+f"(c[2]), "+f"(c[3])
                 : "r"(a[0]), "r"(a[1]), "r"(a[2]), "r"(a[3]), "r"(b0), "r"(b1));
}

__device__ __forceinline__ void grid_barrier(unsigned nblocks) {
    __syncthreads();
    if (threadIdx.x == 0) {
        unsigned my = *((volatile unsigned*)&g_bar_gen);
        __threadfence();
        if (atomicAdd(&g_bar_count, 1u) == nblocks - 1u) {
            g_bar_count = 0;
            __threadfence();
            atomicAdd(&g_bar_gen, 1u);
        } else {
            while (*((volatile unsigned*)&g_bar_gen) == my) { }
        }
        __threadfence();
    }
    __syncthreads();
}

// ------------------------- tiny kernels -------------------------
__global__ void topic_kernel(const float* __restrict__ beta, const float* __restrict__ theta) {
    int v = blockIdx.x * 256 + threadIdx.x;
    if (v < Vv) {
        float s = 0.f;
#pragma unroll
        for (int k = 0; k < Kk; k++) s += theta[k] * beta[k * Vv + v];
        g_topic[v] = s;
    }
}
__global__ void init_h_kernel(const float* __restrict__ hidden) {
    int i = blockIdx.x * 256 + threadIdx.x;
    if (i < Bb * Hh) g_H[0][i] = hidden[i];
}
__global__ void copy_ht_kernel(float* __restrict__ out) {
    int i = blockIdx.x * 256 + threadIdx.x;
    if (i < Bb * Hh) out[(size_t)Bb * Ss * Vv + i] = g_Hf[i];
}
__global__ void convB_kernel(const float* __restrict__ W_dec) {
    size_t i = (size_t)blockIdx.x * 256 + threadIdx.x;  // 32000*1024
    g_B2[i] = __float2bfloat16(W_dec[i]);
}

// ------------------------- embedding gather + input projection -------------------------
__global__ __launch_bounds__(256) void embed_gemm(const int* __restrict__ ids,
                                                  const float* __restrict__ W_emb,
                                                  const float* __restrict__ W_ih,
                                                  const float* __restrict__ b_ih,
                                                  const float* __restrict__ b_hh) {
    __shared__ __align__(16) float As[8][132];
    __shared__ __align__(16) float Bs[8][132];
    __shared__ int rowid[128];
    const int tid = threadIdx.x;
    const int bm = blockIdx.x * 128;
    const int bn = blockIdx.y * 128;
    if (tid < 128) {
        int m = bm + tid;
        rowid[tid] = ids[(m & 15) * Ss + (m >> 4)];
    }
    __syncthreads();
    const int lrow = tid >> 1;
    const int lk = (tid & 1) * 4;
    const float* Ap = W_emb + (size_t)rowid[lrow] * Ee + lk;
    const float* Bp = W_ih + (size_t)(bn + lrow) * Ee + lk;
    const int tx = tid & 15, ty = tid >> 4;
    float acc[8][8] = {};
    float4 av = *(const float4*)(Ap);
    float4 bv = *(const float4*)(Bp);
    for (int kt = 0; kt < Ee; kt += 8) {
        As[lk + 0][lrow] = av.x; As[lk + 1][lrow] = av.y;
        As[lk + 2][lrow] = av.z; As[lk + 3][lrow] = av.w;
        Bs[lk + 0][lrow] = bv.x; Bs[lk + 1][lrow] = bv.y;
        Bs[lk + 2][lrow] = bv.z; Bs[lk + 3][lrow] = bv.w;
        __syncthreads();
        if (kt + 8 < Ee) {
            av = *(const float4*)(Ap + kt + 8);
            bv = *(const float4*)(Bp + kt + 8);
        }
#pragma unroll
        for (int kk = 0; kk < 8; kk++) {
            float a[8], b[8];
            *(float4*)&a[0] = *(const float4*)&As[kk][ty * 8];
            *(float4*)&a[4] = *(const float4*)&As[kk][ty * 8 + 4];
            *(float4*)&b[0] = *(const float4*)&Bs[kk][tx * 8];
            *(float4*)&b[4] = *(const float4*)&Bs[kk][tx * 8 + 4];
#pragma unroll
            for (int i = 0; i < 8; i++)
#pragma unroll
                for (int j = 0; j < 8; j++) acc[i][j] = fmaf(a[i], b[j], acc[i][j]);
        }
        __syncthreads();
    }
#pragma unroll
    for (int i = 0; i < 8; i++) {
        int m = bm + ty * 8 + i;
#pragma unroll
        for (int j = 0; j < 8; j++) {
            int n = bn + tx * 8 + j;
            g_G[(size_t)m * Hh + n] = acc[i][j] + b_ih[n] + b_hh[n];
        }
    }
}

// ------------------------- persistent RNN recurrence (split-precision HMMA) ----------
// 64 blocks x 256 threads; block owns 16 n-columns. fp32 h state; per step matvec via
// 3-term bf16 K-concat:  W.h ~= Whi.hhi + Whi.hlo + Wlo.hhi  (error ~2^-18)
#define RNN_NB 64
#define WHI_OFF 0
#define WLO_OFF 32768
#define HHI_OFF 65536
#define HLO_OFF 98304
#define RNN_RED_OFF 131072
#define RNN_SMEM (131072 + 8 * 288 * 4)

__global__ __launch_bounds__(256, 1) void rnn_kernel(const float* __restrict__ W_hh) {
    extern __shared__ __align__(16) char rsm[];
    float* red = (float*)(rsm + RNN_RED_OFF);          // [8][16][18]
    const int tid = threadIdx.x;
    const int wid = tid >> 5;
    const int lane = tid & 31;
    const int n0 = blockIdx.x * 16;

    // load W_hh slice (16 rows), fp32 -> (hi, lo) bf16 slabs, XOR-swizzled 16B chunks
#pragma unroll
    for (int i = 0; i < 8; i++) {
        int c = tid + i * 256;                // 2048 chunks: r = c>>7, kc = c&127
        int r = c >> 7, kc = c & 127;
        const float* src = W_hh + (size_t)(n0 + r) * Hh + kc * 8;
        float4 v0 = *(const float4*)src;
        float4 v1 = *(const float4*)(src + 4);
        float x[8] = {v0.x, v0.y, v0.z, v0.w, v1.x, v1.y, v1.z, v1.w};
        __nv_bfloat16 hi[8], lo[8];
#pragma unroll
        for (int q = 0; q < 8; q++) {
            hi[q] = __float2bfloat16(x[q]);
            lo[q] = __float2bfloat16(x[q] - __bfloat162float(hi[q]));
        }
        uint32_t off = r * 2048 + (((kc ^ (r & 7)) & 127) << 4);
        *(uint4*)(rsm + WHI_OFF + off) = *(uint4*)hi;
        *(uint4*)(rsm + WLO_OFF + off) = *(uint4*)lo;
    }

    // ldmatrix lane addressing (verified layout from dec_mma / R7)
    const int arow = lane & 15;              // batch row
    const int ach = lane >> 4;
    const int brow = ((lane >> 4) << 3) + (lane & 7);   // n row
    const int bch = (lane >> 3) & 1;
    const int crow = lane >> 2, ccol = (lane & 3) * 2;
    const int rb = tid >> 4, rn = tid & 15;  // reduction output (b, n)
    const uint32_t smb = smem_u32(rsm);

    for (int s = 0; s < Ss; s++) {
        const int cur = s & 1;
        // stage h (fp32, 64KB) -> (hi, lo) bf16 slabs in SMEM
        const float* hsrc = g_H[cur];
#pragma unroll
        for (int i = 0; i < 8; i++) {
            int c = tid + i * 256;
            int r = c >> 7, kc = c & 127;
            const float* src = hsrc + r * Hh + kc * 8;
            float4 v0 = __ldcg((const float4*)src);
            float4 v1 = __ldcg((const float4*)(src + 4));
            float x[8] = {v0.x, v0.y, v0.z, v0.w, v1.x, v1.y, v1.z, v1.w};
            __nv_bfloat16 hi[8], lo[8];
#pragma unroll
            for (int q = 0; q < 8; q++) {
                hi[q] = __float2bfloat16(x[q]);
                lo[q] = __float2bfloat16(x[q] - __bfloat162float(hi[q]));
            }
            uint32_t off = r * 2048 + (((kc ^ (r & 7)) & 127) << 4);
            *(uint4*)(rsm + HHI_OFF + off) = *(uint4*)hi;
            *(uint4*)(rsm + HLO_OFF + off) = *(uint4*)lo;
        }
        __syncthreads();

        // split-K HMMA over 3 virtual passes: (hhi,Whi), (hlo,Whi), (hhi,Wlo)
        float acc0[4] = {0.f, 0.f, 0.f, 0.f};
        float acc1[4] = {0.f, 0.f, 0.f, 0.f};
#pragma unroll
        for (int t = 0; t < 3; t++) {
            const uint32_t aS = smb + ((t == 1) ? HLO_OFF : HHI_OFF) + arow * 2048;
            const uint32_t bS = smb + ((t == 2) ? WLO_OFF : WHI_OFF) + brow * 2048;
#pragma unroll
            for (int jj = 0; jj < 8; jj++) {
                int cj = (wid * 8 + jj) * 2;     // chunk index (2 x 16B per k16)
                uint32_t af[4], bf[4];
                ldsm4(af, aS + ((((cj + ach) ^ (arow & 7)) & 127) << 4));
                ldsm4(bf, bS + ((((cj + bch) ^ (brow & 7)) & 127) << 4));
                mma16816(acc0, af, bf[0], bf[1]);
                mma16816(acc1, af, bf[2], bf[3]);
            }
        }
        // store warp partials
        float* rw = red + wid * 288;
        rw[crow * 18 + ccol]           = acc0[0];
        rw[crow * 18 + ccol + 1]       = acc0[1];
        rw[(crow + 8) * 18 + ccol]     = acc0[2];
        rw[(crow + 8) * 18 + ccol + 1] = acc0[3];
        rw[crow * 18 + 8 + ccol]           = acc1[0];
        rw[crow * 18 + 8 + ccol + 1]       = acc1[1];
        rw[(crow + 8) * 18 + 8 + ccol]     = acc1[2];
        rw[(crow + 8) * 18 + 8 + ccol + 1] = acc1[3];
        __syncthreads();

        // reduce 8 partials + G, tanh, write next h (fp32) + decoder operand (bf16)
        float v = g_G[(size_t)s * (Bb * Hh) + rb * Hh + n0 + rn];
#pragma unroll
        for (int w = 0; w < 8; w++) v += red[w * 288 + rb * 18 + rn];
        float hv = tanhf(v);
        __stcg(&g_H[cur ^ 1][rb * Hh + n0 + rn], hv);
        g_A2[((size_t)rb * Ss + s) * Hh + n0 + rn] = __float2bfloat16(hv);
        if (s == Ss - 1) g_Hf[rb * Hh + n0 + rn] = hv;
        grid_barrier(RNN_NB);
    }
}

// ------------------------- tensor-core decoder GEMM (mma.sync bf16, single pass) -----
#define DEC_KI 16
#define DEC_ASZ 16384              // 128 rows * 128 B
#define DEC_BSZ 32768              // 256 rows * 128 B
#define DEC_STG (DEC_ASZ + DEC_BSZ)
#define DEC_SMEM (3 * DEC_STG + 1024)

__device__ __forceinline__ void dec_load_stage(uint32_t sb, int stg, int ki,
                                               int bm, int bn, int tid) {
    uint32_t base = sb + stg * DEC_STG;
    const __nv_bfloat16* gA = g_A2 + (size_t)bm * 1024 + ki * 64;
    const __nv_bfloat16* gB = g_B2 + (size_t)bn * 1024 + ki * 64;
#pragma unroll
    for (int i = 0; i < 4; i++) {                  // A: 1024 x 16B
        int c = tid + i * 256;
        int r = c >> 3, cc = c & 7;
        cp_async16(base + r * 128 + (((cc ^ (r & 7)) & 7) << 4),
                   gA + (size_t)r * 1024 + cc * 8);
    }
#pragma unroll
    for (int i = 0; i < 8; i++) {                  // B: 2048 x 16B
        int c = tid + i * 256;
        int r = c >> 3, cc = c & 7;
        cp_async16(base + DEC_ASZ + r * 128 + (((cc ^ (r & 7)) & 7) << 4),
                   gB + (size_t)r * 1024 + cc * 8);
    }
}

__global__ __launch_bounds__(256, 1) void dec_mma(const float* __restrict__ b_dec,
                                                  const int* __restrict__ stop,
                                                  float* __restrict__ out) {
    extern __shared__ char dsm_raw[];
    const int tid = threadIdx.x;
    const int wid = tid >> 5;
    const int lane = tid & 31;
    const int wm = wid & 1;
    const int wn = wid >> 1;
    const int bm = blockIdx.x * 128;    // 16
    const int bn = blockIdx.y * 256;    // 125
    uint32_t sb = (smem_u32(dsm_raw) + 1023) & ~1023u;

    float acc[4][8][4];
#pragma unroll
    for (int i = 0; i < 4; i++)
#pragma unroll
        for (int j = 0; j < 8; j++)
#pragma unroll
            for (int q = 0; q < 4; q++) acc[i][j][q] = 0.f;

    const int arow = wm * 64 + (lane & 15);
    const int ach = lane >> 4;
    const int as = arow & 7;
    const int brow = wn * 64 + ((lane >> 4) << 3) + (lane & 7);
    const int bch = (lane >> 3) & 1;
    const int bs = brow & 7;

    dec_load_stage(sb, 0, 0, bm, bn, tid); cp_commit();
    dec_load_stage(sb, 1, 1, bm, bn, tid); cp_commit();

    for (int ki = 0; ki < DEC_KI; ki++) {
        const int cur = ki % 3;
        if (ki + 2 < DEC_KI) {
            dec_load_stage(sb, (ki + 2) % 3, ki + 2, bm, bn, tid); cp_commit();
            asm volatile("cp.async.wait_group 2;" ::: "memory");
        } else if (ki + 1 < DEC_KI) {
            asm volatile("cp.async.wait_group 1;" ::: "memory");
        } else {
            asm volatile("cp.async.wait_group 0;" ::: "memory");
        }
        __syncthreads();

        const uint32_t aB = sb + cur * DEC_STG + arow * 128;
        const uint32_t bB = sb + cur * DEC_STG + DEC_ASZ + brow * 128;
#pragma unroll
        for (int k16 = 0; k16 < 4; k16++) {
            uint32_t af[4][4], bf[4][4];
            const uint32_t acs = ((uint32_t)((k16 * 2 + ach) ^ as)) << 4;
            const uint32_t bcs = ((uint32_t)((k16 * 2 + bch) ^ bs)) << 4;
#pragma unroll
            for (int mi = 0; mi < 4; mi++) ldsm4(af[mi], aB + mi * 2048 + acs);
#pragma unroll
            for (int ni2 = 0; ni2 < 4; ni2++) ldsm4(bf[ni2], bB + ni2 * 2048 + bcs);
#pragma unroll
            for (int mi = 0; mi < 4; mi++)
#pragma unroll
                for (int ni = 0; ni < 8; ni++)
                    mma16816(acc[mi][ni], af[mi], bf[ni >> 1][(ni & 1) * 2],
                             bf[ni >> 1][(ni & 1) * 2 + 1]);
        }
        __syncthreads();
    }

    // ------------- epilogue: bias + topic*mask, fp32 out -------------
    float msk0[4], msk1[4];
#pragma unroll
    for (int mi = 0; mi < 4; mi++) {
        int m0 = bm + wm * 64 + mi * 16 + (lane >> 2);
        msk0[mi] = (stop[m0] == 0) ? 1.0f : 0.0f;
        msk1[mi] = (stop[m0 + 8] == 0) ? 1.0f : 0.0f;
    }
#pragma unroll
    for (int ni = 0; ni < 8; ni++) {
        int n0 = bn + wn * 64 + ni * 8 + (lane & 3) * 2;
        float2 bd = *(const float2*)(b_dec + n0);
        float2 tp = *(const float2*)(g_topic + n0);
#pragma unroll
        for (int mi = 0; mi < 4; mi++) {
            int m0 = bm + wm * 64 + mi * 16 + (lane >> 2);
            float2 o0, o1;
            o0.x = acc[mi][ni][0] + bd.x + tp.x * msk0[mi];
            o0.y = acc[mi][ni][1] + bd.y + tp.y * msk0[mi];
            o1.x = acc[mi][ni][2] + bd.x + tp.x * msk1[mi];
            o1.y = acc[mi][ni][3] + bd.y + tp.y * msk1[mi];
            *(float2*)(out + (size_t)m0 * Vv + n0) = o0;
            *(float2*)(out + (size_t)(m0 + 8) * Vv + n0) = o1;
        }
    }
}

// ------------------------- launch -------------------------
extern "C" void kernel_launch(void* const* d_in, const int* in_sizes, int n_in,
                              void* d_out, int out_size) {
    const int*   input_ids = (const int*)d_in[0];
    const float* hidden    = (const float*)d_in[1];
    const int*   stop      = (const int*)d_in[2];
    const float* W_emb     = (const float*)d_in[3];
    const float* W_ih      = (const float*)d_in[4];
    const float* b_ih      = (const float*)d_in[5];
    const float* W_hh      = (const float*)d_in[6];
    const float* b_hh      = (const float*)d_in[7];
    const float* W_dec     = (const float*)d_in[8];
    const float* b_dec     = (const float*)d_in[9];
    const float* beta      = (const float*)d_in[10];
    const float* theta     = (const float*)d_in[11];
    float* out = (float*)d_out;

    cudaFuncSetAttribute(rnn_kernel, cudaFuncAttributeMaxDynamicSharedMemorySize, RNN_SMEM);
    cudaFuncSetAttribute(dec_mma, cudaFuncAttributeMaxDynamicSharedMemorySize, DEC_SMEM);

    topic_kernel<<<(Vv + 255) / 256, 256>>>(beta, theta);
    init_h_kernel<<<(Bb * Hh + 255) / 256, 256>>>(hidden);
    convB_kernel<<<(int)(((size_t)Vv * 1024) / 256), 256>>>(W_dec);
    embed_gemm<<<dim3(16, 8), 256>>>(input_ids, W_emb, W_ih, b_ih, b_hh);
    rnn_kernel<<<RNN_NB, 256, RNN_SMEM>>>(W_hh);
    dec_mma<<<dim3(16, 125), 256, DEC_SMEM>>>(b_dec, stop, out);
    copy_ht_kernel<<<(Bb * Hh + 255) / 256, 256>>>(out);
}

// round 9
// speedup vs baseline: 4.6232x; 1.0238x over previous
#include <cuda_runtime.h>
#include <cuda_bf16.h>
#include <math.h>
#include <stdint.h>

#define Vv 32000
#define Ee 512
#define Hh 1024
#define Bb 16
#define Ss 128
#define Kk 15

// ------------------------- device scratch (no allocs allowed) -------------------------
__device__ float g_G[Ss * Bb * Hh];               // [s][b][h] : x@W_ih^T + b_ih + b_hh
__device__ __nv_bfloat16 g_Hhi[2][Bb * Hh];       // ping-pong hidden, hi part (bf16)
__device__ __nv_bfloat16 g_Hlo[2][Bb * Hh];       // ping-pong hidden, lo part (bf16)
__device__ float g_Hf[Bb * Hh];                   // final hidden hT (fp32)
__device__ float g_topic[Vv];                     // theta @ beta
__device__ unsigned g_epoch;                      // bumped once per launch by init_h
__device__ unsigned g_flags[64];                  // per-CTA step flags (monotone values)
// bf16 operands for the decoder GEMM
__device__ __nv_bfloat16 g_A2[2048 * 1024];       // [m = b*128+s][k]
__device__ __nv_bfloat16 g_B2[(size_t)Vv * 1024]; // [v][k]

// ------------------------- PTX helpers -------------------------
__device__ __forceinline__ uint32_t smem_u32(const void* p) {
    uint32_t a;
    asm("{ .reg .u64 t; cvta.to.shared.u64 t, %1; cvt.u32.u64 %0, t; }" : "=r"(a) : "l"(p));
    return a;
}
__device__ __forceinline__ void cp_async16(uint32_t dst, const void* src) {
    asm volatile("cp.async.cg.shared.global [%0], [%1], 16;" :: "r"(dst), "l"(src) : "memory");
}
__device__ __forceinline__ void cp_commit() { asm volatile("cp.async.commit_group;" ::: "memory"); }

__device__ __forceinline__ void ldsm4(uint32_t* r, uint32_t addr) {
    asm volatile("ldmatrix.sync.aligned.m8n8.x4.shared.b16 {%0,%1,%2,%3}, [%4];"
                 : "=r"(r[0]), "=r"(r[1]), "=r"(r[2]), "=r"(r[3]) : "r"(addr));
}
__device__ __forceinline__ void mma16816(float* c, const uint32_t* a, uint32_t b0, uint32_t b1) {
    asm volatile("mma.sync.aligned.m16n8k16.row.col.f32.bf16.bf16.f32 "
                 "{%0,%1,%2,%3}, {%4,%5,%6,%7}, {%8,%9}, {%0,%1,%2,%3};"
                 : "+f"(c[0]), "+f"(c[1]), "+f"(c[2]), "+f"(c[3])
                 : "r"(a[0]), "r"(a[1]), "r"(a[2]), "r"(a[3]), "r"(b0), "r"(b1));
}

// ------------------------- tiny kernels -------------------------
__global__ void topic_kernel(const float* __restrict__ beta, const float* __restrict__ theta) {
    int v = blockIdx.x * 256 + threadIdx.x;
    if (v < Vv) {
        float s = 0.f;
#pragma unroll
        for (int k = 0; k < Kk; k++) s += theta[k] * beta[k * Vv + v];
        g_topic[v] = s;
    }
}
__global__ void init_h_kernel(const float* __restrict__ hidden) {
    int i = blockIdx.x * 256 + threadIdx.x;
    if (i < Bb * Hh) {
        float x = hidden[i];
        __nv_bfloat16 hi = __float2bfloat16(x);
        g_Hhi[0][i] = hi;
        g_Hlo[0][i] = __float2bfloat16(x - __bfloat162float(hi));
    }
    if (i == 0) g_epoch = g_epoch + 1;   // per-launch epoch (monotone, replay-safe)
}
__global__ void copy_ht_kernel(float* __restrict__ out) {
    int i = blockIdx.x * 256 + threadIdx.x;
    if (i < Bb * Hh) out[(size_t)Bb * Ss * Vv + i] = g_Hf[i];
}
__global__ void convB_kernel(const float* __restrict__ W_dec) {
    size_t i = (size_t)blockIdx.x * 256 + threadIdx.x;  // 32000*1024
    g_B2[i] = __float2bfloat16(W_dec[i]);
}

// ------------------------- embedding gather + input projection -------------------------
__global__ __launch_bounds__(256) void embed_gemm(const int* __restrict__ ids,
                                                  const float* __restrict__ W_emb,
                                                  const float* __restrict__ W_ih,
                                                  const float* __restrict__ b_ih,
                                                  const float* __restrict__ b_hh) {
    __shared__ __align__(16) float As[8][132];
    __shared__ __align__(16) float Bs[8][132];
    __shared__ int rowid[128];
    const int tid = threadIdx.x;
    const int bm = blockIdx.x * 128;
    const int bn = blockIdx.y * 128;
    if (tid < 128) {
        int m = bm + tid;
        rowid[tid] = ids[(m & 15) * Ss + (m >> 4)];
    }
    __syncthreads();
    const int lrow = tid >> 1;
    const int lk = (tid & 1) * 4;
    const float* Ap = W_emb + (size_t)rowid[lrow] * Ee + lk;
    const float* Bp = W_ih + (size_t)(bn + lrow) * Ee + lk;
    const int tx = tid & 15, ty = tid >> 4;
    float acc[8][8] = {};
    float4 av = *(const float4*)(Ap);
    float4 bv = *(const float4*)(Bp);
    for (int kt = 0; kt < Ee; kt += 8) {
        As[lk + 0][lrow] = av.x; As[lk + 1][lrow] = av.y;
        As[lk + 2][lrow] = av.z; As[lk + 3][lrow] = av.w;
        Bs[lk + 0][lrow] = bv.x; Bs[lk + 1][lrow] = bv.y;
        Bs[lk + 2][lrow] = bv.z; Bs[lk + 3][lrow] = bv.w;
        __syncthreads();
        if (kt + 8 < Ee) {
            av = *(const float4*)(Ap + kt + 8);
            bv = *(const float4*)(Bp + kt + 8);
        }
#pragma unroll
        for (int kk = 0; kk < 8; kk++) {
            float a[8], b[8];
            *(float4*)&a[0] = *(const float4*)&As[kk][ty * 8];
            *(float4*)&a[4] = *(const float4*)&As[kk][ty * 8 + 4];
            *(float4*)&b[0] = *(const float4*)&Bs[kk][tx * 8];
            *(float4*)&b[4] = *(const float4*)&Bs[kk][tx * 8 + 4];
#pragma unroll
            for (int i = 0; i < 8; i++)
#pragma unroll
                for (int j = 0; j < 8; j++) acc[i][j] = fmaf(a[i], b[j], acc[i][j]);
        }
        __syncthreads();
    }
#pragma unroll
    for (int i = 0; i < 8; i++) {
        int m = bm + ty * 8 + i;
#pragma unroll
        for (int j = 0; j < 8; j++) {
            int n = bn + tx * 8 + j;
            g_G[(size_t)m * Hh + n] = acc[i][j] + b_ih[n] + b_hh[n];
        }
    }
}

// ------------------------- persistent RNN recurrence (split-precision HMMA) ----------
// 64 blocks x 256 threads; block owns 16 n-columns. fp32-equivalent matvec via
// 3-term bf16 K-concat: W.h ~= Whi.hhi + Whi.hlo + Wlo.hhi.
// Cross-CTA sync: per-CTA monotone flag values (epoch*256 + s+1) — no atomic contention.
#define RNN_NB 64
#define WHI_OFF 0
#define WLO_OFF 32768
#define HHI_OFF 65536
#define HLO_OFF 98304
#define RNN_RED_OFF 131072
#define RNN_SMEM (131072 + 8 * 288 * 4)

__global__ __launch_bounds__(256, 1) void rnn_kernel(const float* __restrict__ W_hh) {
    extern __shared__ __align__(16) char rsm[];
    float* red = (float*)(rsm + RNN_RED_OFF);          // [8][16][18]
    const int tid = threadIdx.x;
    const int wid = tid >> 5;
    const int lane = tid & 31;
    const int n0 = blockIdx.x * 16;
    const unsigned base = g_epoch << 8;                // same value in all CTAs

    // load W_hh slice (16 rows), fp32 -> (hi, lo) bf16 slabs, XOR-swizzled 16B chunks
#pragma unroll
    for (int i = 0; i < 8; i++) {
        int c = tid + i * 256;                // 2048 chunks: r = c>>7, kc = c&127
        int r = c >> 7, kc = c & 127;
        const float* src = W_hh + (size_t)(n0 + r) * Hh + kc * 8;
        float4 v0 = *(const float4*)src;
        float4 v1 = *(const float4*)(src + 4);
        float x[8] = {v0.x, v0.y, v0.z, v0.w, v1.x, v1.y, v1.z, v1.w};
        __nv_bfloat16 hi[8], lo[8];
#pragma unroll
        for (int q = 0; q < 8; q++) {
            hi[q] = __float2bfloat16(x[q]);
            lo[q] = __float2bfloat16(x[q] - __bfloat162float(hi[q]));
        }
        uint32_t off = r * 2048 + (((kc ^ (r & 7)) & 127) << 4);
        *(uint4*)(rsm + WHI_OFF + off) = *(uint4*)hi;
        *(uint4*)(rsm + WLO_OFF + off) = *(uint4*)lo;
    }

    // ldmatrix lane addressing (verified layout)
    const int arow = lane & 15;              // batch row
    const int ach = lane >> 4;
    const int brow = ((lane >> 4) << 3) + (lane & 7);   // n row
    const int bch = (lane >> 3) & 1;
    const int crow = lane >> 2, ccol = (lane & 3) * 2;
    const int rb = tid >> 4, rn = tid & 15;  // reduction output (b, n)
    const uint32_t smb = smem_u32(rsm);

    for (int s = 0; s < Ss; s++) {
        const int cur = s & 1;
        // prefetch this step's G addend (launch-constant; hides behind wait+staging)
        float gval = __ldcg(&g_G[(size_t)s * (Bb * Hh) + rb * Hh + n0 + rn]);

        // wait for all CTAs to have published h of step s-1
        if (s > 0) {
            if (tid < RNN_NB) {
                while (((volatile unsigned*)g_flags)[tid] < base + (unsigned)s) { }
                __threadfence();
            }
            __syncthreads();
        }

        // stage h hi/lo slabs (raw bf16 copies, no conversion)
        const __nv_bfloat16* hh = g_Hhi[cur];
        const __nv_bfloat16* hl = g_Hlo[cur];
#pragma unroll
        for (int i = 0; i < 8; i++) {
            int c = tid + i * 256;
            int r = c >> 7, kc = c & 127;
            uint32_t off = r * 2048 + (((kc ^ (r & 7)) & 127) << 4);
            uint4 vh = __ldcg((const uint4*)(hh + r * Hh + kc * 8));
            uint4 vl = __ldcg((const uint4*)(hl + r * Hh + kc * 8));
            *(uint4*)(rsm + HHI_OFF + off) = vh;
            *(uint4*)(rsm + HLO_OFF + off) = vl;
        }
        __syncthreads();

        // split-K HMMA over 3 virtual passes: (hhi,Whi), (hlo,Whi), (hhi,Wlo)
        float acc0[4] = {0.f, 0.f, 0.f, 0.f};
        float acc1[4] = {0.f, 0.f, 0.f, 0.f};
#pragma unroll
        for (int t = 0; t < 3; t++) {
            const uint32_t aS = smb + ((t == 1) ? HLO_OFF : HHI_OFF) + arow * 2048;
            const uint32_t bS = smb + ((t == 2) ? WLO_OFF : WHI_OFF) + brow * 2048;
#pragma unroll
            for (int jj = 0; jj < 8; jj++) {
                int cj = (wid * 8 + jj) * 2;
                uint32_t af[4], bf[4];
                ldsm4(af, aS + ((((cj + ach) ^ (arow & 7)) & 127) << 4));
                ldsm4(bf, bS + ((((cj + bch) ^ (brow & 7)) & 127) << 4));
                mma16816(acc0, af, bf[0], bf[1]);
                mma16816(acc1, af, bf[2], bf[3]);
            }
        }
        // store warp partials
        float* rw = red + wid * 288;
        rw[crow * 18 + ccol]           = acc0[0];
        rw[crow * 18 + ccol + 1]       = acc0[1];
        rw[(crow + 8) * 18 + ccol]     = acc0[2];
        rw[(crow + 8) * 18 + ccol + 1] = acc0[3];
        rw[crow * 18 + 8 + ccol]           = acc1[0];
        rw[crow * 18 + 8 + ccol + 1]       = acc1[1];
        rw[(crow + 8) * 18 + 8 + ccol]     = acc1[2];
        rw[(crow + 8) * 18 + 8 + ccol + 1] = acc1[3];
        __syncthreads();

        // reduce 8 partials + G, tanh, publish next h (hi/lo) + decoder operand
        float v = gval;
#pragma unroll
        for (int w = 0; w < 8; w++) v += red[w * 288 + rb * 18 + rn];
        float hv = tanhf(v);
        __nv_bfloat16 hi = __float2bfloat16(hv);
        __nv_bfloat16 lo = __float2bfloat16(hv - __bfloat162float(hi));
        const int nxt = cur ^ 1;
        const int idx = rb * Hh + n0 + rn;
        g_Hhi[nxt][idx] = hi;
        g_Hlo[nxt][idx] = lo;
        g_A2[((size_t)rb * Ss + s) * Hh + n0 + rn] = hi;
        if (s == Ss - 1) g_Hf[idx] = hv;
        __syncthreads();
        if (tid == 0) {
            __threadfence();
            ((volatile unsigned*)g_flags)[blockIdx.x] = base + (unsigned)(s + 1);
        }
    }
}

// ------------------------- tensor-core decoder GEMM (mma.sync bf16, single pass) -----
#define DEC_KI 16
#define DEC_ASZ 16384              // 128 rows * 128 B
#define DEC_BSZ 32768              // 256 rows * 128 B
#define DEC_STG (DEC_ASZ + DEC_BSZ)
#define DEC_SMEM (3 * DEC_STG + 1024)

__device__ __forceinline__ void dec_load_stage(uint32_t sb, int stg, int ki,
                                               int bm, int bn, int tid) {
    uint32_t base = sb + stg * DEC_STG;
    const __nv_bfloat16* gA = g_A2 + (size_t)bm * 1024 + ki * 64;
    const __nv_bfloat16* gB = g_B2 + (size_t)bn * 1024 + ki * 64;
#pragma unroll
    for (int i = 0; i < 4; i++) {                  // A: 1024 x 16B
        int c = tid + i * 256;
        int r = c >> 3, cc = c & 7;
        cp_async16(base + r * 128 + (((cc ^ (r & 7)) & 7) << 4),
                   gA + (size_t)r * 1024 + cc * 8);
    }
#pragma unroll
    for (int i = 0; i < 8; i++) {                  // B: 2048 x 16B
        int c = tid + i * 256;
        int r = c >> 3, cc = c & 7;
        cp_async16(base + DEC_ASZ + r * 128 + (((cc ^ (r & 7)) & 7) << 4),
                   gB + (size_t)r * 1024 + cc * 8);
    }
}

__global__ __launch_bounds__(256, 1) void dec_mma(const float* __restrict__ b_dec,
                                                  const int* __restrict__ stop,
                                                  float* __restrict__ out) {
    extern __shared__ char dsm_raw[];
    const int tid = threadIdx.x;
    const int wid = tid >> 5;
    const int lane = tid & 31;
    const int wm = wid & 1;
    const int wn = wid >> 1;
    const int bm = blockIdx.x * 128;    // 16
    const int bn = blockIdx.y * 256;    // 125
    uint32_t sb = (smem_u32(dsm_raw) + 1023) & ~1023u;

    float acc[4][8][4];
#pragma unroll
    for (int i = 0; i < 4; i++)
#pragma unroll
        for (int j = 0; j < 8; j++)
#pragma unroll
            for (int q = 0; q < 4; q++) acc[i][j][q] = 0.f;

    const int arow = wm * 64 + (lane & 15);
    const int ach = lane >> 4;
    const int as = arow & 7;
    const int brow = wn * 64 + ((lane >> 4) << 3) + (lane & 7);
    const int bch = (lane >> 3) & 1;
    const int bs = brow & 7;

    dec_load_stage(sb, 0, 0, bm, bn, tid); cp_commit();
    dec_load_stage(sb, 1, 1, bm, bn, tid); cp_commit();

    for (int ki = 0; ki < DEC_KI; ki++) {
        const int cur = ki % 3;
        if (ki + 2 < DEC_KI) {
            dec_load_stage(sb, (ki + 2) % 3, ki + 2, bm, bn, tid); cp_commit();
            asm volatile("cp.async.wait_group 2;" ::: "memory");
        } else if (ki + 1 < DEC_KI) {
            asm volatile("cp.async.wait_group 1;" ::: "memory");
        } else {
            asm volatile("cp.async.wait_group 0;" ::: "memory");
        }
        __syncthreads();

        const uint32_t aB = sb + cur * DEC_STG + arow * 128;
        const uint32_t bB = sb + cur * DEC_STG + DEC_ASZ + brow * 128;
#pragma unroll
        for (int k16 = 0; k16 < 4; k16++) {
            uint32_t af[4][4], bf[4][4];
            const uint32_t acs = ((uint32_t)((k16 * 2 + ach) ^ as)) << 4;
            const uint32_t bcs = ((uint32_t)((k16 * 2 + bch) ^ bs)) << 4;
#pragma unroll
            for (int mi = 0; mi < 4; mi++) ldsm4(af[mi], aB + mi * 2048 + acs);
#pragma unroll
            for (int ni2 = 0; ni2 < 4; ni2++) ldsm4(bf[ni2], bB + ni2 * 2048 + bcs);
#pragma unroll
            for (int mi = 0; mi < 4; mi++)
#pragma unroll
                for (int ni = 0; ni < 8; ni++)
                    mma16816(acc[mi][ni], af[mi], bf[ni >> 1][(ni & 1) * 2],
                             bf[ni >> 1][(ni & 1) * 2 + 1]);
        }
        __syncthreads();
    }

    // ------------- epilogue: bias + topic*mask, fp32 out -------------
    float msk0[4], msk1[4];
#pragma unroll
    for (int mi = 0; mi < 4; mi++) {
        int m0 = bm + wm * 64 + mi * 16 + (lane >> 2);
        msk0[mi] = (stop[m0] == 0) ? 1.0f : 0.0f;
        msk1[mi] = (stop[m0 + 8] == 0) ? 1.0f : 0.0f;
    }
#pragma unroll
    for (int ni = 0; ni < 8; ni++) {
        int n0 = bn + wn * 64 + ni * 8 + (lane & 3) * 2;
        float2 bd = *(const float2*)(b_dec + n0);
        float2 tp = *(const float2*)(g_topic + n0);
#pragma unroll
        for (int mi = 0; mi < 4; mi++) {
            int m0 = bm + wm * 64 + mi * 16 + (lane >> 2);
            float2 o0, o1;
            o0.x = acc[mi][ni][0] + bd.x + tp.x * msk0[mi];
            o0.y = acc[mi][ni][1] + bd.y + tp.y * msk0[mi];
            o1.x = acc[mi][ni][2] + bd.x + tp.x * msk1[mi];
            o1.y = acc[mi][ni][3] + bd.y + tp.y * msk1[mi];
            *(float2*)(out + (size_t)m0 * Vv + n0) = o0;
            *(float2*)(out + (size_t)(m0 + 8) * Vv + n0) = o1;
        }
    }
}

// ------------------------- launch -------------------------
extern "C" void kernel_launch(void* const* d_in, const int* in_sizes, int n_in,
                              void* d_out, int out_size) {
    const int*   input_ids = (const int*)d_in[0];
    const float* hidden    = (const float*)d_in[1];
    const int*   stop      = (const int*)d_in[2];
    const float* W_emb     = (const float*)d_in[3];
    const float* W_ih      = (const float*)d_in[4];
    const float* b_ih      = (const float*)d_in[5];
    const float* W_hh      = (const float*)d_in[6];
    const float* b_hh      = (const float*)d_in[7];
    const float* W_dec     = (const float*)d_in[8];
    const float* b_dec     = (const float*)d_in[9];
    const float* beta      = (const float*)d_in[10];
    const float* theta     = (const float*)d_in[11];
    float* out = (float*)d_out;

    cudaFuncSetAttribute(rnn_kernel, cudaFuncAttributeMaxDynamicSharedMemorySize, RNN_SMEM);
    cudaFuncSetAttribute(dec_mma, cudaFuncAttributeMaxDynamicSharedMemorySize, DEC_SMEM);

    topic_kernel<<<(Vv + 255) / 256, 256>>>(beta, theta);
    init_h_kernel<<<(Bb * Hh + 255) / 256, 256>>>(hidden);
    convB_kernel<<<(int)(((size_t)Vv * 1024) / 256), 256>>>(W_dec);
    embed_gemm<<<dim3(16, 8), 256>>>(input_ids, W_emb, W_ih, b_ih, b_hh);
    rnn_kernel<<<RNN_NB, 256, RNN_SMEM>>>(W_hh);
    dec_mma<<<dim3(16, 125), 256, DEC_SMEM>>>(b_dec, stop, out);
    copy_ht_kernel<<<(Bb * Hh + 255) / 256, 256>>>(out);
}

// round 10
// speedup vs baseline: 5.2378x; 1.1329x over previous
#include <cuda_runtime.h>
#include <cuda_bf16.h>
#include <cuda_fp8.h>
#include <math.h>
#include <stdint.h>

#define Vv 32000
#define Ee 512
#define Hh 1024
#define Bb 16
#define Ss 128
#define Kk 15

// scales for fp8 quantization (epilogue divides them back out)
#define ASCALE 128.0f
#define BSCALE 256.0f

// ------------------------- device scratch (no allocs allowed) -------------------------
__device__ float g_G[Ss * Bb * Hh];               // [s][b][h] : x@W_ih^T + b_ih + b_hh
__device__ __nv_bfloat16 g_Hhi[2][Bb * Hh];       // ping-pong hidden, hi part (bf16)
__device__ __nv_bfloat16 g_Hlo[2][Bb * Hh];       // ping-pong hidden, lo part (bf16)
__device__ float g_Hf[Bb * Hh];                   // final hidden hT (fp32)
__device__ float g_topic[Vv];                     // theta @ beta
__device__ unsigned g_epoch;                      // bumped once per launch by init_h
__device__ unsigned g_flags[64];                  // per-CTA step flags (monotone values)
// fp8 operands for the decoder GEMM
__device__ uint8_t g_A8[2048 * 1024];             // [m = b*128+s][k]  (h * 128, e4m3)
__device__ uint8_t g_B8[(size_t)Vv * 1024];       // [v][k]            (W_dec * 256, e4m3)

// ------------------------- PTX helpers -------------------------
__device__ __forceinline__ uint32_t smem_u32(const void* p) {
    uint32_t a;
    asm("{ .reg .u64 t; cvta.to.shared.u64 t, %1; cvt.u32.u64 %0, t; }" : "=r"(a) : "l"(p));
    return a;
}
__device__ __forceinline__ void cp_async16(uint32_t dst, const void* src) {
    asm volatile("cp.async.cg.shared.global [%0], [%1], 16;" :: "r"(dst), "l"(src) : "memory");
}
__device__ __forceinline__ void cp_commit() { asm volatile("cp.async.commit_group;" ::: "memory"); }

__device__ __forceinline__ void ldsm4(uint32_t* r, uint32_t addr) {
    asm volatile("ldmatrix.sync.aligned.m8n8.x4.shared.b16 {%0,%1,%2,%3}, [%4];"
                 : "=r"(r[0]), "=r"(r[1]), "=r"(r[2]), "=r"(r[3]) : "r"(addr));
}
__device__ __forceinline__ void mma16816(float* c, const uint32_t* a, uint32_t b0, uint32_t b1) {
    asm volatile("mma.sync.aligned.m16n8k16.row.col.f32.bf16.bf16.f32 "
                 "{%0,%1,%2,%3}, {%4,%5,%6,%7}, {%8,%9}, {%0,%1,%2,%3};"
                 : "+f"(c[0]), "+f"(c[1]), "+f"(c[2]), "+f"(c[3])
                 : "r"(a[0]), "r"(a[1]), "r"(a[2]), "r"(a[3]), "r"(b0), "r"(b1));
}
__device__ __forceinline__ void mma16832f8(float* c, const uint32_t* a, uint32_t b0, uint32_t b1) {
    asm volatile("mma.sync.aligned.m16n8k32.row.col.f32.e4m3.e4m3.f32 "
                 "{%0,%1,%2,%3}, {%4,%5,%6,%7}, {%8,%9}, {%0,%1,%2,%3};"
                 : "+f"(c[0]), "+f"(c[1]), "+f"(c[2]), "+f"(c[3])
                 : "r"(a[0]), "r"(a[1]), "r"(a[2]), "r"(a[3]), "r"(b0), "r"(b1));
}
__device__ __forceinline__ uint8_t to_e4m3(float x) {
    return (uint8_t)__nv_cvt_float_to_fp8(x, __NV_SATFINITE, __NV_E4M3);
}

// ------------------------- tiny kernels -------------------------
__global__ void topic_kernel(const float* __restrict__ beta, const float* __restrict__ theta) {
    int v = blockIdx.x * 256 + threadIdx.x;
    if (v < Vv) {
        float s = 0.f;
#pragma unroll
        for (int k = 0; k < Kk; k++) s += theta[k] * beta[k * Vv + v];
        g_topic[v] = s;
    }
}
__global__ void init_h_kernel(const float* __restrict__ hidden) {
    int i = blockIdx.x * 256 + threadIdx.x;
    if (i < Bb * Hh) {
        float x = hidden[i];
        __nv_bfloat16 hi = __float2bfloat16(x);
        g_Hhi[0][i] = hi;
        g_Hlo[0][i] = __float2bfloat16(x - __bfloat162float(hi));
    }
    if (i == 0) g_epoch = g_epoch + 1;   // per-launch epoch (monotone, replay-safe)
}
__global__ void copy_ht_kernel(float* __restrict__ out) {
    int i = blockIdx.x * 256 + threadIdx.x;
    if (i < Bb * Hh) out[(size_t)Bb * Ss * Vv + i] = g_Hf[i];
}
// fp32 W_dec -> e4m3 * BSCALE (vectorized)
__global__ void convB_kernel(const float* __restrict__ W_dec) {
    size_t i = (size_t)blockIdx.x * 256 + threadIdx.x;   // over 8.192M float4 groups
    float4 v = ((const float4*)W_dec)[i];
    uchar4 o;
    o.x = to_e4m3(v.x * BSCALE);
    o.y = to_e4m3(v.y * BSCALE);
    o.z = to_e4m3(v.z * BSCALE);
    o.w = to_e4m3(v.w * BSCALE);
    ((uchar4*)g_B8)[i] = o;
}

// ------------------------- embedding gather + input projection -------------------------
__global__ __launch_bounds__(256) void embed_gemm(const int* __restrict__ ids,
                                                  const float* __restrict__ W_emb,
                                                  const float* __restrict__ W_ih,
                                                  const float* __restrict__ b_ih,
                                                  const float* __restrict__ b_hh) {
    __shared__ __align__(16) float As[8][132];
    __shared__ __align__(16) float Bs[8][132];
    __shared__ int rowid[128];
    const int tid = threadIdx.x;
    const int bm = blockIdx.x * 128;
    const int bn = blockIdx.y * 128;
    if (tid < 128) {
        int m = bm + tid;
        rowid[tid] = ids[(m & 15) * Ss + (m >> 4)];
    }
    __syncthreads();
    const int lrow = tid >> 1;
    const int lk = (tid & 1) * 4;
    const float* Ap = W_emb + (size_t)rowid[lrow] * Ee + lk;
    const float* Bp = W_ih + (size_t)(bn + lrow) * Ee + lk;
    const int tx = tid & 15, ty = tid >> 4;
    float acc[8][8] = {};
    float4 av = *(const float4*)(Ap);
    float4 bv = *(const float4*)(Bp);
    for (int kt = 0; kt < Ee; kt += 8) {
        As[lk + 0][lrow] = av.x; As[lk + 1][lrow] = av.y;
        As[lk + 2][lrow] = av.z; As[lk + 3][lrow] = av.w;
        Bs[lk + 0][lrow] = bv.x; Bs[lk + 1][lrow] = bv.y;
        Bs[lk + 2][lrow] = bv.z; Bs[lk + 3][lrow] = bv.w;
        __syncthreads();
        if (kt + 8 < Ee) {
            av = *(const float4*)(Ap + kt + 8);
            bv = *(const float4*)(Bp + kt + 8);
        }
#pragma unroll
        for (int kk = 0; kk < 8; kk++) {
            float a[8], b[8];
            *(float4*)&a[0] = *(const float4*)&As[kk][ty * 8];
            *(float4*)&a[4] = *(const float4*)&As[kk][ty * 8 + 4];
            *(float4*)&b[0] = *(const float4*)&Bs[kk][tx * 8];
            *(float4*)&b[4] = *(const float4*)&Bs[kk][tx * 8 + 4];
#pragma unroll
            for (int i = 0; i < 8; i++)
#pragma unroll
                for (int j = 0; j < 8; j++) acc[i][j] = fmaf(a[i], b[j], acc[i][j]);
        }
        __syncthreads();
    }
#pragma unroll
    for (int i = 0; i < 8; i++) {
        int m = bm + ty * 8 + i;
#pragma unroll
        for (int j = 0; j < 8; j++) {
            int n = bn + tx * 8 + j;
            g_G[(size_t)m * Hh + n] = acc[i][j] + b_ih[n] + b_hh[n];
        }
    }
}

// ------------------------- persistent RNN recurrence (split-precision HMMA) ----------
#define RNN_NB 64
#define WHI_OFF 0
#define WLO_OFF 32768
#define HHI_OFF 65536
#define HLO_OFF 98304
#define RNN_RED_OFF 131072
#define RNN_SMEM (131072 + 8 * 288 * 4)

__global__ __launch_bounds__(256, 1) void rnn_kernel(const float* __restrict__ W_hh) {
    extern __shared__ __align__(16) char rsm[];
    float* red = (float*)(rsm + RNN_RED_OFF);          // [8][16][18]
    const int tid = threadIdx.x;
    const int wid = tid >> 5;
    const int lane = tid & 31;
    const int n0 = blockIdx.x * 16;
    const unsigned base = g_epoch << 8;

    // load W_hh slice (16 rows), fp32 -> (hi, lo) bf16 slabs, XOR-swizzled 16B chunks
#pragma unroll
    for (int i = 0; i < 8; i++) {
        int c = tid + i * 256;
        int r = c >> 7, kc = c & 127;
        const float* src = W_hh + (size_t)(n0 + r) * Hh + kc * 8;
        float4 v0 = *(const float4*)src;
        float4 v1 = *(const float4*)(src + 4);
        float x[8] = {v0.x, v0.y, v0.z, v0.w, v1.x, v1.y, v1.z, v1.w};
        __nv_bfloat16 hi[8], lo[8];
#pragma unroll
        for (int q = 0; q < 8; q++) {
            hi[q] = __float2bfloat16(x[q]);
            lo[q] = __float2bfloat16(x[q] - __bfloat162float(hi[q]));
        }
        uint32_t off = r * 2048 + (((kc ^ (r & 7)) & 127) << 4);
        *(uint4*)(rsm + WHI_OFF + off) = *(uint4*)hi;
        *(uint4*)(rsm + WLO_OFF + off) = *(uint4*)lo;
    }

    const int arow = lane & 15;
    const int ach = lane >> 4;
    const int brow = ((lane >> 4) << 3) + (lane & 7);
    const int bch = (lane >> 3) & 1;
    const int crow = lane >> 2, ccol = (lane & 3) * 2;
    const int rb = tid >> 4, rn = tid & 15;
    const uint32_t smb = smem_u32(rsm);

    for (int s = 0; s < Ss; s++) {
        const int cur = s & 1;
        float gval = __ldcg(&g_G[(size_t)s * (Bb * Hh) + rb * Hh + n0 + rn]);

        if (s > 0) {
            if (tid < RNN_NB) {
                while (((volatile unsigned*)g_flags)[tid] < base + (unsigned)s) { }
                __threadfence();
            }
            __syncthreads();
        }

        // stage h hi/lo slabs via cp.async (no register round-trip)
        const __nv_bfloat16* hh = g_Hhi[cur];
        const __nv_bfloat16* hl = g_Hlo[cur];
#pragma unroll
        for (int i = 0; i < 8; i++) {
            int c = tid + i * 256;
            int r = c >> 7, kc = c & 127;
            uint32_t off = r * 2048 + (((kc ^ (r & 7)) & 127) << 4);
            cp_async16(smb + HHI_OFF + off, hh + r * Hh + kc * 8);
            cp_async16(smb + HLO_OFF + off, hl + r * Hh + kc * 8);
        }
        cp_commit();
        asm volatile("cp.async.wait_group 0;" ::: "memory");
        __syncthreads();

        // split-K HMMA, 3 virtual passes, 4 independent acc chains
        float a0e[4] = {}, a0o[4] = {}, a1e[4] = {}, a1o[4] = {};
#pragma unroll
        for (int t = 0; t < 3; t++) {
            const uint32_t aS = smb + ((t == 1) ? HLO_OFF : HHI_OFF) + arow * 2048;
            const uint32_t bS = smb + ((t == 2) ? WLO_OFF : WHI_OFF) + brow * 2048;
#pragma unroll
            for (int jj = 0; jj < 8; jj++) {
                int cj = (wid * 8 + jj) * 2;
                uint32_t af[4], bf[4];
                ldsm4(af, aS + ((((cj + ach) ^ (arow & 7)) & 127) << 4));
                ldsm4(bf, bS + ((((cj + bch) ^ (brow & 7)) & 127) << 4));
                if (jj & 1) {
                    mma16816(a0o, af, bf[0], bf[1]);
                    mma16816(a1o, af, bf[2], bf[3]);
                } else {
                    mma16816(a0e, af, bf[0], bf[1]);
                    mma16816(a1e, af, bf[2], bf[3]);
                }
            }
        }
        float* rw = red + wid * 288;
        rw[crow * 18 + ccol]           = a0e[0] + a0o[0];
        rw[crow * 18 + ccol + 1]       = a0e[1] + a0o[1];
        rw[(crow + 8) * 18 + ccol]     = a0e[2] + a0o[2];
        rw[(crow + 8) * 18 + ccol + 1] = a0e[3] + a0o[3];
        rw[crow * 18 + 8 + ccol]           = a1e[0] + a1o[0];
        rw[crow * 18 + 8 + ccol + 1]       = a1e[1] + a1o[1];
        rw[(crow + 8) * 18 + 8 + ccol]     = a1e[2] + a1o[2];
        rw[(crow + 8) * 18 + 8 + ccol + 1] = a1e[3] + a1o[3];
        __syncthreads();

        float v = gval;
#pragma unroll
        for (int w = 0; w < 8; w++) v += red[w * 288 + rb * 18 + rn];
        float hv = tanhf(v);
        __nv_bfloat16 hi = __float2bfloat16(hv);
        __nv_bfloat16 lo = __float2bfloat16(hv - __bfloat162float(hi));
        const int nxt = cur ^ 1;
        const int idx = rb * Hh + n0 + rn;
        g_Hhi[nxt][idx] = hi;
        g_Hlo[nxt][idx] = lo;
        __syncthreads();
        if (tid == 0) {
            __threadfence();
            ((volatile unsigned*)g_flags)[blockIdx.x] = base + (unsigned)(s + 1);
        }
        // non-critical stores after the flag publish (consumed only after kernel end)
        g_A8[((size_t)rb * Ss + s) * Hh + n0 + rn] = to_e4m3(hv * ASCALE);
        if (s == Ss - 1) g_Hf[idx] = hv;
    }
}

// ------------------------- tensor-core decoder GEMM (mma.sync e4m3, single pass) -----
// Same 128B-row SMEM geometry as bf16 version (k32 fp8 tile == 32 B == k16 bf16 tile).
#define DEC_KI 8
#define DEC_ASZ 16384              // 128 rows * 128 B
#define DEC_BSZ 32768              // 256 rows * 128 B
#define DEC_STG (DEC_ASZ + DEC_BSZ)
#define DEC_SMEM (3 * DEC_STG + 1024)

__device__ __forceinline__ void dec_load_stage(uint32_t sb, int stg, int ki,
                                               int bm, int bn, int tid) {
    uint32_t base = sb + stg * DEC_STG;
    const uint8_t* gA = g_A8 + (size_t)bm * 1024 + ki * 128;
    const uint8_t* gB = g_B8 + (size_t)bn * 1024 + ki * 128;
#pragma unroll
    for (int i = 0; i < 4; i++) {                  // A: 1024 x 16B
        int c = tid + i * 256;
        int r = c >> 3, cc = c & 7;
        cp_async16(base + r * 128 + (((cc ^ (r & 7)) & 7) << 4),
                   gA + (size_t)r * 1024 + cc * 16);
    }
#pragma unroll
    for (int i = 0; i < 8; i++) {                  // B: 2048 x 16B
        int c = tid + i * 256;
        int r = c >> 3, cc = c & 7;
        cp_async16(base + DEC_ASZ + r * 128 + (((cc ^ (r & 7)) & 7) << 4),
                   gB + (size_t)r * 1024 + cc * 16);
    }
}

__global__ __launch_bounds__(256, 1) void dec_mma(const float* __restrict__ b_dec,
                                                  const int* __restrict__ stop,
                                                  float* __restrict__ out) {
    extern __shared__ char dsm_raw[];
    const int tid = threadIdx.x;
    const int wid = tid >> 5;
    const int lane = tid & 31;
    const int wm = wid & 1;
    const int wn = wid >> 1;
    const int bm = blockIdx.x * 128;    // 16
    const int bn = blockIdx.y * 256;    // 125
    uint32_t sb = (smem_u32(dsm_raw) + 1023) & ~1023u;

    float acc[4][8][4];
#pragma unroll
    for (int i = 0; i < 4; i++)
#pragma unroll
        for (int j = 0; j < 8; j++)
#pragma unroll
            for (int q = 0; q < 4; q++) acc[i][j][q] = 0.f;

    const int arow = wm * 64 + (lane & 15);
    const int ach = lane >> 4;
    const int as = arow & 7;
    const int brow = wn * 64 + ((lane >> 4) << 3) + (lane & 7);
    const int bch = (lane >> 3) & 1;
    const int bs = brow & 7;

    dec_load_stage(sb, 0, 0, bm, bn, tid); cp_commit();
    dec_load_stage(sb, 1, 1, bm, bn, tid); cp_commit();

    for (int ki = 0; ki < DEC_KI; ki++) {
        const int cur = ki % 3;
        if (ki + 2 < DEC_KI) {
            dec_load_stage(sb, (ki + 2) % 3, ki + 2, bm, bn, tid); cp_commit();
            asm volatile("cp.async.wait_group 2;" ::: "memory");
        } else if (ki + 1 < DEC_KI) {
            asm volatile("cp.async.wait_group 1;" ::: "memory");
        } else {
            asm volatile("cp.async.wait_group 0;" ::: "memory");
        }
        __syncthreads();

        const uint32_t aB = sb + cur * DEC_STG + arow * 128;
        const uint32_t bB = sb + cur * DEC_STG + DEC_ASZ + brow * 128;
#pragma unroll
        for (int kt = 0; kt < 4; kt++) {           // 4 x k32 fp8 tiles per 128B chunk
            uint32_t af[4][4], bf[4][4];
            const uint32_t acs = ((uint32_t)((kt * 2 + ach) ^ as)) << 4;
            const uint32_t bcs = ((uint32_t)((kt * 2 + bch) ^ bs)) << 4;
#pragma unroll
            for (int mi = 0; mi < 4; mi++) ldsm4(af[mi], aB + mi * 2048 + acs);
#pragma unroll
            for (int ni2 = 0; ni2 < 4; ni2++) ldsm4(bf[ni2], bB + ni2 * 2048 + bcs);
#pragma unroll
            for (int mi = 0; mi < 4; mi++)
#pragma unroll
                for (int ni = 0; ni < 8; ni++)
                    mma16832f8(acc[mi][ni], af[mi], bf[ni >> 1][(ni & 1) * 2],
                               bf[ni >> 1][(ni & 1) * 2 + 1]);
        }
        __syncthreads();
    }

    // ------------- epilogue: rescale + bias + topic*mask -------------
    const float SC = 1.0f / (ASCALE * BSCALE);
    float msk0[4], msk1[4];
#pragma unroll
    for (int mi = 0; mi < 4; mi++) {
        int m0 = bm + wm * 64 + mi * 16 + (lane >> 2);
        msk0[mi] = (stop[m0] == 0) ? 1.0f : 0.0f;
        msk1[mi] = (stop[m0 + 8] == 0) ? 1.0f : 0.0f;
    }
#pragma unroll
    for (int ni = 0; ni < 8; ni++) {
        int n0 = bn + wn * 64 + ni * 8 + (lane & 3) * 2;
        float2 bd = *(const float2*)(b_dec + n0);
        float2 tp = *(const float2*)(g_topic + n0);
#pragma unroll
        for (int mi = 0; mi < 4; mi++) {
            int m0 = bm + wm * 64 + mi * 16 + (lane >> 2);
            float2 o0, o1;
            o0.x = acc[mi][ni][0] * SC + bd.x + tp.x * msk0[mi];
            o0.y = acc[mi][ni][1] * SC + bd.y + tp.y * msk0[mi];
            o1.x = acc[mi][ni][2] * SC + bd.x + tp.x * msk1[mi];
            o1.y = acc[mi][ni][3] * SC + bd.y + tp.y * msk1[mi];
            *(float2*)(out + (size_t)m0 * Vv + n0) = o0;
            *(float2*)(out + (size_t)(m0 + 8) * Vv + n0) = o1;
        }
    }
}

// ------------------------- launch -------------------------
extern "C" void kernel_launch(void* const* d_in, const int* in_sizes, int n_in,
                              void* d_out, int out_size) {
    const int*   input_ids = (const int*)d_in[0];
    const float* hidden    = (const float*)d_in[1];
    const int*   stop      = (const int*)d_in[2];
    const float* W_emb     = (const float*)d_in[3];
    const float* W_ih      = (const float*)d_in[4];
    const float* b_ih      = (const float*)d_in[5];
    const float* W_hh      = (const float*)d_in[6];
    const float* b_hh      = (const float*)d_in[7];
    const float* W_dec     = (const float*)d_in[8];
    const float* b_dec     = (const float*)d_in[9];
    const float* beta      = (const float*)d_in[10];
    const float* theta     = (const float*)d_in[11];
    float* out = (float*)d_out;

    cudaFuncSetAttribute(rnn_kernel, cudaFuncAttributeMaxDynamicSharedMemorySize, RNN_SMEM);
    cudaFuncSetAttribute(dec_mma, cudaFuncAttributeMaxDynamicSharedMemorySize, DEC_SMEM);

    // side streams / events (host-side handles only; created once, same work every call)
    static cudaStream_t sA = nullptr, sB = nullptr;
    static cudaEvent_t eF = nullptr, eA = nullptr, eB = nullptr, eR = nullptr, eC = nullptr;
    if (sA == nullptr) {
        cudaStreamCreateWithFlags(&sA, cudaStreamNonBlocking);
        cudaStreamCreateWithFlags(&sB, cudaStreamNonBlocking);
        cudaEventCreateWithFlags(&eF, cudaEventDisableTiming);
        cudaEventCreateWithFlags(&eA, cudaEventDisableTiming);
        cudaEventCreateWithFlags(&eB, cudaEventDisableTiming);
        cudaEventCreateWithFlags(&eR, cudaEventDisableTiming);
        cudaEventCreateWithFlags(&eC, cudaEventDisableTiming);
    }

    // fork: convB on sA; topic+init on sB; embed on main
    cudaEventRecord(eF, 0);
    cudaStreamWaitEvent(sA, eF, 0);
    cudaStreamWaitEvent(sB, eF, 0);
    convB_kernel<<<(int)(((size_t)Vv * 1024 / 4) / 256), 256, 0, sA>>>(W_dec);
    topic_kernel<<<(Vv + 255) / 256, 256, 0, sB>>>(beta, theta);
    init_h_kernel<<<(Bb * Hh + 255) / 256, 256, 0, sB>>>(hidden);
    embed_gemm<<<dim3(16, 8), 256>>>(input_ids, W_emb, W_ih, b_ih, b_hh);
    cudaEventRecord(eA, sA);
    cudaEventRecord(eB, sB);
    cudaStreamWaitEvent(0, eA, 0);
    cudaStreamWaitEvent(0, eB, 0);

    rnn_kernel<<<RNN_NB, 256, RNN_SMEM>>>(W_hh);

    // fork after rnn: copy_ht on sA overlaps dec on main
    cudaEventRecord(eR, 0);
    cudaStreamWaitEvent(sA, eR, 0);
    copy_ht_kernel<<<(Bb * Hh + 255) / 256, 256, 0, sA>>>(out);
    dec_mma<<<dim3(16, 125), 256, DEC_SMEM>>>(b_dec, stop, out);
    cudaEventRecord(eC, sA);
    cudaStreamWaitEvent(0, eC, 0);
}

// round 12
// speedup vs baseline: 5.6858x; 1.0855x over previous
#include <cuda_runtime.h>
#include <cuda_bf16.h>
#include <cuda_fp8.h>
#include <math.h>
#include <stdint.h>

#define Vv 32000
#define Ee 512
#define Hh 1024
#define Bb 16
#define Ss 128
#define Kk 15

#define ASCALE 128.0f
#define BSCALE 256.0f

// ------------------------- device scratch (no allocs allowed) -------------------------
__device__ float g_G[Ss * Bb * Hh];               // [s][b][h]
__device__ __nv_bfloat16 g_Hhi[2][Bb * Hh];
__device__ __nv_bfloat16 g_Hlo[2][Bb * Hh];
__device__ float g_topic[Vv];
__device__ unsigned g_epoch;                      // bumped each launch (init_h)
__device__ unsigned g_flags[64 * 32];             // per-rnn-CTA flag, 1 per 128B line
__device__ unsigned g_tile;                       // dec tile queue head (reset each launch)
// fp8 decoder operands
__device__ uint8_t g_A8[2048 * 1024];             // [m = s*16+b][k]  (h * 128, e4m3)
__device__ uint8_t g_B8[(size_t)Vv * 1024];       // [v][k]           (W_dec * 256, e4m3)

// ------------------------- PTX helpers -------------------------
__device__ __forceinline__ uint32_t smem_u32(const void* p) {
    uint32_t a;
    asm("{ .reg .u64 t; cvta.to.shared.u64 t, %1; cvt.u32.u64 %0, t; }" : "=r"(a) : "l"(p));
    return a;
}
__device__ __forceinline__ void cp_async16(uint32_t dst, const void* src) {
    asm volatile("cp.async.cg.shared.global [%0], [%1], 16;" :: "r"(dst), "l"(src) : "memory");
}
__device__ __forceinline__ void cp_commit() { asm volatile("cp.async.commit_group;" ::: "memory"); }

__device__ __forceinline__ void ldsm4(uint32_t* r, uint32_t addr) {
    asm volatile("ldmatrix.sync.aligned.m8n8.x4.shared.b16 {%0,%1,%2,%3}, [%4];"
                 : "=r"(r[0]), "=r"(r[1]), "=r"(r[2]), "=r"(r[3]) : "r"(addr));
}
__device__ __forceinline__ void mma16816(float* c, const uint32_t* a, uint32_t b0, uint32_t b1) {
    asm volatile("mma.sync.aligned.m16n8k16.row.col.f32.bf16.bf16.f32 "
                 "{%0,%1,%2,%3}, {%4,%5,%6,%7}, {%8,%9}, {%0,%1,%2,%3};"
                 : "+f"(c[0]), "+f"(c[1]), "+f"(c[2]), "+f"(c[3])
                 : "r"(a[0]), "r"(a[1]), "r"(a[2]), "r"(a[3]), "r"(b0), "r"(b1));
}
__device__ __forceinline__ void mma16832f8(float* c, const uint32_t* a, uint32_t b0, uint32_t b1) {
    asm volatile("mma.sync.aligned.m16n8k32.row.col.f32.e4m3.e4m3.f32 "
                 "{%0,%1,%2,%3}, {%4,%5,%6,%7}, {%8,%9}, {%0,%1,%2,%3};"
                 : "+f"(c[0]), "+f"(c[1]), "+f"(c[2]), "+f"(c[3])
                 : "r"(a[0]), "r"(a[1]), "r"(a[2]), "r"(a[3]), "r"(b0), "r"(b1));
}
__device__ __forceinline__ uint8_t to_e4m3(float x) {
    return (uint8_t)__nv_cvt_float_to_fp8(x, __NV_SATFINITE, __NV_E4M3);
}

// ------------------------- tiny kernels -------------------------
__global__ void topic_kernel(const float* __restrict__ beta, const float* __restrict__ theta) {
    int v = blockIdx.x * 256 + threadIdx.x;
    if (v < Vv) {
        float s = 0.f;
#pragma unroll
        for (int k = 0; k < Kk; k++) s += theta[k] * beta[k * Vv + v];
        g_topic[v] = s;
    }
}
__global__ void init_h_kernel(const float* __restrict__ hidden) {
    int i = blockIdx.x * 256 + threadIdx.x;
    if (i < Bb * Hh) {
        float x = hidden[i];
        __nv_bfloat16 hi = __float2bfloat16(x);
        g_Hhi[0][i] = hi;
        g_Hlo[0][i] = __float2bfloat16(x - __bfloat162float(hi));
    }
    if (i == 0) { g_epoch = g_epoch + 1; g_tile = 0; }
}
__global__ void convB_kernel(const float* __restrict__ W_dec) {
    size_t i = (size_t)blockIdx.x * 256 + threadIdx.x;   // float4 groups
    float4 v = ((const float4*)W_dec)[i];
    uchar4 o;
    o.x = to_e4m3(v.x * BSCALE);
    o.y = to_e4m3(v.y * BSCALE);
    o.z = to_e4m3(v.z * BSCALE);
    o.w = to_e4m3(v.w * BSCALE);
    ((uchar4*)g_B8)[i] = o;
}

// ------------------------- embedding gather + input projection -------------------------
__global__ __launch_bounds__(256) void embed_gemm(const int* __restrict__ ids,
                                                  const float* __restrict__ W_emb,
                                                  const float* __restrict__ W_ih,
                                                  const float* __restrict__ b_ih,
                                                  const float* __restrict__ b_hh) {
    __shared__ __align__(16) float As[8][132];
    __shared__ __align__(16) float Bs[8][132];
    __shared__ int rowid[128];
    const int tid = threadIdx.x;
    const int bm = blockIdx.x * 128;
    const int bn = blockIdx.y * 128;
    if (tid < 128) {
        int m = bm + tid;
        rowid[tid] = ids[(m & 15) * Ss + (m >> 4)];
    }
    __syncthreads();
    const int lrow = tid >> 1;
    const int lk = (tid & 1) * 4;
    const float* Ap = W_emb + (size_t)rowid[lrow] * Ee + lk;
    const float* Bp = W_ih + (size_t)(bn + lrow) * Ee + lk;
    const int tx = tid & 15, ty = tid >> 4;
    float acc[8][8] = {};
    float4 av = *(const float4*)(Ap);
    float4 bv = *(const float4*)(Bp);
    for (int kt = 0; kt < Ee; kt += 8) {
        As[lk + 0][lrow] = av.x; As[lk + 1][lrow] = av.y;
        As[lk + 2][lrow] = av.z; As[lk + 3][lrow] = av.w;
        Bs[lk + 0][lrow] = bv.x; Bs[lk + 1][lrow] = bv.y;
        Bs[lk + 2][lrow] = bv.z; Bs[lk + 3][lrow] = bv.w;
        __syncthreads();
        if (kt + 8 < Ee) {
            av = *(const float4*)(Ap + kt + 8);
            bv = *(const float4*)(Bp + kt + 8);
        }
#pragma unroll
        for (int kk = 0; kk < 8; kk++) {
            float a[8], b[8];
            *(float4*)&a[0] = *(const float4*)&As[kk][ty * 8];
            *(float4*)&a[4] = *(const float4*)&As[kk][ty * 8 + 4];
            *(float4*)&b[0] = *(const float4*)&Bs[kk][tx * 8];
            *(float4*)&b[4] = *(const float4*)&Bs[kk][tx * 8 + 4];
#pragma unroll
            for (int i = 0; i < 8; i++)
#pragma unroll
                for (int j = 0; j < 8; j++) acc[i][j] = fmaf(a[i], b[j], acc[i][j]);
        }
        __syncthreads();
    }
#pragma unroll
    for (int i = 0; i < 8; i++) {
        int m = bm + ty * 8 + i;
#pragma unroll
        for (int j = 0; j < 8; j++) {
            int n = bn + tx * 8 + j;
            g_G[(size_t)m * Hh + n] = acc[i][j] + b_ih[n] + b_hh[n];
        }
    }
}

// ------------------------- fused persistent kernel: rnn + dec -------------------------
#define RNN_NB 64
#define CMB_NB 148
#define N_TILES (16 * 125)
#define WHI_OFF 0
#define WLO_OFF 32768
#define HHI_OFF 65536
#define HLO_OFF 98304
#define RNN_RED_OFF 131072
#define DEC_ASZ 16384
#define DEC_BSZ 32768
#define DEC_STG (DEC_ASZ + DEC_BSZ)
#define FUSED_SMEM (3 * DEC_STG + 1024)           // 148480 >= rnn's 140288

// ---- rnn role ----
__device__ void rnn_role(char* rsm, const float* __restrict__ W_hh,
                         float* __restrict__ out, unsigned base) {
    float* red = (float*)(rsm + RNN_RED_OFF);
    const int tid = threadIdx.x;
    const int wid = tid >> 5;
    const int lane = tid & 31;
    const int n0 = blockIdx.x * 16;

#pragma unroll
    for (int i = 0; i < 8; i++) {
        int c = tid + i * 256;
        int r = c >> 7, kc = c & 127;
        const float* src = W_hh + (size_t)(n0 + r) * Hh + kc * 8;
        float4 v0 = *(const float4*)src;
        float4 v1 = *(const float4*)(src + 4);
        float x[8] = {v0.x, v0.y, v0.z, v0.w, v1.x, v1.y, v1.z, v1.w};
        __nv_bfloat16 hi[8], lo[8];
#pragma unroll
        for (int q = 0; q < 8; q++) {
            hi[q] = __float2bfloat16(x[q]);
            lo[q] = __float2bfloat16(x[q] - __bfloat162float(hi[q]));
        }
        uint32_t off = r * 2048 + (((kc ^ (r & 7)) & 127) << 4);
        *(uint4*)(rsm + WHI_OFF + off) = *(uint4*)hi;
        *(uint4*)(rsm + WLO_OFF + off) = *(uint4*)lo;
    }

    const int arow = lane & 15;
    const int ach = lane >> 4;
    const int brow = ((lane >> 4) << 3) + (lane & 7);
    const int bch = (lane >> 3) & 1;
    const int crow = lane >> 2, ccol = (lane & 3) * 2;
    const int rb = tid >> 4, rn = tid & 15;
    const uint32_t smb = smem_u32(rsm);

    for (int s = 0; s < Ss; s++) {
        const int cur = s & 1;
        float gval = __ldcg(&g_G[(size_t)s * (Bb * Hh) + rb * Hh + n0 + rn]);

        if (s > 0) {
            if (tid < RNN_NB) {
                while (((volatile unsigned*)g_flags)[tid * 32] < base + (unsigned)s) { }
                __threadfence();
            }
            __syncthreads();
        }

        const __nv_bfloat16* hh = g_Hhi[cur];
        const __nv_bfloat16* hl = g_Hlo[cur];
#pragma unroll
        for (int i = 0; i < 8; i++) {
            int c = tid + i * 256;
            int r = c >> 7, kc = c & 127;
            uint32_t off = r * 2048 + (((kc ^ (r & 7)) & 127) << 4);
            cp_async16(smb + HHI_OFF + off, hh + r * Hh + kc * 8);
            cp_async16(smb + HLO_OFF + off, hl + r * Hh + kc * 8);
        }
        cp_commit();
        asm volatile("cp.async.wait_group 0;" ::: "memory");
        __syncthreads();

        float a0e[4] = {}, a0o[4] = {}, a1e[4] = {}, a1o[4] = {};
#pragma unroll
        for (int t = 0; t < 3; t++) {
            const uint32_t aS = smb + ((t == 1) ? HLO_OFF : HHI_OFF) + arow * 2048;
            const uint32_t bS = smb + ((t == 2) ? WLO_OFF : WHI_OFF) + brow * 2048;
#pragma unroll
            for (int jj = 0; jj < 8; jj++) {
                int cj = (wid * 8 + jj) * 2;
                uint32_t af[4], bf[4];
                ldsm4(af, aS + ((((cj + ach) ^ (arow & 7)) & 127) << 4));
                ldsm4(bf, bS + ((((cj + bch) ^ (brow & 7)) & 127) << 4));
                if (jj & 1) {
                    mma16816(a0o, af, bf[0], bf[1]);
                    mma16816(a1o, af, bf[2], bf[3]);
                } else {
                    mma16816(a0e, af, bf[0], bf[1]);
                    mma16816(a1e, af, bf[2], bf[3]);
                }
            }
        }
        float* rw = red + wid * 288;
        rw[crow * 18 + ccol]           = a0e[0] + a0o[0];
        rw[crow * 18 + ccol + 1]       = a0e[1] + a0o[1];
        rw[(crow + 8) * 18 + ccol]     = a0e[2] + a0o[2];
        rw[(crow + 8) * 18 + ccol + 1] = a0e[3] + a0o[3];
        rw[crow * 18 + 8 + ccol]           = a1e[0] + a1o[0];
        rw[crow * 18 + 8 + ccol + 1]       = a1e[1] + a1o[1];
        rw[(crow + 8) * 18 + 8 + ccol]     = a1e[2] + a1o[2];
        rw[(crow + 8) * 18 + 8 + ccol + 1] = a1e[3] + a1o[3];
        __syncthreads();

        float v = gval;
#pragma unroll
        for (int w = 0; w < 8; w++) v += red[w * 288 + rb * 18 + rn];
        float hv = tanhf(v);
        __nv_bfloat16 hi = __float2bfloat16(hv);
        __nv_bfloat16 lo = __float2bfloat16(hv - __bfloat162float(hi));
        const int nxt = cur ^ 1;
        const int idx = rb * Hh + n0 + rn;
        g_Hhi[nxt][idx] = hi;
        g_Hlo[nxt][idx] = lo;
        g_A8[((size_t)s * Bb + rb) * Hh + n0 + rn] = to_e4m3(hv * ASCALE);  // m = s*16+b
        if (s == Ss - 1) out[(size_t)Bb * Ss * Vv + idx] = hv;              // hT direct
        __syncthreads();
        if (tid == 0) {
            __threadfence();
            ((volatile unsigned*)g_flags)[blockIdx.x * 32] = base + (unsigned)(s + 1);
        }
    }
}

// ---- dec role ----
__device__ void dec_load_stage(uint32_t sb, int stg, int ki, int bm, int bn, int tid) {
    uint32_t base = sb + stg * DEC_STG;
    const uint8_t* gA = g_A8 + (size_t)bm * 1024 + ki * 128;
    const uint8_t* gB = g_B8 + (size_t)bn * 1024 + ki * 128;
#pragma unroll
    for (int i = 0; i < 4; i++) {
        int c = tid + i * 256;
        int r = c >> 3, cc = c & 7;
        cp_async16(base + r * 128 + (((cc ^ (r & 7)) & 7) << 4),
                   gA + (size_t)r * 1024 + cc * 16);
    }
#pragma unroll
    for (int i = 0; i < 8; i++) {
        int c = tid + i * 256;
        int r = c >> 3, cc = c & 7;
        cp_async16(base + DEC_ASZ + r * 128 + (((cc ^ (r & 7)) & 7) << 4),
                   gB + (size_t)r * 1024 + cc * 16);
    }
}

__device__ void dec_tile(uint32_t sb, int bm, int bn, const float* __restrict__ b_dec,
                         const int* __restrict__ stop, float* __restrict__ out) {
    const int tid = threadIdx.x;
    const int wid = tid >> 5;
    const int lane = tid & 31;
    const int wm = wid & 1;
    const int wn = wid >> 1;

    float acc[4][8][4];
#pragma unroll
    for (int i = 0; i < 4; i++)
#pragma unroll
        for (int j = 0; j < 8; j++)
#pragma unroll
            for (int q = 0; q < 4; q++) acc[i][j][q] = 0.f;

    const int arow = wm * 64 + (lane & 15);
    const int ach = lane >> 4;
    const int as = arow & 7;
    const int brow = wn * 64 + ((lane >> 4) << 3) + (lane & 7);
    const int bch = (lane >> 3) & 1;
    const int bs = brow & 7;

    dec_load_stage(sb, 0, 0, bm, bn, tid); cp_commit();
    dec_load_stage(sb, 1, 1, bm, bn, tid); cp_commit();

    for (int ki = 0; ki < 8; ki++) {
        const int cur = ki % 3;
        if (ki + 2 < 8) {
            dec_load_stage(sb, (ki + 2) % 3, ki + 2, bm, bn, tid); cp_commit();
            asm volatile("cp.async.wait_group 2;" ::: "memory");
        } else if (ki + 1 < 8) {
            asm volatile("cp.async.wait_group 1;" ::: "memory");
        } else {
            asm volatile("cp.async.wait_group 0;" ::: "memory");
        }
        __syncthreads();

        const uint32_t aB = sb + cur * DEC_STG + arow * 128;
        const uint32_t bB = sb + cur * DEC_STG + DEC_ASZ + brow * 128;
#pragma unroll
        for (int kt = 0; kt < 4; kt++) {
            uint32_t af[4][4], bf[4][4];
            const uint32_t acs = ((uint32_t)((kt * 2 + ach) ^ as)) << 4;
            const uint32_t bcs = ((uint32_t)((kt * 2 + bch) ^ bs)) << 4;
#pragma unroll
            for (int mi = 0; mi < 4; mi++) ldsm4(af[mi], aB + mi * 2048 + acs);
#pragma unroll
            for (int ni2 = 0; ni2 < 4; ni2++) ldsm4(bf[ni2], bB + ni2 * 2048 + bcs);
#pragma unroll
            for (int mi = 0; mi < 4; mi++)
#pragma unroll
                for (int ni = 0; ni < 8; ni++)
                    mma16832f8(acc[mi][ni], af[mi], bf[ni >> 1][(ni & 1) * 2],
                               bf[ni >> 1][(ni & 1) * 2 + 1]);
        }
        __syncthreads();
    }

    // epilogue: m = s*16+b  ->  out row = b*128+s (s constant within a 16-row group)
    const float SC = 1.0f / (ASCALE * BSCALE);
    int orow0[4];
    float msk0[4], msk1[4];
#pragma unroll
    for (int mi = 0; mi < 4; mi++) {
        int m0 = bm + wm * 64 + mi * 16 + (lane >> 2);
        orow0[mi] = (m0 & 15) * 128 + (m0 >> 4);
        msk0[mi] = (stop[orow0[mi]] == 0) ? 1.0f : 0.0f;
        msk1[mi] = (stop[orow0[mi] + 1024] == 0) ? 1.0f : 0.0f;   // +8 batches
    }
#pragma unroll
    for (int ni = 0; ni < 8; ni++) {
        int n0 = bn + wn * 64 + ni * 8 + (lane & 3) * 2;
        float2 bd = *(const float2*)(b_dec + n0);
        float2 tp = *(const float2*)(g_topic + n0);
#pragma unroll
        for (int mi = 0; mi < 4; mi++) {
            float2 o0, o1;
            o0.x = acc[mi][ni][0] * SC + bd.x + tp.x * msk0[mi];
            o0.y = acc[mi][ni][1] * SC + bd.y + tp.y * msk0[mi];
            o1.x = acc[mi][ni][2] * SC + bd.x + tp.x * msk1[mi];
            o1.y = acc[mi][ni][3] * SC + bd.y + tp.y * msk1[mi];
            *(float2*)(out + (size_t)orow0[mi] * Vv + n0) = o0;
            *(float2*)(out + (size_t)(orow0[mi] + 1024) * Vv + n0) = o1;
        }
    }
}

__device__ void dec_role(char* dsm, const float* __restrict__ b_dec,
                         const int* __restrict__ stop, float* __restrict__ out,
                         unsigned base) {
    __shared__ int s_t;
    const int tid = threadIdx.x;
    uint32_t sb = (smem_u32(dsm) + 1023) & ~1023u;
    for (;;) {
        if (tid == 0) s_t = (int)atomicAdd(&g_tile, 1u);
        __syncthreads();
        int t = s_t;
        if (t >= N_TILES) return;
        int x = t / 125;            // s-range group (needs rnn steps 0..8x+7 complete)
        int y = t - x * 125;
        unsigned need = base + (unsigned)(x * 8 + 8);
        // poll ALL 64 producer flags directly (same proven pattern as rnn<->rnn sync)
        if (tid < RNN_NB) {
            while (((volatile unsigned*)g_flags)[tid * 32] < need) __nanosleep(1024);
            __threadfence();
        }
        __syncthreads();
        dec_tile(sb, x * 128, y * 256, b_dec, stop, out);
        __syncthreads();            // protect smem reuse across tiles
    }
}

__global__ __launch_bounds__(256, 1) void fused_kernel(const float* __restrict__ W_hh,
                                                       const float* __restrict__ b_dec,
                                                       const int* __restrict__ stop,
                                                       float* __restrict__ out) {
    extern __shared__ __align__(16) char fsm[];
    const unsigned base = g_epoch << 8;
    if (blockIdx.x < RNN_NB) rnn_role(fsm, W_hh, out, base);
    else                     dec_role(fsm, b_dec, stop, out, base);
}

// ------------------------- launch -------------------------
extern "C" void kernel_launch(void* const* d_in, const int* in_sizes, int n_in,
                              void* d_out, int out_size) {
    const int*   input_ids = (const int*)d_in[0];
    const float* hidden    = (const float*)d_in[1];
    const int*   stop      = (const int*)d_in[2];
    const float* W_emb     = (const float*)d_in[3];
    const float* W_ih      = (const float*)d_in[4];
    const float* b_ih      = (const float*)d_in[5];
    const float* W_hh      = (const float*)d_in[6];
    const float* b_hh      = (const float*)d_in[7];
    const float* W_dec     = (const float*)d_in[8];
    const float* b_dec     = (const float*)d_in[9];
    const float* beta      = (const float*)d_in[10];
    const float* theta     = (const float*)d_in[11];
    float* out = (float*)d_out;

    cudaFuncSetAttribute(fused_kernel, cudaFuncAttributeMaxDynamicSharedMemorySize,
                         FUSED_SMEM);

    static cudaStream_t sA = nullptr, sB = nullptr;
    static cudaEvent_t eF = nullptr, eA = nullptr, eB = nullptr;
    if (sA == nullptr) {
        cudaStreamCreateWithFlags(&sA, cudaStreamNonBlocking);
        cudaStreamCreateWithFlags(&sB, cudaStreamNonBlocking);
        cudaEventCreateWithFlags(&eF, cudaEventDisableTiming);
        cudaEventCreateWithFlags(&eA, cudaEventDisableTiming);
        cudaEventCreateWithFlags(&eB, cudaEventDisableTiming);
    }

    // pre-phase fork: convB on sA; topic+init on sB; embed on main
    cudaEventRecord(eF, 0);
    cudaStreamWaitEvent(sA, eF, 0);
    cudaStreamWaitEvent(sB, eF, 0);
    convB_kernel<<<(int)(((size_t)Vv * 1024 / 4) / 256), 256, 0, sA>>>(W_dec);
    topic_kernel<<<(Vv + 255) / 256, 256, 0, sB>>>(beta, theta);
    init_h_kernel<<<(Bb * Hh + 255) / 256, 256, 0, sB>>>(hidden);
    embed_gemm<<<dim3(16, 8), 256>>>(input_ids, W_emb, W_ih, b_ih, b_hh);
    cudaEventRecord(eA, sA);
    cudaEventRecord(eB, sB);
    cudaStreamWaitEvent(0, eA, 0);
    cudaStreamWaitEvent(0, eB, 0);

    // fused rnn + decoder (all 148 CTAs co-resident; writes ALL of out)
    fused_kernel<<<CMB_NB, 256, FUSED_SMEM>>>(W_hh, b_dec, stop, out);
}

// round 13
// speedup vs baseline: 6.0523x; 1.0645x over previous
#include <cuda_runtime.h>
#include <cuda_bf16.h>
#include <cuda_fp8.h>
#include <math.h>
#include <stdint.h>

#define Vv 32000
#define Ee 512
#define Hh 1024
#define Bb 16
#define Ss 128
#define Kk 15

#define ASCALE 128.0f
#define BSCALE 256.0f

// ------------------------- device scratch (no allocs allowed) -------------------------
__device__ float g_G[Ss * Bb * Hh];               // [s][b][h]
__device__ __nv_bfloat16 g_Hhi[2][Bb * Hh];
__device__ __nv_bfloat16 g_Hlo[2][Bb * Hh];
__device__ float g_topic[Vv];
__device__ unsigned g_epoch;                      // bumped each launch (init_h)
__device__ unsigned g_flags[64 * 32];             // per-rnn-CTA flag, 1 per 128B line
__device__ unsigned g_tile;                       // dec tile queue head (reset each launch)
// fp8 decoder operands
__device__ uint8_t g_A8[2048 * 1024];             // [m = s*16+b][k]  (h * 128, e4m3)
__device__ uint8_t g_B8[(size_t)Vv * 1024];       // [v][k]           (W_dec * 256, e4m3)

// ------------------------- PTX helpers -------------------------
__device__ __forceinline__ uint32_t smem_u32(const void* p) {
    uint32_t a;
    asm("{ .reg .u64 t; cvta.to.shared.u64 t, %1; cvt.u32.u64 %0, t; }" : "=r"(a) : "l"(p));
    return a;
}
__device__ __forceinline__ void cp_async16(uint32_t dst, const void* src) {
    asm volatile("cp.async.cg.shared.global [%0], [%1], 16;" :: "r"(dst), "l"(src) : "memory");
}
__device__ __forceinline__ void cp_commit() { asm volatile("cp.async.commit_group;" ::: "memory"); }

__device__ __forceinline__ void ldsm4(uint32_t* r, uint32_t addr) {
    asm volatile("ldmatrix.sync.aligned.m8n8.x4.shared.b16 {%0,%1,%2,%3}, [%4];"
                 : "=r"(r[0]), "=r"(r[1]), "=r"(r[2]), "=r"(r[3]) : "r"(addr));
}
__device__ __forceinline__ void mma16816(float* c, const uint32_t* a, uint32_t b0, uint32_t b1) {
    asm volatile("mma.sync.aligned.m16n8k16.row.col.f32.bf16.bf16.f32 "
                 "{%0,%1,%2,%3}, {%4,%5,%6,%7}, {%8,%9}, {%0,%1,%2,%3};"
                 : "+f"(c[0]), "+f"(c[1]), "+f"(c[2]), "+f"(c[3])
                 : "r"(a[0]), "r"(a[1]), "r"(a[2]), "r"(a[3]), "r"(b0), "r"(b1));
}
__device__ __forceinline__ void mma16832f8(float* c, const uint32_t* a, uint32_t b0, uint32_t b1) {
    asm volatile("mma.sync.aligned.m16n8k32.row.col.f32.e4m3.e4m3.f32 "
                 "{%0,%1,%2,%3}, {%4,%5,%6,%7}, {%8,%9}, {%0,%1,%2,%3};"
                 : "+f"(c[0]), "+f"(c[1]), "+f"(c[2]), "+f"(c[3])
                 : "r"(a[0]), "r"(a[1]), "r"(a[2]), "r"(a[3]), "r"(b0), "r"(b1));
}
__device__ __forceinline__ uint8_t to_e4m3(float x) {
    return (uint8_t)__nv_cvt_float_to_fp8(x, __NV_SATFINITE, __NV_E4M3);
}
// release store / acquire load (gpu scope) for flag protocol
__device__ __forceinline__ void st_release(unsigned* p, unsigned v) {
    asm volatile("st.release.gpu.global.u32 [%0], %1;" :: "l"(p), "r"(v) : "memory");
}
__device__ __forceinline__ unsigned ld_relaxed(const unsigned* p) {
    unsigned v;
    asm volatile("ld.relaxed.gpu.global.u32 %0, [%1];" : "=r"(v) : "l"(p));
    return v;
}
__device__ __forceinline__ unsigned ld_acquire(const unsigned* p) {
    unsigned v;
    asm volatile("ld.acquire.gpu.global.u32 %0, [%1];" : "=r"(v) : "l"(p) : "memory");
    return v;
}

// ------------------------- tiny kernels -------------------------
__global__ void topic_kernel(const float* __restrict__ beta, const float* __restrict__ theta) {
    int v = blockIdx.x * 256 + threadIdx.x;
    if (v < Vv) {
        float s = 0.f;
#pragma unroll
        for (int k = 0; k < Kk; k++) s += theta[k] * beta[k * Vv + v];
        g_topic[v] = s;
    }
}
__global__ void init_h_kernel(const float* __restrict__ hidden) {
    int i = blockIdx.x * 256 + threadIdx.x;
    if (i < Bb * Hh) {
        float x = hidden[i];
        __nv_bfloat16 hi = __float2bfloat16(x);
        g_Hhi[0][i] = hi;
        g_Hlo[0][i] = __float2bfloat16(x - __bfloat162float(hi));
    }
    if (i == 0) { g_epoch = g_epoch + 1; g_tile = 0; }
}
__global__ void convB_kernel(const float* __restrict__ W_dec) {
    size_t i = (size_t)blockIdx.x * 256 + threadIdx.x;   // float4 groups
    float4 v = ((const float4*)W_dec)[i];
    uchar4 o;
    o.x = to_e4m3(v.x * BSCALE);
    o.y = to_e4m3(v.y * BSCALE);
    o.z = to_e4m3(v.z * BSCALE);
    o.w = to_e4m3(v.w * BSCALE);
    ((uchar4*)g_B8)[i] = o;
}

// ------------------------- embedding gather + input projection (HMMA) ----------------
// G[m][n] = W_emb[ids(m)] . W_ih[n] + b_ih[n] + b_hh[n]; 3-term bf16 split.
// CTA tile 128m x 128n; K = 512 in 8 chunks of 64; 8 warps (2m x 4n), warp 64m x 32n.
#define EMB_AHI 0
#define EMB_ALO 16384
#define EMB_BHI 32768
#define EMB_BLO 49152
#define EMB_SMEM 65536

__global__ __launch_bounds__(256, 1) void embed_gemm(const int* __restrict__ ids,
                                                     const float* __restrict__ W_emb,
                                                     const float* __restrict__ W_ih,
                                                     const float* __restrict__ b_ih,
                                                     const float* __restrict__ b_hh) {
    extern __shared__ __align__(16) char esm[];
    __shared__ int rowid[128];
    const int tid = threadIdx.x;
    const int wid = tid >> 5;
    const int lane = tid & 31;
    const int wm = wid & 1;
    const int wn = wid >> 1;
    const int bm = blockIdx.x * 128;
    const int bn = blockIdx.y * 128;
    if (tid < 128) {
        int m = bm + tid;
        rowid[tid] = ids[(m & 15) * Ss + (m >> 4)];   // input_ids[b][s]
    }
    __syncthreads();

    float acc[4][4][4];
#pragma unroll
    for (int i = 0; i < 4; i++)
#pragma unroll
        for (int j = 0; j < 4; j++)
#pragma unroll
            for (int q = 0; q < 4; q++) acc[i][j][q] = 0.f;

    const int arow = wm * 64 + (lane & 15);
    const int ach = lane >> 4;
    const int as = arow & 7;
    const int brow = wn * 32 + ((lane >> 4) << 3) + (lane & 7);
    const int bch = (lane >> 3) & 1;
    const int bs = brow & 7;
    const uint32_t smb = smem_u32(esm);

    for (int kt = 0; kt < 8; kt++) {
        __syncthreads();
        // load + split-convert chunk: A (gathered) and B, 128 rows x 64 floats each
#pragma unroll
        for (int i = 0; i < 4; i++) {
            int c = tid + i * 256;          // 1024 units of 8 floats
            int r = c >> 3, q = c & 7;
            const float* srcA = W_emb + (size_t)rowid[r] * Ee + kt * 64 + q * 8;
            const float* srcB = W_ih + (size_t)(bn + r) * Ee + kt * 64 + q * 8;
            float4 a0 = *(const float4*)srcA;
            float4 a1 = *(const float4*)(srcA + 4);
            float4 b0 = *(const float4*)srcB;
            float4 b1 = *(const float4*)(srcB + 4);
            float xa[8] = {a0.x, a0.y, a0.z, a0.w, a1.x, a1.y, a1.z, a1.w};
            float xb[8] = {b0.x, b0.y, b0.z, b0.w, b1.x, b1.y, b1.z, b1.w};
            __nv_bfloat16 ahi[8], alo[8], bhi[8], blo[8];
#pragma unroll
            for (int q2 = 0; q2 < 8; q2++) {
                ahi[q2] = __float2bfloat16(xa[q2]);
                alo[q2] = __float2bfloat16(xa[q2] - __bfloat162float(ahi[q2]));
                bhi[q2] = __float2bfloat16(xb[q2]);
                blo[q2] = __float2bfloat16(xb[q2] - __bfloat162float(bhi[q2]));
            }
            uint32_t off = r * 128 + (((q ^ (r & 7)) & 7) << 4);
            *(uint4*)(esm + EMB_AHI + off) = *(uint4*)ahi;
            *(uint4*)(esm + EMB_ALO + off) = *(uint4*)alo;
            *(uint4*)(esm + EMB_BHI + off) = *(uint4*)bhi;
            *(uint4*)(esm + EMB_BLO + off) = *(uint4*)blo;
        }
        __syncthreads();

#pragma unroll
        for (int t = 0; t < 3; t++) {
            const uint32_t aB = smb + ((t == 1) ? EMB_ALO : EMB_AHI) + arow * 128;
            const uint32_t bB = smb + ((t == 2) ? EMB_BLO : EMB_BHI) + brow * 128;
#pragma unroll
            for (int k16 = 0; k16 < 4; k16++) {
                uint32_t af[4][4], bf[2][4];
                const uint32_t acs = ((uint32_t)((k16 * 2 + ach) ^ as)) << 4;
                const uint32_t bcs = ((uint32_t)((k16 * 2 + bch) ^ bs)) << 4;
#pragma unroll
                for (int mi = 0; mi < 4; mi++) ldsm4(af[mi], aB + mi * 2048 + acs);
#pragma unroll
                for (int ni2 = 0; ni2 < 2; ni2++) ldsm4(bf[ni2], bB + ni2 * 2048 + bcs);
#pragma unroll
                for (int mi = 0; mi < 4; mi++)
#pragma unroll
                    for (int ni = 0; ni < 4; ni++)
                        mma16816(acc[mi][ni], af[mi], bf[ni >> 1][(ni & 1) * 2],
                                 bf[ni >> 1][(ni & 1) * 2 + 1]);
            }
        }
    }

    // epilogue: + b_ih + b_hh, fp32 store
#pragma unroll
    for (int ni = 0; ni < 4; ni++) {
        int n0 = bn + wn * 32 + ni * 8 + (lane & 3) * 2;
        float2 bi = *(const float2*)(b_ih + n0);
        float2 bh = *(const float2*)(b_hh + n0);
        float2 bb = make_float2(bi.x + bh.x, bi.y + bh.y);
#pragma unroll
        for (int mi = 0; mi < 4; mi++) {
            int m0 = bm + wm * 64 + mi * 16 + (lane >> 2);
            float2 o0 = make_float2(acc[mi][ni][0] + bb.x, acc[mi][ni][1] + bb.y);
            float2 o1 = make_float2(acc[mi][ni][2] + bb.x, acc[mi][ni][3] + bb.y);
            *(float2*)(g_G + (size_t)m0 * Hh + n0) = o0;
            *(float2*)(g_G + (size_t)(m0 + 8) * Hh + n0) = o1;
        }
    }
}

// ------------------------- fused persistent kernel: rnn + dec -------------------------
#define RNN_NB 64
#define CMB_NB 148
#define N_TILES (16 * 125)
#define WHI_OFF 0
#define WLO_OFF 32768
#define HHI_OFF 65536
#define HLO_OFF 98304
#define RNN_RED_OFF 131072
#define DEC_ASZ 16384
#define DEC_BSZ 32768
#define DEC_STG (DEC_ASZ + DEC_BSZ)
#define FUSED_SMEM (3 * DEC_STG + 1024)           // 148480 >= rnn's 140288

// ---- rnn role ----
__device__ void rnn_role(char* rsm, const float* __restrict__ W_hh,
                         float* __restrict__ out, unsigned base) {
    float* red = (float*)(rsm + RNN_RED_OFF);
    const int tid = threadIdx.x;
    const int wid = tid >> 5;
    const int lane = tid & 31;
    const int n0 = blockIdx.x * 16;

#pragma unroll
    for (int i = 0; i < 8; i++) {
        int c = tid + i * 256;
        int r = c >> 7, kc = c & 127;
        const float* src = W_hh + (size_t)(n0 + r) * Hh + kc * 8;
        float4 v0 = *(const float4*)src;
        float4 v1 = *(const float4*)(src + 4);
        float x[8] = {v0.x, v0.y, v0.z, v0.w, v1.x, v1.y, v1.z, v1.w};
        __nv_bfloat16 hi[8], lo[8];
#pragma unroll
        for (int q = 0; q < 8; q++) {
            hi[q] = __float2bfloat16(x[q]);
            lo[q] = __float2bfloat16(x[q] - __bfloat162float(hi[q]));
        }
        uint32_t off = r * 2048 + (((kc ^ (r & 7)) & 127) << 4);
        *(uint4*)(rsm + WHI_OFF + off) = *(uint4*)hi;
        *(uint4*)(rsm + WLO_OFF + off) = *(uint4*)lo;
    }

    const int arow = lane & 15;
    const int ach = lane >> 4;
    const int brow = ((lane >> 4) << 3) + (lane & 7);
    const int bch = (lane >> 3) & 1;
    const int crow = lane >> 2, ccol = (lane & 3) * 2;
    const int rb = tid >> 4, rn = tid & 15;
    const uint32_t smb = smem_u32(rsm);

    for (int s = 0; s < Ss; s++) {
        const int cur = s & 1;
        float gval = __ldcg(&g_G[(size_t)s * (Bb * Hh) + rb * Hh + n0 + rn]);

        if (s > 0) {
            if (tid < RNN_NB) {
                const unsigned* fp = &g_flags[tid * 32];
                unsigned need = base + (unsigned)s;
                while (ld_relaxed(fp) < need) { }
                (void)ld_acquire(fp);
            }
            __syncthreads();
        }

        // stage h: hhi group first, hlo group second
        const __nv_bfloat16* hh = g_Hhi[cur];
        const __nv_bfloat16* hl = g_Hlo[cur];
#pragma unroll
        for (int i = 0; i < 8; i++) {
            int c = tid + i * 256;
            int r = c >> 7, kc = c & 127;
            uint32_t off = r * 2048 + (((kc ^ (r & 7)) & 127) << 4);
            cp_async16(smb + HHI_OFF + off, hh + r * Hh + kc * 8);
        }
        cp_commit();
#pragma unroll
        for (int i = 0; i < 8; i++) {
            int c = tid + i * 256;
            int r = c >> 7, kc = c & 127;
            uint32_t off = r * 2048 + (((kc ^ (r & 7)) & 127) << 4);
            cp_async16(smb + HLO_OFF + off, hl + r * Hh + kc * 8);
        }
        cp_commit();
        asm volatile("cp.async.wait_group 1;" ::: "memory");   // hhi ready
        __syncthreads();

        float a0e[4] = {}, a0o[4] = {}, a1e[4] = {}, a1o[4] = {};
        // passes on hhi: t0 (Whi), t2 (Wlo)
#pragma unroll
        for (int t = 0; t < 2; t++) {
            const uint32_t aS = smb + HHI_OFF + arow * 2048;
            const uint32_t bS = smb + ((t == 1) ? WLO_OFF : WHI_OFF) + brow * 2048;
#pragma unroll
            for (int jj = 0; jj < 8; jj++) {
                int cj = (wid * 8 + jj) * 2;
                uint32_t af[4], bf[4];
                ldsm4(af, aS + ((((cj + ach) ^ (arow & 7)) & 127) << 4));
                ldsm4(bf, bS + ((((cj + bch) ^ (brow & 7)) & 127) << 4));
                if (jj & 1) {
                    mma16816(a0o, af, bf[0], bf[1]);
                    mma16816(a1o, af, bf[2], bf[3]);
                } else {
                    mma16816(a0e, af, bf[0], bf[1]);
                    mma16816(a1e, af, bf[2], bf[3]);
                }
            }
        }
        asm volatile("cp.async.wait_group 0;" ::: "memory");   // hlo ready
        __syncthreads();
        // pass on hlo: t1 (Whi)
        {
            const uint32_t aS = smb + HLO_OFF + arow * 2048;
            const uint32_t bS = smb + WHI_OFF + brow * 2048;
#pragma unroll
            for (int jj = 0; jj < 8; jj++) {
                int cj = (wid * 8 + jj) * 2;
                uint32_t af[4], bf[4];
                ldsm4(af, aS + ((((cj + ach) ^ (arow & 7)) & 127) << 4));
                ldsm4(bf, bS + ((((cj + bch) ^ (brow & 7)) & 127) << 4));
                if (jj & 1) {
                    mma16816(a0o, af, bf[0], bf[1]);
                    mma16816(a1o, af, bf[2], bf[3]);
                } else {
                    mma16816(a0e, af, bf[0], bf[1]);
                    mma16816(a1e, af, bf[2], bf[3]);
                }
            }
        }
        float* rw = red + wid * 288;
        rw[crow * 18 + ccol]           = a0e[0] + a0o[0];
        rw[crow * 18 + ccol + 1]       = a0e[1] + a0o[1];
        rw[(crow + 8) * 18 + ccol]     = a0e[2] + a0o[2];
        rw[(crow + 8) * 18 + ccol + 1] = a0e[3] + a0o[3];
        rw[crow * 18 + 8 + ccol]           = a1e[0] + a1o[0];
        rw[crow * 18 + 8 + ccol + 1]       = a1e[1] + a1o[1];
        rw[(crow + 8) * 18 + 8 + ccol]     = a1e[2] + a1o[2];
        rw[(crow + 8) * 18 + 8 + ccol + 1] = a1e[3] + a1o[3];
        __syncthreads();

        float v = gval;
#pragma unroll
        for (int w = 0; w < 8; w++) v += red[w * 288 + rb * 18 + rn];
        float hv = tanhf(v);
        __nv_bfloat16 hi = __float2bfloat16(hv);
        __nv_bfloat16 lo = __float2bfloat16(hv - __bfloat162float(hi));
        const int nxt = cur ^ 1;
        const int idx = rb * Hh + n0 + rn;
        g_Hhi[nxt][idx] = hi;
        g_Hlo[nxt][idx] = lo;
        g_A8[((size_t)s * Bb + rb) * Hh + n0 + rn] = to_e4m3(hv * ASCALE);  // m = s*16+b
        if (s == Ss - 1) out[(size_t)Bb * Ss * Vv + idx] = hv;              // hT direct
        __syncthreads();
        if (tid == 0)
            st_release(&g_flags[blockIdx.x * 32], base + (unsigned)(s + 1));
    }
}

// ---- dec role ----
__device__ void dec_load_stage(uint32_t sb, int stg, int ki, int bm, int bn, int tid) {
    uint32_t base = sb + stg * DEC_STG;
    const uint8_t* gA = g_A8 + (size_t)bm * 1024 + ki * 128;
    const uint8_t* gB = g_B8 + (size_t)bn * 1024 + ki * 128;
#pragma unroll
    for (int i = 0; i < 4; i++) {
        int c = tid + i * 256;
        int r = c >> 3, cc = c & 7;
        cp_async16(base + r * 128 + (((cc ^ (r & 7)) & 7) << 4),
                   gA + (size_t)r * 1024 + cc * 16);
    }
#pragma unroll
    for (int i = 0; i < 8; i++) {
        int c = tid + i * 256;
        int r = c >> 3, cc = c & 7;
        cp_async16(base + DEC_ASZ + r * 128 + (((cc ^ (r & 7)) & 7) << 4),
                   gB + (size_t)r * 1024 + cc * 16);
    }
}

__device__ void dec_tile(uint32_t sb, int bm, int bn, const float* __restrict__ b_dec,
                         const int* __restrict__ stop, float* __restrict__ out) {
    const int tid = threadIdx.x;
    const int wid = tid >> 5;
    const int lane = tid & 31;
    const int wm = wid & 1;
    const int wn = wid >> 1;

    float acc[4][8][4];
#pragma unroll
    for (int i = 0; i < 4; i++)
#pragma unroll
        for (int j = 0; j < 8; j++)
#pragma unroll
            for (int q = 0; q < 4; q++) acc[i][j][q] = 0.f;

    const int arow = wm * 64 + (lane & 15);
    const int ach = lane >> 4;
    const int as = arow & 7;
    const int brow = wn * 64 + ((lane >> 4) << 3) + (lane & 7);
    const int bch = (lane >> 3) & 1;
    const int bs = brow & 7;

    dec_load_stage(sb, 0, 0, bm, bn, tid); cp_commit();
    dec_load_stage(sb, 1, 1, bm, bn, tid); cp_commit();

    for (int ki = 0; ki < 8; ki++) {
        const int cur = ki % 3;
        if (ki + 2 < 8) {
            dec_load_stage(sb, (ki + 2) % 3, ki + 2, bm, bn, tid); cp_commit();
            asm volatile("cp.async.wait_group 2;" ::: "memory");
        } else if (ki + 1 < 8) {
            asm volatile("cp.async.wait_group 1;" ::: "memory");
        } else {
            asm volatile("cp.async.wait_group 0;" ::: "memory");
        }
        __syncthreads();

        const uint32_t aB = sb + cur * DEC_STG + arow * 128;
        const uint32_t bB = sb + cur * DEC_STG + DEC_ASZ + brow * 128;
#pragma unroll
        for (int kt = 0; kt < 4; kt++) {
            uint32_t af[4][4], bf[4][4];
            const uint32_t acs = ((uint32_t)((kt * 2 + ach) ^ as)) << 4;
            const uint32_t bcs = ((uint32_t)((kt * 2 + bch) ^ bs)) << 4;
#pragma unroll
            for (int mi = 0; mi < 4; mi++) ldsm4(af[mi], aB + mi * 2048 + acs);
#pragma unroll
            for (int ni2 = 0; ni2 < 4; ni2++) ldsm4(bf[ni2], bB + ni2 * 2048 + bcs);
#pragma unroll
            for (int mi = 0; mi < 4; mi++)
#pragma unroll
                for (int ni = 0; ni < 8; ni++)
                    mma16832f8(acc[mi][ni], af[mi], bf[ni >> 1][(ni & 1) * 2],
                               bf[ni >> 1][(ni & 1) * 2 + 1]);
        }
        __syncthreads();
    }

    // epilogue: m = s*16+b  ->  out row = b*128+s
    const float SC = 1.0f / (ASCALE * BSCALE);
    int orow0[4];
    float msk0[4], msk1[4];
#pragma unroll
    for (int mi = 0; mi < 4; mi++) {
        int m0 = bm + wm * 64 + mi * 16 + (lane >> 2);
        orow0[mi] = (m0 & 15) * 128 + (m0 >> 4);
        msk0[mi] = (stop[orow0[mi]] == 0) ? 1.0f : 0.0f;
        msk1[mi] = (stop[orow0[mi] + 1024] == 0) ? 1.0f : 0.0f;   // +8 batches
    }
#pragma unroll
    for (int ni = 0; ni < 8; ni++) {
        int n0 = bn + wn * 64 + ni * 8 + (lane & 3) * 2;
        float2 bd = *(const float2*)(b_dec + n0);
        float2 tp = *(const float2*)(g_topic + n0);
#pragma unroll
        for (int mi = 0; mi < 4; mi++) {
            float2 o0, o1;
            o0.x = acc[mi][ni][0] * SC + bd.x + tp.x * msk0[mi];
            o0.y = acc[mi][ni][1] * SC + bd.y + tp.y * msk0[mi];
            o1.x = acc[mi][ni][2] * SC + bd.x + tp.x * msk1[mi];
            o1.y = acc[mi][ni][3] * SC + bd.y + tp.y * msk1[mi];
            *(float2*)(out + (size_t)orow0[mi] * Vv + n0) = o0;
            *(float2*)(out + (size_t)(orow0[mi] + 1024) * Vv + n0) = o1;
        }
    }
}

__device__ void dec_role(char* dsm, const float* __restrict__ b_dec,
                         const int* __restrict__ stop, float* __restrict__ out,
                         unsigned base) {
    __shared__ int s_t;
    const int tid = threadIdx.x;
    uint32_t sb = (smem_u32(dsm) + 1023) & ~1023u;
    for (;;) {
        if (tid == 0) s_t = (int)atomicAdd(&g_tile, 1u);
        __syncthreads();
        int t = s_t;
        if (t >= N_TILES) return;
        int x = t / 125;            // s-range group (needs rnn steps 0..8x+7 complete)
        int y = t - x * 125;
        unsigned need = base + (unsigned)(x * 8 + 8);
        if (tid < RNN_NB) {
            const unsigned* fp = &g_flags[tid * 32];
            while (ld_relaxed(fp) < need) __nanosleep(1024);
            (void)ld_acquire(fp);
        }
        __syncthreads();
        dec_tile(sb, x * 128, y * 256, b_dec, stop, out);
        __syncthreads();            // protect smem reuse across tiles
    }
}

__global__ __launch_bounds__(256, 1) void fused_kernel(const float* __restrict__ W_hh,
                                                       const float* __restrict__ b_dec,
                                                       const int* __restrict__ stop,
                                                       float* __restrict__ out) {
    extern __shared__ __align__(16) char fsm[];
    const unsigned base = g_epoch << 8;
    if (blockIdx.x < RNN_NB) rnn_role(fsm, W_hh, out, base);
    else                     dec_role(fsm, b_dec, stop, out, base);
}

// ------------------------- launch -------------------------
extern "C" void kernel_launch(void* const* d_in, const int* in_sizes, int n_in,
                              void* d_out, int out_size) {
    const int*   input_ids = (const int*)d_in[0];
    const float* hidden    = (const float*)d_in[1];
    const int*   stop      = (const int*)d_in[2];
    const float* W_emb     = (const float*)d_in[3];
    const float* W_ih      = (const float*)d_in[4];
    const float* b_ih      = (const float*)d_in[5];
    const float* W_hh      = (const float*)d_in[6];
    const float* b_hh      = (const float*)d_in[7];
    const float* W_dec     = (const float*)d_in[8];
    const float* b_dec     = (const float*)d_in[9];
    const float* beta      = (const float*)d_in[10];
    const float* theta     = (const float*)d_in[11];
    float* out = (float*)d_out;

    cudaFuncSetAttribute(fused_kernel, cudaFuncAttributeMaxDynamicSharedMemorySize,
                         FUSED_SMEM);
    cudaFuncSetAttribute(embed_gemm, cudaFuncAttributeMaxDynamicSharedMemorySize,
                         EMB_SMEM);

    static cudaStream_t sA = nullptr, sB = nullptr;
    static cudaEvent_t eF = nullptr, eA = nullptr, eB = nullptr;
    if (sA == nullptr) {
        cudaStreamCreateWithFlags(&sA, cudaStreamNonBlocking);
        cudaStreamCreateWithFlags(&sB, cudaStreamNonBlocking);
        cudaEventCreateWithFlags(&eF, cudaEventDisableTiming);
        cudaEventCreateWithFlags(&eA, cudaEventDisableTiming);
        cudaEventCreateWithFlags(&eB, cudaEventDisableTiming);
    }

    // pre-phase fork: convB on sA; topic+init on sB; embed (HMMA) on main
    cudaEventRecord(eF, 0);
    cudaStreamWaitEvent(sA, eF, 0);
    cudaStreamWaitEvent(sB, eF, 0);
    convB_kernel<<<(int)(((size_t)Vv * 1024 / 4) / 256), 256, 0, sA>>>(W_dec);
    topic_kernel<<<(Vv + 255) / 256, 256, 0, sB>>>(beta, theta);
    init_h_kernel<<<(Bb * Hh + 255) / 256, 256, 0, sB>>>(hidden);
    embed_gemm<<<dim3(16, 8), 256, EMB_SMEM>>>(input_ids, W_emb, W_ih, b_ih, b_hh);
    cudaEventRecord(eA, sA);
    cudaEventRecord(eB, sB);
    cudaStreamWaitEvent(0, eA, 0);
    cudaStreamWaitEvent(0, eB, 0);

    // fused rnn + decoder (all 148 CTAs co-resident; writes ALL of out)
    fused_kernel<<<CMB_NB, 256, FUSED_SMEM>>>(W_hh, b_dec, stop, out);
}

// round 14
// speedup vs baseline: 7.1628x; 1.1835x over previous
#include <cuda_runtime.h>
#include <cuda_bf16.h>
#include <cuda_fp8.h>
#include <math.h>
#include <stdint.h>

#define Vv 32000
#define Ee 512
#define Hh 1024
#define Bb 16
#define Ss 128
#define Kk 15

#define ASCALE 128.0f
#define BSCALE 256.0f

// ------------------------- device scratch (no allocs allowed) -------------------------
__device__ float g_G[Ss * Bb * Hh];               // [s][b][h]
__device__ __nv_bfloat16 g_Hhi[2][Bb * Hh];
__device__ __nv_bfloat16 g_Hlo[2][Bb * Hh];
__device__ float g_topic[Vv];
__device__ unsigned g_epoch;                      // bumped each launch (init_h)
__device__ unsigned g_flags[64 * 32];             // per-rnn-CTA flag, 1 per 128B line
__device__ unsigned g_tile;                       // dec tile queue head (reset each launch)
// fp8 decoder operands
__device__ uint8_t g_A8[2048 * 1024];             // [m = s*16+b][k]  (h * 128, e4m3)
__device__ uint8_t g_B8[(size_t)Vv * 1024];       // [v][k]           (W_dec * 256, e4m3)

// ------------------------- PTX helpers -------------------------
__device__ __forceinline__ uint32_t smem_u32(const void* p) {
    uint32_t a;
    asm("{ .reg .u64 t; cvta.to.shared.u64 t, %1; cvt.u32.u64 %0, t; }" : "=r"(a) : "l"(p));
    return a;
}
__device__ __forceinline__ void cp_async16(uint32_t dst, const void* src) {
    asm volatile("cp.async.cg.shared.global [%0], [%1], 16;" :: "r"(dst), "l"(src) : "memory");
}
__device__ __forceinline__ void cp_commit() { asm volatile("cp.async.commit_group;" ::: "memory"); }

__device__ __forceinline__ void ldsm4(uint32_t* r, uint32_t addr) {
    asm volatile("ldmatrix.sync.aligned.m8n8.x4.shared.b16 {%0,%1,%2,%3}, [%4];"
                 : "=r"(r[0]), "=r"(r[1]), "=r"(r[2]), "=r"(r[3]) : "r"(addr));
}
__device__ __forceinline__ void mma16816(float* c, const uint32_t* a, uint32_t b0, uint32_t b1) {
    asm volatile("mma.sync.aligned.m16n8k16.row.col.f32.bf16.bf16.f32 "
                 "{%0,%1,%2,%3}, {%4,%5,%6,%7}, {%8,%9}, {%0,%1,%2,%3};"
                 : "+f"(c[0]), "+f"(c[1]), "+f"(c[2]), "+f"(c[3])
                 : "r"(a[0]), "r"(a[1]), "r"(a[2]), "r"(a[3]), "r"(b0), "r"(b1));
}
__device__ __forceinline__ void mma16832f8(float* c, const uint32_t* a, uint32_t b0, uint32_t b1) {
    asm volatile("mma.sync.aligned.m16n8k32.row.col.f32.e4m3.e4m3.f32 "
                 "{%0,%1,%2,%3}, {%4,%5,%6,%7}, {%8,%9}, {%0,%1,%2,%3};"
                 : "+f"(c[0]), "+f"(c[1]), "+f"(c[2]), "+f"(c[3])
                 : "r"(a[0]), "r"(a[1]), "r"(a[2]), "r"(a[3]), "r"(b0), "r"(b1));
}
__device__ __forceinline__ uint8_t to_e4m3(float x) {
    return (uint8_t)__nv_cvt_float_to_fp8(x, __NV_SATFINITE, __NV_E4M3);
}
__device__ __forceinline__ void st_release(unsigned* p, unsigned v) {
    asm volatile("st.release.gpu.global.u32 [%0], %1;" :: "l"(p), "r"(v) : "memory");
}
__device__ __forceinline__ unsigned ld_relaxed(const unsigned* p) {
    unsigned v;
    asm volatile("ld.relaxed.gpu.global.u32 %0, [%1];" : "=r"(v) : "l"(p));
    return v;
}
__device__ __forceinline__ unsigned ld_acquire(const unsigned* p) {
    unsigned v;
    asm volatile("ld.acquire.gpu.global.u32 %0, [%1];" : "=r"(v) : "l"(p) : "memory");
    return v;
}

// ------------------------- tiny kernels -------------------------
__global__ void topic_kernel(const float* __restrict__ beta, const float* __restrict__ theta) {
    int v = blockIdx.x * 256 + threadIdx.x;
    if (v < Vv) {
        float s = 0.f;
#pragma unroll
        for (int k = 0; k < Kk; k++) s += theta[k] * beta[k * Vv + v];
        g_topic[v] = s;
    }
}
__global__ void init_h_kernel(const float* __restrict__ hidden) {
    int i = blockIdx.x * 256 + threadIdx.x;
    if (i < Bb * Hh) {
        float x = hidden[i];
        __nv_bfloat16 hi = __float2bfloat16(x);
        g_Hhi[0][i] = hi;
        g_Hlo[0][i] = __float2bfloat16(x - __bfloat162float(hi));
    }
    if (i == 0) { g_epoch = g_epoch + 1; g_tile = 0; }
}
__global__ void convB_kernel(const float* __restrict__ W_dec) {
    size_t i = (size_t)blockIdx.x * 256 + threadIdx.x;   // float4 groups
    float4 v = ((const float4*)W_dec)[i];
    uchar4 o;
    o.x = to_e4m3(v.x * BSCALE);
    o.y = to_e4m3(v.y * BSCALE);
    o.z = to_e4m3(v.z * BSCALE);
    o.w = to_e4m3(v.w * BSCALE);
    ((uchar4*)g_B8)[i] = o;
}

// ------------------------- embedding gather + input projection (HMMA) ----------------
#define EMB_AHI 0
#define EMB_ALO 16384
#define EMB_BHI 32768
#define EMB_BLO 49152
#define EMB_SMEM 65536

__global__ __launch_bounds__(256, 1) void embed_gemm(const int* __restrict__ ids,
                                                     const float* __restrict__ W_emb,
                                                     const float* __restrict__ W_ih,
                                                     const float* __restrict__ b_ih,
                                                     const float* __restrict__ b_hh) {
    extern __shared__ __align__(16) char esm[];
    __shared__ int rowid[128];
    const int tid = threadIdx.x;
    const int wid = tid >> 5;
    const int lane = tid & 31;
    const int wm = wid & 1;
    const int wn = wid >> 1;
    const int bm = blockIdx.x * 128;
    const int bn = blockIdx.y * 128;
    if (tid < 128) {
        int m = bm + tid;
        rowid[tid] = ids[(m & 15) * Ss + (m >> 4)];
    }
    __syncthreads();

    float acc[4][4][4];
#pragma unroll
    for (int i = 0; i < 4; i++)
#pragma unroll
        for (int j = 0; j < 4; j++)
#pragma unroll
            for (int q = 0; q < 4; q++) acc[i][j][q] = 0.f;

    const int arow = wm * 64 + (lane & 15);
    const int ach = lane >> 4;
    const int as = arow & 7;
    const int brow = wn * 32 + ((lane >> 4) << 3) + (lane & 7);
    const int bch = (lane >> 3) & 1;
    const int bs = brow & 7;
    const uint32_t smb = smem_u32(esm);

    for (int kt = 0; kt < 8; kt++) {
        __syncthreads();
#pragma unroll
        for (int i = 0; i < 4; i++) {
            int c = tid + i * 256;
            int r = c >> 3, q = c & 7;
            const float* srcA = W_emb + (size_t)rowid[r] * Ee + kt * 64 + q * 8;
            const float* srcB = W_ih + (size_t)(bn + r) * Ee + kt * 64 + q * 8;
            float4 a0 = *(const float4*)srcA;
            float4 a1 = *(const float4*)(srcA + 4);
            float4 b0 = *(const float4*)srcB;
            float4 b1 = *(const float4*)(srcB + 4);
            float xa[8] = {a0.x, a0.y, a0.z, a0.w, a1.x, a1.y, a1.z, a1.w};
            float xb[8] = {b0.x, b0.y, b0.z, b0.w, b1.x, b1.y, b1.z, b1.w};
            __nv_bfloat16 ahi[8], alo[8], bhi[8], blo[8];
#pragma unroll
            for (int q2 = 0; q2 < 8; q2++) {
                ahi[q2] = __float2bfloat16(xa[q2]);
                alo[q2] = __float2bfloat16(xa[q2] - __bfloat162float(ahi[q2]));
                bhi[q2] = __float2bfloat16(xb[q2]);
                blo[q2] = __float2bfloat16(xb[q2] - __bfloat162float(bhi[q2]));
            }
            uint32_t off = r * 128 + (((q ^ (r & 7)) & 7) << 4);
            *(uint4*)(esm + EMB_AHI + off) = *(uint4*)ahi;
            *(uint4*)(esm + EMB_ALO + off) = *(uint4*)alo;
            *(uint4*)(esm + EMB_BHI + off) = *(uint4*)bhi;
            *(uint4*)(esm + EMB_BLO + off) = *(uint4*)blo;
        }
        __syncthreads();

#pragma unroll
        for (int t = 0; t < 3; t++) {
            const uint32_t aB = smb + ((t == 1) ? EMB_ALO : EMB_AHI) + arow * 128;
            const uint32_t bB = smb + ((t == 2) ? EMB_BLO : EMB_BHI) + brow * 128;
#pragma unroll
            for (int k16 = 0; k16 < 4; k16++) {
                uint32_t af[4][4], bf[2][4];
                const uint32_t acs = ((uint32_t)((k16 * 2 + ach) ^ as)) << 4;
                const uint32_t bcs = ((uint32_t)((k16 * 2 + bch) ^ bs)) << 4;
#pragma unroll
                for (int mi = 0; mi < 4; mi++) ldsm4(af[mi], aB + mi * 2048 + acs);
#pragma unroll
                for (int ni2 = 0; ni2 < 2; ni2++) ldsm4(bf[ni2], bB + ni2 * 2048 + bcs);
#pragma unroll
                for (int mi = 0; mi < 4; mi++)
#pragma unroll
                    for (int ni = 0; ni < 4; ni++)
                        mma16816(acc[mi][ni], af[mi], bf[ni >> 1][(ni & 1) * 2],
                                 bf[ni >> 1][(ni & 1) * 2 + 1]);
            }
        }
    }

#pragma unroll
    for (int ni = 0; ni < 4; ni++) {
        int n0 = bn + wn * 32 + ni * 8 + (lane & 3) * 2;
        float2 bi = *(const float2*)(b_ih + n0);
        float2 bh = *(const float2*)(b_hh + n0);
        float2 bb = make_float2(bi.x + bh.x, bi.y + bh.y);
#pragma unroll
        for (int mi = 0; mi < 4; mi++) {
            int m0 = bm + wm * 64 + mi * 16 + (lane >> 2);
            float2 o0 = make_float2(acc[mi][ni][0] + bb.x, acc[mi][ni][1] + bb.y);
            float2 o1 = make_float2(acc[mi][ni][2] + bb.x, acc[mi][ni][3] + bb.y);
            *(float2*)(g_G + (size_t)m0 * Hh + n0) = o0;
            *(float2*)(g_G + (size_t)(m0 + 8) * Hh + n0) = o1;
        }
    }
}

// ------------------------- fused persistent kernel: rnn + dec -------------------------
#define RNN_NB 64
#define CMB_NB 148
#define N_TILES (16 * 125)
#define WHI_OFF 0
#define WLO_OFF 32768
#define HHI_OFF 65536
#define HLO_OFF 98304
#define RNN_RED_OFF 131072
#define DEC_ASZ 16384
#define DEC_BSZ 32768
#define DEC_STG (DEC_ASZ + DEC_BSZ)
#define FUSED_SMEM (3 * DEC_STG + 1024)           // 148480 >= rnn's 140288

// ---- rnn role: per-warp dataflow (warp w consumes k in [128w,128w+128) from CTAs 8w..8w+7)
__device__ void rnn_role(char* rsm, const float* __restrict__ W_hh,
                         float* __restrict__ out, unsigned base) {
    float* red = (float*)(rsm + RNN_RED_OFF);
    const int tid = threadIdx.x;
    const int wid = tid >> 5;
    const int lane = tid & 31;
    const int n0 = blockIdx.x * 16;

    // load W_hh slice (16 rows), fp32 -> (hi, lo) bf16 slabs, XOR-swizzled 16B chunks
#pragma unroll
    for (int i = 0; i < 8; i++) {
        int c = tid + i * 256;
        int r = c >> 7, kc = c & 127;
        const float* src = W_hh + (size_t)(n0 + r) * Hh + kc * 8;
        float4 v0 = *(const float4*)src;
        float4 v1 = *(const float4*)(src + 4);
        float x[8] = {v0.x, v0.y, v0.z, v0.w, v1.x, v1.y, v1.z, v1.w};
        __nv_bfloat16 hi[8], lo[8];
#pragma unroll
        for (int q = 0; q < 8; q++) {
            hi[q] = __float2bfloat16(x[q]);
            lo[q] = __float2bfloat16(x[q] - __bfloat162float(hi[q]));
        }
        uint32_t off = r * 2048 + (((kc ^ (r & 7)) & 127) << 4);
        *(uint4*)(rsm + WHI_OFF + off) = *(uint4*)hi;
        *(uint4*)(rsm + WLO_OFF + off) = *(uint4*)lo;
    }
    __syncthreads();   // W slabs ready before any warp's first MMA

    const int arow = lane & 15;
    const int ach = lane >> 4;
    const int brow = ((lane >> 4) << 3) + (lane & 7);
    const int bch = (lane >> 3) & 1;
    const int crow = lane >> 2, ccol = (lane & 3) * 2;
    const int rb = tid >> 4, rn = tid & 15;
    const uint32_t smb = smem_u32(rsm);
    // this warp's producer flag (one of the 8 group CTAs), polled by lanes 0-7
    const unsigned* wfp = &g_flags[(wid * 8 + (lane & 7)) * 32];

    for (int s = 0; s < Ss; s++) {
        const int cur = s & 1;
        float gval = __ldcg(&g_G[(size_t)s * (Bb * Hh) + rb * Hh + n0 + rn]);

        // per-warp wait: only this warp's 8 producers
        if (s > 0) {
            if (lane < 8) {
                unsigned need = base + (unsigned)s;
                while (ld_relaxed(wfp) < need) { }
                (void)ld_acquire(wfp);
            }
            __syncwarp();
        }

        // per-warp staging of its own h slab: rows 0-15, kc in [16*wid, 16*wid+16)
        const __nv_bfloat16* hh = g_Hhi[cur];
        const __nv_bfloat16* hl = g_Hlo[cur];
#pragma unroll
        for (int l = 0; l < 8; l++) {
            int c = l * 32 + lane;             // 256 chunks
            int r = c >> 4;
            int kc = wid * 16 + (c & 15);
            uint32_t off = r * 2048 + (((kc ^ (r & 7)) & 127) << 4);
            cp_async16(smb + HHI_OFF + off, hh + r * Hh + kc * 8);
            cp_async16(smb + HLO_OFF + off, hl + r * Hh + kc * 8);
        }
        cp_commit();
        asm volatile("cp.async.wait_group 0;" ::: "memory");
        __syncwarp();

        // split-K HMMA, 3 virtual passes (warp reads only its own k region)
        float a0e[4] = {}, a0o[4] = {}, a1e[4] = {}, a1o[4] = {};
#pragma unroll
        for (int t = 0; t < 3; t++) {
            const uint32_t aS = smb + ((t == 1) ? HLO_OFF : HHI_OFF) + arow * 2048;
            const uint32_t bS = smb + ((t == 2) ? WLO_OFF : WHI_OFF) + brow * 2048;
#pragma unroll
            for (int jj = 0; jj < 8; jj++) {
                int cj = (wid * 8 + jj) * 2;
                uint32_t af[4], bf[4];
                ldsm4(af, aS + ((((cj + ach) ^ (arow & 7)) & 127) << 4));
                ldsm4(bf, bS + ((((cj + bch) ^ (brow & 7)) & 127) << 4));
                if (jj & 1) {
                    mma16816(a0o, af, bf[0], bf[1]);
                    mma16816(a1o, af, bf[2], bf[3]);
                } else {
                    mma16816(a0e, af, bf[0], bf[1]);
                    mma16816(a1e, af, bf[2], bf[3]);
                }
            }
        }
        float* rw = red + wid * 288;
        rw[crow * 18 + ccol]           = a0e[0] + a0o[0];
        rw[crow * 18 + ccol + 1]       = a0e[1] + a0o[1];
        rw[(crow + 8) * 18 + ccol]     = a0e[2] + a0o[2];
        rw[(crow + 8) * 18 + ccol + 1] = a0e[3] + a0o[3];
        rw[crow * 18 + 8 + ccol]           = a1e[0] + a1o[0];
        rw[crow * 18 + 8 + ccol + 1]       = a1e[1] + a1o[1];
        rw[(crow + 8) * 18 + 8 + ccol]     = a1e[2] + a1o[2];
        rw[(crow + 8) * 18 + 8 + ccol + 1] = a1e[3] + a1o[3];
        __syncthreads();

        float v = gval;
#pragma unroll
        for (int w = 0; w < 8; w++) v += red[w * 288 + rb * 18 + rn];
        float hv = tanhf(v);
        __nv_bfloat16 hi = __float2bfloat16(hv);
        __nv_bfloat16 lo = __float2bfloat16(hv - __bfloat162float(hi));
        const int nxt = cur ^ 1;
        const int idx = rb * Hh + n0 + rn;
        g_Hhi[nxt][idx] = hi;
        g_Hlo[nxt][idx] = lo;
        g_A8[((size_t)s * Bb + rb) * Hh + n0 + rn] = to_e4m3(hv * ASCALE);  // m = s*16+b
        if (s == Ss - 1) out[(size_t)Bb * Ss * Vv + idx] = hv;              // hT direct
        __syncthreads();
        if (tid == 0)
            st_release(&g_flags[blockIdx.x * 32], base + (unsigned)(s + 1));
    }
}

// ---- dec role ----
__device__ void dec_load_stage(uint32_t sb, int stg, int ki, int bm, int bn, int tid) {
    uint32_t base = sb + stg * DEC_STG;
    const uint8_t* gA = g_A8 + (size_t)bm * 1024 + ki * 128;
    const uint8_t* gB = g_B8 + (size_t)bn * 1024 + ki * 128;
#pragma unroll
    for (int i = 0; i < 4; i++) {
        int c = tid + i * 256;
        int r = c >> 3, cc = c & 7;
        cp_async16(base + r * 128 + (((cc ^ (r & 7)) & 7) << 4),
                   gA + (size_t)r * 1024 + cc * 16);
    }
#pragma unroll
    for (int i = 0; i < 8; i++) {
        int c = tid + i * 256;
        int r = c >> 3, cc = c & 7;
        cp_async16(base + DEC_ASZ + r * 128 + (((cc ^ (r & 7)) & 7) << 4),
                   gB + (size_t)r * 1024 + cc * 16);
    }
}

__device__ void dec_tile(uint32_t sb, int bm, int bn, const float* __restrict__ b_dec,
                         const int* __restrict__ stop, float* __restrict__ out) {
    const int tid = threadIdx.x;
    const int wid = tid >> 5;
    const int lane = tid & 31;
    const int wm = wid & 1;
    const int wn = wid >> 1;

    float acc[4][8][4];
#pragma unroll
    for (int i = 0; i < 4; i++)
#pragma unroll
        for (int j = 0; j < 8; j++)
#pragma unroll
            for (int q = 0; q < 4; q++) acc[i][j][q] = 0.f;

    const int arow = wm * 64 + (lane & 15);
    const int ach = lane >> 4;
    const int as = arow & 7;
    const int brow = wn * 64 + ((lane >> 4) << 3) + (lane & 7);
    const int bch = (lane >> 3) & 1;
    const int bs = brow & 7;

    dec_load_stage(sb, 0, 0, bm, bn, tid); cp_commit();
    dec_load_stage(sb, 1, 1, bm, bn, tid); cp_commit();

    for (int ki = 0; ki < 8; ki++) {
        const int cur = ki % 3;
        if (ki + 2 < 8) {
            dec_load_stage(sb, (ki + 2) % 3, ki + 2, bm, bn, tid); cp_commit();
            asm volatile("cp.async.wait_group 2;" ::: "memory");
        } else if (ki + 1 < 8) {
            asm volatile("cp.async.wait_group 1;" ::: "memory");
        } else {
            asm volatile("cp.async.wait_group 0;" ::: "memory");
        }
        __syncthreads();

        const uint32_t aB = sb + cur * DEC_STG + arow * 128;
        const uint32_t bB = sb + cur * DEC_STG + DEC_ASZ + brow * 128;
#pragma unroll
        for (int kt = 0; kt < 4; kt++) {
            uint32_t af[4][4], bf[4][4];
            const uint32_t acs = ((uint32_t)((kt * 2 + ach) ^ as)) << 4;
            const uint32_t bcs = ((uint32_t)((kt * 2 + bch) ^ bs)) << 4;
#pragma unroll
            for (int mi = 0; mi < 4; mi++) ldsm4(af[mi], aB + mi * 2048 + acs);
#pragma unroll
            for (int ni2 = 0; ni2 < 4; ni2++) ldsm4(bf[ni2], bB + ni2 * 2048 + bcs);
#pragma unroll
            for (int mi = 0; mi < 4; mi++)
#pragma unroll
                for (int ni = 0; ni < 8; ni++)
                    mma16832f8(acc[mi][ni], af[mi], bf[ni >> 1][(ni & 1) * 2],
                               bf[ni >> 1][(ni & 1) * 2 + 1]);
        }
        __syncthreads();
    }

    // epilogue: m = s*16+b  ->  out row = b*128+s
    const float SC = 1.0f / (ASCALE * BSCALE);
    int orow0[4];
    float msk0[4], msk1[4];
#pragma unroll
    for (int mi = 0; mi < 4; mi++) {
        int m0 = bm + wm * 64 + mi * 16 + (lane >> 2);
        orow0[mi] = (m0 & 15) * 128 + (m0 >> 4);
        msk0[mi] = (stop[orow0[mi]] == 0) ? 1.0f : 0.0f;
        msk1[mi] = (stop[orow0[mi] + 1024] == 0) ? 1.0f : 0.0f;   // +8 batches
    }
#pragma unroll
    for (int ni = 0; ni < 8; ni++) {
        int n0 = bn + wn * 64 + ni * 8 + (lane & 3) * 2;
        float2 bd = *(const float2*)(b_dec + n0);
        float2 tp = *(const float2*)(g_topic + n0);
#pragma unroll
        for (int mi = 0; mi < 4; mi++) {
            float2 o0, o1;
            o0.x = acc[mi][ni][0] * SC + bd.x + tp.x * msk0[mi];
            o0.y = acc[mi][ni][1] * SC + bd.y + tp.y * msk0[mi];
            o1.x = acc[mi][ni][2] * SC + bd.x + tp.x * msk1[mi];
            o1.y = acc[mi][ni][3] * SC + bd.y + tp.y * msk1[mi];
            *(float2*)(out + (size_t)orow0[mi] * Vv + n0) = o0;
            *(float2*)(out + (size_t)(orow0[mi] + 1024) * Vv + n0) = o1;
        }
    }
}

__device__ void dec_role(char* dsm, const float* __restrict__ b_dec,
                         const int* __restrict__ stop, float* __restrict__ out,
                         unsigned base) {
    __shared__ int s_t;
    const int tid = threadIdx.x;
    uint32_t sb = (smem_u32(dsm) + 1023) & ~1023u;
    for (;;) {
        if (tid == 0) s_t = (int)atomicAdd(&g_tile, 1u);
        __syncthreads();
        int t = s_t;
        if (t >= N_TILES) return;
        int x = t / 125;            // s-range group (needs rnn steps 0..8x+7 complete)
        int y = t - x * 125;
        unsigned need = base + (unsigned)(x * 8 + 8);
        if (tid < RNN_NB) {
            const unsigned* fp = &g_flags[tid * 32];
            while (ld_relaxed(fp) < need) __nanosleep(1024);
            (void)ld_acquire(fp);
        }
        __syncthreads();
        dec_tile(sb, x * 128, y * 256, b_dec, stop, out);
        __syncthreads();            // protect smem reuse across tiles
    }
}

__global__ __launch_bounds__(256, 1) void fused_kernel(const float* __restrict__ W_hh,
                                                       const float* __restrict__ b_dec,
                                                       const int* __restrict__ stop,
                                                       float* __restrict__ out) {
    extern __shared__ __align__(16) char fsm[];
    const unsigned base = g_epoch << 8;
    if (blockIdx.x < RNN_NB) {
        rnn_role(fsm, W_hh, out, base);
        __syncthreads();
        dec_role(fsm, b_dec, stop, out, base);   // join tile queue for the tail
    } else {
        dec_role(fsm, b_dec, stop, out, base);
    }
}

// ------------------------- launch -------------------------
extern "C" void kernel_launch(void* const* d_in, const int* in_sizes, int n_in,
                              void* d_out, int out_size) {
    const int*   input_ids = (const int*)d_in[0];
    const float* hidden    = (const float*)d_in[1];
    const int*   stop      = (const int*)d_in[2];
    const float* W_emb     = (const float*)d_in[3];
    const float* W_ih      = (const float*)d_in[4];
    const float* b_ih      = (const float*)d_in[5];
    const float* W_hh      = (const float*)d_in[6];
    const float* b_hh      = (const float*)d_in[7];
    const float* W_dec     = (const float*)d_in[8];
    const float* b_dec     = (const float*)d_in[9];
    const float* beta      = (const float*)d_in[10];
    const float* theta     = (const float*)d_in[11];
    float* out = (float*)d_out;

    cudaFuncSetAttribute(fused_kernel, cudaFuncAttributeMaxDynamicSharedMemorySize,
                         FUSED_SMEM);
    cudaFuncSetAttribute(embed_gemm, cudaFuncAttributeMaxDynamicSharedMemorySize,
                         EMB_SMEM);

    static cudaStream_t sA = nullptr, sB = nullptr;
    static cudaEvent_t eF = nullptr, eA = nullptr, eB = nullptr;
    if (sA == nullptr) {
        cudaStreamCreateWithFlags(&sA, cudaStreamNonBlocking);
        cudaStreamCreateWithFlags(&sB, cudaStreamNonBlocking);
        cudaEventCreateWithFlags(&eF, cudaEventDisableTiming);
        cudaEventCreateWithFlags(&eA, cudaEventDisableTiming);
        cudaEventCreateWithFlags(&eB, cudaEventDisableTiming);
    }

    // pre-phase fork: convB on sA; topic+init on sB; embed (HMMA) on main
    cudaEventRecord(eF, 0);
    cudaStreamWaitEvent(sA, eF, 0);
    cudaStreamWaitEvent(sB, eF, 0);
    convB_kernel<<<(int)(((size_t)Vv * 1024 / 4) / 256), 256, 0, sA>>>(W_dec);
    topic_kernel<<<(Vv + 255) / 256, 256, 0, sB>>>(beta, theta);
    init_h_kernel<<<(Bb * Hh + 255) / 256, 256, 0, sB>>>(hidden);
    embed_gemm<<<dim3(16, 8), 256, EMB_SMEM>>>(input_ids, W_emb, W_ih, b_ih, b_hh);
    cudaEventRecord(eA, sA);
    cudaEventRecord(eB, sB);
    cudaStreamWaitEvent(0, eA, 0);
    cudaStreamWaitEvent(0, eB, 0);

    // fused rnn + decoder (all 148 CTAs co-resident; writes ALL of out)
    fused_kernel<<<CMB_NB, 256, FUSED_SMEM>>>(W_hh, b_dec, stop, out);
}

// round 15
// speedup vs baseline: 7.2525x; 1.0125x over previous
#include <cuda_runtime.h>
#include <cuda_bf16.h>
#include <cuda_fp8.h>
#include <math.h>
#include <stdint.h>

#define Vv 32000
#define Ee 512
#define Hh 1024
#define Bb 16
#define Ss 128
#define Kk 15

#define ASCALE 128.0f
#define BSCALE 256.0f

// ------------------------- device scratch (no allocs allowed) -------------------------
__device__ float g_G[Ss * Bb * Hh];               // [s][b][h]
__device__ __nv_bfloat16 g_Hhi[2][Bb * Hh];
__device__ __nv_bfloat16 g_Hlo[2][Bb * Hh];
__device__ float g_topic[Vv];
__device__ unsigned g_epoch;                      // bumped each launch (init_h)
__device__ unsigned g_flags[64 * 32];             // per-rnn-CTA flag, 1 per 128B line
__device__ unsigned g_tile;                       // dec tile queue head (reset each launch)
// fp8 decoder operands
__device__ uint8_t g_A8[2048 * 1024];             // [m = s*16+b][k]  (h * 128, e4m3)
__device__ uint8_t g_B8[(size_t)Vv * 1024];       // [v][k]           (W_dec * 256, e4m3)
// pre-split bf16 operands for embed GEMM
__device__ __nv_bfloat16 g_EAhi[2048 * Ee];       // gathered W_emb rows, hi
__device__ __nv_bfloat16 g_EAlo[2048 * Ee];       // lo
__device__ __nv_bfloat16 g_EBhi[Hh * Ee];         // W_ih hi
__device__ __nv_bfloat16 g_EBlo[Hh * Ee];         // lo

// ------------------------- PTX helpers -------------------------
__device__ __forceinline__ uint32_t smem_u32(const void* p) {
    uint32_t a;
    asm("{ .reg .u64 t; cvta.to.shared.u64 t, %1; cvt.u32.u64 %0, t; }" : "=r"(a) : "l"(p));
    return a;
}
__device__ __forceinline__ void cp_async16(uint32_t dst, const void* src) {
    asm volatile("cp.async.cg.shared.global [%0], [%1], 16;" :: "r"(dst), "l"(src) : "memory");
}
__device__ __forceinline__ void cp_commit() { asm volatile("cp.async.commit_group;" ::: "memory"); }

__device__ __forceinline__ void ldsm4(uint32_t* r, uint32_t addr) {
    asm volatile("ldmatrix.sync.aligned.m8n8.x4.shared.b16 {%0,%1,%2,%3}, [%4];"
                 : "=r"(r[0]), "=r"(r[1]), "=r"(r[2]), "=r"(r[3]) : "r"(addr));
}
__device__ __forceinline__ void mma16816(float* c, const uint32_t* a, uint32_t b0, uint32_t b1) {
    asm volatile("mma.sync.aligned.m16n8k16.row.col.f32.bf16.bf16.f32 "
                 "{%0,%1,%2,%3}, {%4,%5,%6,%7}, {%8,%9}, {%0,%1,%2,%3};"
                 : "+f"(c[0]), "+f"(c[1]), "+f"(c[2]), "+f"(c[3])
                 : "r"(a[0]), "r"(a[1]), "r"(a[2]), "r"(a[3]), "r"(b0), "r"(b1));
}
__device__ __forceinline__ void mma16832f8(float* c, const uint32_t* a, uint32_t b0, uint32_t b1) {
    asm volatile("mma.sync.aligned.m16n8k32.row.col.f32.e4m3.e4m3.f32 "
                 "{%0,%1,%2,%3}, {%4,%5,%6,%7}, {%8,%9}, {%0,%1,%2,%3};"
                 : "+f"(c[0]), "+f"(c[1]), "+f"(c[2]), "+f"(c[3])
                 : "r"(a[0]), "r"(a[1]), "r"(a[2]), "r"(a[3]), "r"(b0), "r"(b1));
}
__device__ __forceinline__ uint8_t to_e4m3(float x) {
    return (uint8_t)__nv_cvt_float_to_fp8(x, __NV_SATFINITE, __NV_E4M3);
}
__device__ __forceinline__ void st_release(unsigned* p, unsigned v) {
    asm volatile("st.release.gpu.global.u32 [%0], %1;" :: "l"(p), "r"(v) : "memory");
}
__device__ __forceinline__ unsigned ld_relaxed(const unsigned* p) {
    unsigned v;
    asm volatile("ld.relaxed.gpu.global.u32 %0, [%1];" : "=r"(v) : "l"(p));
    return v;
}
__device__ __forceinline__ unsigned ld_acquire(const unsigned* p) {
    unsigned v;
    asm volatile("ld.acquire.gpu.global.u32 %0, [%1];" : "=r"(v) : "l"(p) : "memory");
    return v;
}

// ------------------------- tiny kernels -------------------------
__global__ void topic_kernel(const float* __restrict__ beta, const float* __restrict__ theta) {
    int v = blockIdx.x * 256 + threadIdx.x;
    if (v < Vv) {
        float s = 0.f;
#pragma unroll
        for (int k = 0; k < Kk; k++) s += theta[k] * beta[k * Vv + v];
        g_topic[v] = s;
    }
}
__global__ void init_h_kernel(const float* __restrict__ hidden) {
    int i = blockIdx.x * 256 + threadIdx.x;
    if (i < Bb * Hh) {
        float x = hidden[i];
        __nv_bfloat16 hi = __float2bfloat16(x);
        g_Hhi[0][i] = hi;
        g_Hlo[0][i] = __float2bfloat16(x - __bfloat162float(hi));
    }
    if (i == 0) { g_epoch = g_epoch + 1; g_tile = 0; }
}
__global__ void convB_kernel(const float* __restrict__ W_dec) {
    size_t i = (size_t)blockIdx.x * 256 + threadIdx.x;   // float4 groups
    float4 v = ((const float4*)W_dec)[i];
    uchar4 o;
    o.x = to_e4m3(v.x * BSCALE);
    o.y = to_e4m3(v.y * BSCALE);
    o.z = to_e4m3(v.z * BSCALE);
    o.w = to_e4m3(v.w * BSCALE);
    ((uchar4*)g_B8)[i] = o;
}
// gather + split W_emb rows -> EA slabs
__global__ void convA_emb_kernel(const int* __restrict__ ids,
                                 const float* __restrict__ W_emb) {
    int i = blockIdx.x * 256 + threadIdx.x;   // 2048*512
    int m = i >> 9, k = i & 511;
    int row = ids[(m & 15) * Ss + (m >> 4)];
    float x = W_emb[(size_t)row * Ee + k];
    __nv_bfloat16 hi = __float2bfloat16(x);
    g_EAhi[i] = hi;
    g_EAlo[i] = __float2bfloat16(x - __bfloat162float(hi));
}
// split W_ih -> EB slabs
__global__ void convWih_kernel(const float* __restrict__ W_ih) {
    int i = blockIdx.x * 256 + threadIdx.x;   // 1024*512
    float x = W_ih[i];
    __nv_bfloat16 hi = __float2bfloat16(x);
    g_EBhi[i] = hi;
    g_EBlo[i] = __float2bfloat16(x - __bfloat162float(hi));
}

// ------------------------- embed GEMM: pipelined bf16, 3-term K-concat ---------------
// G[m][n] = EA[m].EB[n] (3 passes) + b_ih[n] + b_hh[n]; CTA 128m x 128n; 24 k-chunks.
#define EMB_ASZ 16384
#define EMB_BSZ 16384
#define EMB_STG (EMB_ASZ + EMB_BSZ)
#define EMB_SMEM (3 * EMB_STG + 1024)

__device__ __forceinline__ void emb_load_stage(uint32_t sb, int stg, int ki,
                                               int bm, int bn, int tid) {
    const int t = ki >> 3, kc = ki & 7;                 // term, k-chunk (64 bf16)
    const __nv_bfloat16* sA = (t == 1) ? g_EAlo : g_EAhi;
    const __nv_bfloat16* sB = (t == 2) ? g_EBlo : g_EBhi;
    const __nv_bfloat16* gA = sA + (size_t)bm * Ee + kc * 64;
    const __nv_bfloat16* gB = sB + (size_t)bn * Ee + kc * 64;
    uint32_t base = sb + stg * EMB_STG;
#pragma unroll
    for (int i = 0; i < 4; i++) {                       // A: 1024 x 16B
        int c = tid + i * 256;
        int r = c >> 3, cc = c & 7;
        cp_async16(base + r * 128 + (((cc ^ (r & 7)) & 7) << 4),
                   gA + (size_t)r * Ee + cc * 8);
    }
#pragma unroll
    for (int i = 0; i < 4; i++) {                       // B: 1024 x 16B
        int c = tid + i * 256;
        int r = c >> 3, cc = c & 7;
        cp_async16(base + EMB_ASZ + r * 128 + (((cc ^ (r & 7)) & 7) << 4),
                   gB + (size_t)r * Ee + cc * 8);
    }
}

__global__ __launch_bounds__(256, 1) void embed_gemm(const float* __restrict__ b_ih,
                                                     const float* __restrict__ b_hh) {
    extern __shared__ __align__(16) char esm[];
    const int tid = threadIdx.x;
    const int wid = tid >> 5;
    const int lane = tid & 31;
    const int wm = wid & 1;
    const int wn = wid >> 1;
    const int bm = blockIdx.x * 128;
    const int bn = blockIdx.y * 128;
    uint32_t sb = (smem_u32(esm) + 1023) & ~1023u;

    float acc[4][4][4];
#pragma unroll
    for (int i = 0; i < 4; i++)
#pragma unroll
        for (int j = 0; j < 4; j++)
#pragma unroll
            for (int q = 0; q < 4; q++) acc[i][j][q] = 0.f;

    const int arow = wm * 64 + (lane & 15);
    const int ach = lane >> 4;
    const int as = arow & 7;
    const int brow = wn * 32 + ((lane >> 4) << 3) + (lane & 7);
    const int bch = (lane >> 3) & 1;
    const int bs = brow & 7;

    emb_load_stage(sb, 0, 0, bm, bn, tid); cp_commit();
    emb_load_stage(sb, 1, 1, bm, bn, tid); cp_commit();

    for (int ki = 0; ki < 24; ki++) {
        const int cur = ki % 3;
        if (ki + 2 < 24) {
            emb_load_stage(sb, (ki + 2) % 3, ki + 2, bm, bn, tid); cp_commit();
            asm volatile("cp.async.wait_group 2;" ::: "memory");
        } else if (ki + 1 < 24) {
            asm volatile("cp.async.wait_group 1;" ::: "memory");
        } else {
            asm volatile("cp.async.wait_group 0;" ::: "memory");
        }
        __syncthreads();

        const uint32_t aB = sb + cur * EMB_STG + arow * 128;
        const uint32_t bB = sb + cur * EMB_STG + EMB_ASZ + brow * 128;
#pragma unroll
        for (int k16 = 0; k16 < 4; k16++) {
            uint32_t af[4][4], bf[2][4];
            const uint32_t acs = ((uint32_t)((k16 * 2 + ach) ^ as)) << 4;
            const uint32_t bcs = ((uint32_t)((k16 * 2 + bch) ^ bs)) << 4;
#pragma unroll
            for (int mi = 0; mi < 4; mi++) ldsm4(af[mi], aB + mi * 2048 + acs);
#pragma unroll
            for (int ni2 = 0; ni2 < 2; ni2++) ldsm4(bf[ni2], bB + ni2 * 2048 + bcs);
#pragma unroll
            for (int mi = 0; mi < 4; mi++)
#pragma unroll
                for (int ni = 0; ni < 4; ni++)
                    mma16816(acc[mi][ni], af[mi], bf[ni >> 1][(ni & 1) * 2],
                             bf[ni >> 1][(ni & 1) * 2 + 1]);
        }
        __syncthreads();
    }

#pragma unroll
    for (int ni = 0; ni < 4; ni++) {
        int n0 = bn + wn * 32 + ni * 8 + (lane & 3) * 2;
        float2 bi = *(const float2*)(b_ih + n0);
        float2 bh = *(const float2*)(b_hh + n0);
        float2 bb = make_float2(bi.x + bh.x, bi.y + bh.y);
#pragma unroll
        for (int mi = 0; mi < 4; mi++) {
            int m0 = bm + wm * 64 + mi * 16 + (lane >> 2);
            float2 o0 = make_float2(acc[mi][ni][0] + bb.x, acc[mi][ni][1] + bb.y);
            float2 o1 = make_float2(acc[mi][ni][2] + bb.x, acc[mi][ni][3] + bb.y);
            *(float2*)(g_G + (size_t)m0 * Hh + n0) = o0;
            *(float2*)(g_G + (size_t)(m0 + 8) * Hh + n0) = o1;
        }
    }
}

// ------------------------- fused persistent kernel: rnn + dec -------------------------
#define RNN_NB 64
#define CMB_NB 148
#define N_TILES (16 * 125)
#define WHI_OFF 0
#define WLO_OFF 32768
#define HHI_OFF 65536
#define HLO_OFF 98304
#define RNN_RED_OFF 131072
#define DEC_ASZ 16384
#define DEC_BSZ 32768
#define DEC_STG (DEC_ASZ + DEC_BSZ)
#define FUSED_SMEM (3 * DEC_STG + 1024)           // 148480 >= rnn's 140288

// ---- rnn role: per-warp dataflow ----
__device__ void rnn_role(char* rsm, const float* __restrict__ W_hh,
                         float* __restrict__ out, unsigned base) {
    float* red = (float*)(rsm + RNN_RED_OFF);
    const int tid = threadIdx.x;
    const int wid = tid >> 5;
    const int lane = tid & 31;
    const int n0 = blockIdx.x * 16;

#pragma unroll
    for (int i = 0; i < 8; i++) {
        int c = tid + i * 256;
        int r = c >> 7, kc = c & 127;
        const float* src = W_hh + (size_t)(n0 + r) * Hh + kc * 8;
        float4 v0 = *(const float4*)src;
        float4 v1 = *(const float4*)(src + 4);
        float x[8] = {v0.x, v0.y, v0.z, v0.w, v1.x, v1.y, v1.z, v1.w};
        __nv_bfloat16 hi[8], lo[8];
#pragma unroll
        for (int q = 0; q < 8; q++) {
            hi[q] = __float2bfloat16(x[q]);
            lo[q] = __float2bfloat16(x[q] - __bfloat162float(hi[q]));
        }
        uint32_t off = r * 2048 + (((kc ^ (r & 7)) & 127) << 4);
        *(uint4*)(rsm + WHI_OFF + off) = *(uint4*)hi;
        *(uint4*)(rsm + WLO_OFF + off) = *(uint4*)lo;
    }
    __syncthreads();

    const int arow = lane & 15;
    const int ach = lane >> 4;
    const int brow = ((lane >> 4) << 3) + (lane & 7);
    const int bch = (lane >> 3) & 1;
    const int crow = lane >> 2, ccol = (lane & 3) * 2;
    const int rb = tid >> 4, rn = tid & 15;
    const uint32_t smb = smem_u32(rsm);
    const unsigned* wfp = &g_flags[(wid * 8 + (lane & 7)) * 32];

    for (int s = 0; s < Ss; s++) {
        const int cur = s & 1;
        float gval = __ldcg(&g_G[(size_t)s * (Bb * Hh) + rb * Hh + n0 + rn]);

        if (s > 0) {
            if (lane < 8) {
                unsigned need = base + (unsigned)s;
                while (ld_relaxed(wfp) < need) { }
                (void)ld_acquire(wfp);
            }
            __syncwarp();
        }

        // per-warp staging: hhi group, then hlo group
        const __nv_bfloat16* hh = g_Hhi[cur];
        const __nv_bfloat16* hl = g_Hlo[cur];
#pragma unroll
        for (int l = 0; l < 8; l++) {
            int c = l * 32 + lane;
            int r = c >> 4;
            int kc = wid * 16 + (c & 15);
            uint32_t off = r * 2048 + (((kc ^ (r & 7)) & 127) << 4);
            cp_async16(smb + HHI_OFF + off, hh + r * Hh + kc * 8);
        }
        cp_commit();
#pragma unroll
        for (int l = 0; l < 8; l++) {
            int c = l * 32 + lane;
            int r = c >> 4;
            int kc = wid * 16 + (c & 15);
            uint32_t off = r * 2048 + (((kc ^ (r & 7)) & 127) << 4);
            cp_async16(smb + HLO_OFF + off, hl + r * Hh + kc * 8);
        }
        cp_commit();

        float a0e[4] = {}, a0o[4] = {}, a1e[4] = {}, a1o[4] = {};
        asm volatile("cp.async.wait_group 1;" ::: "memory");   // hhi ready
        __syncwarp();
        // passes on hhi: x Whi, x Wlo
#pragma unroll
        for (int t = 0; t < 2; t++) {
            const uint32_t aS = smb + HHI_OFF + arow * 2048;
            const uint32_t bS = smb + ((t == 1) ? WLO_OFF : WHI_OFF) + brow * 2048;
#pragma unroll
            for (int jj = 0; jj < 8; jj++) {
                int cj = (wid * 8 + jj) * 2;
                uint32_t af[4], bf[4];
                ldsm4(af, aS + ((((cj + ach) ^ (arow & 7)) & 127) << 4));
                ldsm4(bf, bS + ((((cj + bch) ^ (brow & 7)) & 127) << 4));
                if (jj & 1) {
                    mma16816(a0o, af, bf[0], bf[1]);
                    mma16816(a1o, af, bf[2], bf[3]);
                } else {
                    mma16816(a0e, af, bf[0], bf[1]);
                    mma16816(a1e, af, bf[2], bf[3]);
                }
            }
        }
        asm volatile("cp.async.wait_group 0;" ::: "memory");   // hlo ready
        __syncwarp();
        // pass on hlo: x Whi
        {
            const uint32_t aS = smb + HLO_OFF + arow * 2048;
            const uint32_t bS = smb + WHI_OFF + brow * 2048;
#pragma unroll
            for (int jj = 0; jj < 8; jj++) {
                int cj = (wid * 8 + jj) * 2;
                uint32_t af[4], bf[4];
                ldsm4(af, aS + ((((cj + ach) ^ (arow & 7)) & 127) << 4));
                ldsm4(bf, bS + ((((cj + bch) ^ (brow & 7)) & 127) << 4));
                if (jj & 1) {
                    mma16816(a0o, af, bf[0], bf[1]);
                    mma16816(a1o, af, bf[2], bf[3]);
                } else {
                    mma16816(a0e, af, bf[0], bf[1]);
                    mma16816(a1e, af, bf[2], bf[3]);
                }
            }
        }
        float* rw = red + wid * 288;
        rw[crow * 18 + ccol]           = a0e[0] + a0o[0];
        rw[crow * 18 + ccol + 1]       = a0e[1] + a0o[1];
        rw[(crow + 8) * 18 + ccol]     = a0e[2] + a0o[2];
        rw[(crow + 8) * 18 + ccol + 1] = a0e[3] + a0o[3];
        rw[crow * 18 + 8 + ccol]           = a1e[0] + a1o[0];
        rw[crow * 18 + 8 + ccol + 1]       = a1e[1] + a1o[1];
        rw[(crow + 8) * 18 + 8 + ccol]     = a1e[2] + a1o[2];
        rw[(crow + 8) * 18 + 8 + ccol + 1] = a1e[3] + a1o[3];
        __syncthreads();

        float v = gval;
#pragma unroll
        for (int w = 0; w < 8; w++) v += red[w * 288 + rb * 18 + rn];
        float hv = tanhf(v);
        __nv_bfloat16 hi = __float2bfloat16(hv);
        __nv_bfloat16 lo = __float2bfloat16(hv - __bfloat162float(hi));
        const int nxt = cur ^ 1;
        const int idx = rb * Hh + n0 + rn;
        g_Hhi[nxt][idx] = hi;
        g_Hlo[nxt][idx] = lo;
        if (s == Ss - 1) {
            // last step: everything before the final release
            g_A8[((size_t)s * Bb + rb) * Hh + n0 + rn] = to_e4m3(hv * ASCALE);
            out[(size_t)Bb * Ss * Vv + idx] = hv;
            __syncthreads();
            if (tid == 0)
                st_release(&g_flags[blockIdx.x * 32], base + (unsigned)(s + 1));
        } else {
            __syncthreads();
            if (tid == 0)
                st_release(&g_flags[blockIdx.x * 32], base + (unsigned)(s + 1));
            // deferred: ordered by the release of step s+2 (dec waits flag 8x+9)
            g_A8[((size_t)s * Bb + rb) * Hh + n0 + rn] = to_e4m3(hv * ASCALE);
        }
    }
}

// ---- dec role ----
__device__ void dec_load_stage(uint32_t sb, int stg, int ki, int bm, int bn, int tid) {
    uint32_t base = sb + stg * DEC_STG;
    const uint8_t* gA = g_A8 + (size_t)bm * 1024 + ki * 128;
    const uint8_t* gB = g_B8 + (size_t)bn * 1024 + ki * 128;
#pragma unroll
    for (int i = 0; i < 4; i++) {
        int c = tid + i * 256;
        int r = c >> 3, cc = c & 7;
        cp_async16(base + r * 128 + (((cc ^ (r & 7)) & 7) << 4),
                   gA + (size_t)r * 1024 + cc * 16);
    }
#pragma unroll
    for (int i = 0; i < 8; i++) {
        int c = tid + i * 256;
        int r = c >> 3, cc = c & 7;
        cp_async16(base + DEC_ASZ + r * 128 + (((cc ^ (r & 7)) & 7) << 4),
                   gB + (size_t)r * 1024 + cc * 16);
    }
}

__device__ void dec_tile(uint32_t sb, int bm, int bn, const float* __restrict__ b_dec,
                         const int* __restrict__ stop, float* __restrict__ out) {
    const int tid = threadIdx.x;
    const int wid = tid >> 5;
    const int lane = tid & 31;
    const int wm = wid & 1;
    const int wn = wid >> 1;

    float acc[4][8][4];
#pragma unroll
    for (int i = 0; i < 4; i++)
#pragma unroll
        for (int j = 0; j < 8; j++)
#pragma unroll
            for (int q = 0; q < 4; q++) acc[i][j][q] = 0.f;

    const int arow = wm * 64 + (lane & 15);
    const int ach = lane >> 4;
    const int as = arow & 7;
    const int brow = wn * 64 + ((lane >> 4) << 3) + (lane & 7);
    const int bch = (lane >> 3) & 1;
    const int bs = brow & 7;

    dec_load_stage(sb, 0, 0, bm, bn, tid); cp_commit();
    dec_load_stage(sb, 1, 1, bm, bn, tid); cp_commit();

    for (int ki = 0; ki < 8; ki++) {
        const int cur = ki % 3;
        if (ki + 2 < 8) {
            dec_load_stage(sb, (ki + 2) % 3, ki + 2, bm, bn, tid); cp_commit();
            asm volatile("cp.async.wait_group 2;" ::: "memory");
        } else if (ki + 1 < 8) {
            asm volatile("cp.async.wait_group 1;" ::: "memory");
        } else {
            asm volatile("cp.async.wait_group 0;" ::: "memory");
        }
        __syncthreads();

        const uint32_t aB = sb + cur * DEC_STG + arow * 128;
        const uint32_t bB = sb + cur * DEC_STG + DEC_ASZ + brow * 128;
#pragma unroll
        for (int kt = 0; kt < 4; kt++) {
            uint32_t af[4][4], bf[4][4];
            const uint32_t acs = ((uint32_t)((kt * 2 + ach) ^ as)) << 4;
            const uint32_t bcs = ((uint32_t)((kt * 2 + bch) ^ bs)) << 4;
#pragma unroll
            for (int mi = 0; mi < 4; mi++) ldsm4(af[mi], aB + mi * 2048 + acs);
#pragma unroll
            for (int ni2 = 0; ni2 < 4; ni2++) ldsm4(bf[ni2], bB + ni2 * 2048 + bcs);
#pragma unroll
            for (int mi = 0; mi < 4; mi++)
#pragma unroll
                for (int ni = 0; ni < 8; ni++)
                    mma16832f8(acc[mi][ni], af[mi], bf[ni >> 1][(ni & 1) * 2],
                               bf[ni >> 1][(ni & 1) * 2 + 1]);
        }
        __syncthreads();
    }

    const float SC = 1.0f / (ASCALE * BSCALE);
    int orow0[4];
    float msk0[4], msk1[4];
#pragma unroll
    for (int mi = 0; mi < 4; mi++) {
        int m0 = bm + wm * 64 + mi * 16 + (lane >> 2);
        orow0[mi] = (m0 & 15) * 128 + (m0 >> 4);
        msk0[mi] = (stop[orow0[mi]] == 0) ? 1.0f : 0.0f;
        msk1[mi] = (stop[orow0[mi] + 1024] == 0) ? 1.0f : 0.0f;
    }
#pragma unroll
    for (int ni = 0; ni < 8; ni++) {
        int n0 = bn + wn * 64 + ni * 8 + (lane & 3) * 2;
        float2 bd = *(const float2*)(b_dec + n0);
        float2 tp = *(const float2*)(g_topic + n0);
#pragma unroll
        for (int mi = 0; mi < 4; mi++) {
            float2 o0, o1;
            o0.x = acc[mi][ni][0] * SC + bd.x + tp.x * msk0[mi];
            o0.y = acc[mi][ni][1] * SC + bd.y + tp.y * msk0[mi];
            o1.x = acc[mi][ni][2] * SC + bd.x + tp.x * msk1[mi];
            o1.y = acc[mi][ni][3] * SC + bd.y + tp.y * msk1[mi];
            *(float2*)(out + (size_t)orow0[mi] * Vv + n0) = o0;
            *(float2*)(out + (size_t)(orow0[mi] + 1024) * Vv + n0) = o1;
        }
    }
}

__device__ void dec_role(char* dsm, const float* __restrict__ b_dec,
                         const int* __restrict__ stop, float* __restrict__ out,
                         unsigned base) {
    __shared__ int s_t;
    const int tid = threadIdx.x;
    uint32_t sb = (smem_u32(dsm) + 1023) & ~1023u;
    for (;;) {
        if (tid == 0) s_t = (int)atomicAdd(&g_tile, 1u);
        __syncthreads();
        int t = s_t;
        if (t >= N_TILES) return;
        int x = t / 125;
        int y = t - x * 125;
        // A8 rows of step s are ordered by the release of step s+2 -> need 8x+9
        unsigned nv = (x == 15) ? 128u : (unsigned)(x * 8 + 9);
        unsigned need = base + nv;
        if (tid < RNN_NB) {
            const unsigned* fp = &g_flags[tid * 32];
            while (ld_relaxed(fp) < need) __nanosleep(1024);
            (void)ld_acquire(fp);
        }
        __syncthreads();
        dec_tile(sb, x * 128, y * 256, b_dec, stop, out);
        __syncthreads();
    }
}

__global__ __launch_bounds__(256, 1) void fused_kernel(const float* __restrict__ W_hh,
                                                       const float* __restrict__ b_dec,
                                                       const int* __restrict__ stop,
                                                       float* __restrict__ out) {
    extern __shared__ __align__(16) char fsm[];
    const unsigned base = g_epoch << 8;
    if (blockIdx.x < RNN_NB) {
        rnn_role(fsm, W_hh, out, base);
        __syncthreads();
        dec_role(fsm, b_dec, stop, out, base);   // join tile queue for the tail
    } else {
        dec_role(fsm, b_dec, stop, out, base);
    }
}

// ------------------------- launch -------------------------
extern "C" void kernel_launch(void* const* d_in, const int* in_sizes, int n_in,
                              void* d_out, int out_size) {
    const int*   input_ids = (const int*)d_in[0];
    const float* hidden    = (const float*)d_in[1];
    const int*   stop      = (const int*)d_in[2];
    const float* W_emb     = (const float*)d_in[3];
    const float* W_ih      = (const float*)d_in[4];
    const float* b_ih      = (const float*)d_in[5];
    const float* W_hh      = (const float*)d_in[6];
    const float* b_hh      = (const float*)d_in[7];
    const float* W_dec     = (const float*)d_in[8];
    const float* b_dec     = (const float*)d_in[9];
    const float* beta      = (const float*)d_in[10];
    const float* theta     = (const float*)d_in[11];
    float* out = (float*)d_out;

    cudaFuncSetAttribute(fused_kernel, cudaFuncAttributeMaxDynamicSharedMemorySize,
                         FUSED_SMEM);
    cudaFuncSetAttribute(embed_gemm, cudaFuncAttributeMaxDynamicSharedMemorySize,
                         EMB_SMEM);

    static cudaStream_t sA = nullptr, sB = nullptr;
    static cudaEvent_t eF = nullptr, eA = nullptr, eB = nullptr;
    if (sA == nullptr) {
        cudaStreamCreateWithFlags(&sA, cudaStreamNonBlocking);
        cudaStreamCreateWithFlags(&sB, cudaStreamNonBlocking);
        cudaEventCreateWithFlags(&eF, cudaEventDisableTiming);
        cudaEventCreateWithFlags(&eA, cudaEventDisableTiming);
        cudaEventCreateWithFlags(&eB, cudaEventDisableTiming);
    }

    // pre-phase fork: convB on sA; topic+init on sB; embed chain on main
    cudaEventRecord(eF, 0);
    cudaStreamWaitEvent(sA, eF, 0);
    cudaStreamWaitEvent(sB, eF, 0);
    convB_kernel<<<(int)(((size_t)Vv * 1024 / 4) / 256), 256, 0, sA>>>(W_dec);
    topic_kernel<<<(Vv + 255) / 256, 256, 0, sB>>>(beta, theta);
    init_h_kernel<<<(Bb * Hh + 255) / 256, 256, 0, sB>>>(hidden);
    convA_emb_kernel<<<(2048 * Ee) / 256, 256>>>(input_ids, W_emb);
    convWih_kernel<<<(Hh * Ee) / 256, 256>>>(W_ih);
    embed_gemm<<<dim3(16, 8), 256, EMB_SMEM>>>(b_ih, b_hh);
    cudaEventRecord(eA, sA);
    cudaEventRecord(eB, sB);
    cudaStreamWaitEvent(0, eA, 0);
    cudaStreamWaitEvent(0, eB, 0);

    // fused rnn + decoder (all 148 CTAs co-resident; writes ALL of out)
    fused_kernel<<<CMB_NB, 256, FUSED_SMEM>>>(W_hh, b_dec, stop, out);
}